// round 7
// baseline (speedup 1.0000x reference)
#include <cuda_runtime.h>
#include <math.h>
#include <stdint.h>

// Problem constants
#define Tt   4
#define Bb   4
#define Nn   16384
#define KALLc 4
#define Ff   16384
#define ORD  3
#define Hh   64
#define N0c  4096

#define TBc  (Tt*Bb)        // 16
#define BNc  (Bb*Nn)        // 65536
#define TBNc (TBc*Nn)       // 262144
#define H3c  (3*Hh)         // 192

// Output layout: h_fin [B,N,H] | h_global [B,K,64] | logit [T,B,N] | value [T,B]
#define OFF_HG    4194304
#define OFF_LOGIT (OFF_HG + 1024)
#define OFF_VAL   (OFF_LOGIT + 262144)

// Scratch
__device__ float g_h  [TBNc * Hh];    // [T,B,N,64] hidden states per step
__device__ float g_qkv[TBNc * H3c];   // [T,B,N,192]
__device__ float g_yo [TBNc * Hh];    // [T,B,N,64]
__device__ int   g_cnt[Nn];
__device__ float g_M  [64*64];        // Wo @ W1[:64]
__device__ float g_c1 [64];           // bo @ W1[:64]
__device__ float g_E  [64*64];        // per (tb,kall): b1 + extra@W1[64:]
__device__ float g_wv [64];           // Wo @ Wv1[:64]
__device__ float g_bv [1];            // bo @ Wv1[:64]
__device__ float g_s1 [64*64];        // per (tb,kall): sum_n yo*invnnz
__device__ float g_s0 [64];           // per (tb,kall): sum_n cnt*invnnz

__device__ __forceinline__ float sigmoidf_(float v) { return 1.f / (1.f + expf(-v)); }
__device__ __forceinline__ void fma4_(float4& a, float s, float4 w) {
    a.x += s * w.x; a.y += s * w.y; a.z += s * w.z; a.w += s * w.w;
}

// ---- packed fp32 helpers (fma.rn.f32x2) ----
__device__ __forceinline__ unsigned long long packdup(float v) {
    unsigned long long r;
    asm("mov.b64 %0, {%1, %1};" : "=l"(r) : "f"(v));
    return r;
}
__device__ __forceinline__ unsigned long long pack2(float a, float b) {
    unsigned long long r;
    asm("mov.b64 %0, {%1, %2};" : "=l"(r) : "f"(a), "f"(b));
    return r;
}
__device__ __forceinline__ void ffma2(unsigned long long& acc,
                                      unsigned long long a, unsigned long long b) {
    asm("fma.rn.f32x2 %0, %1, %2, %0;" : "+l"(acc) : "l"(a), "l"(b));
}
__device__ __forceinline__ float2 unpack2(unsigned long long v) {
    float lo, hi;
    asm("mov.b64 {%0, %1}, %2;" : "=f"(lo), "=f"(hi) : "l"(v));
    return make_float2(lo, hi);
}

// ---------------------------------------------------------------------------
__global__ void k_count(const int* __restrict__ indices) {
    int i = blockIdx.x * 256 + threadIdx.x;
    if (i < Ff * ORD) atomicAdd(&g_cnt[indices[i]], 1);
}

// ---------------------------------------------------------------------------
__global__ void k_prep(const float* __restrict__ Wo, const float* __restrict__ bo,
                       const float* __restrict__ W1, const float* __restrict__ b1,
                       const float* __restrict__ Wv1,
                       const float* __restrict__ extra)
{
    int o = blockIdx.x * 256 + threadIdx.x;   // grid 32 x 256 = 8192
    if (o < 4096) {
        int j = o >> 6, c = o & 63;
        float s = 0.f;
        #pragma unroll
        for (int h = 0; h < 64; h++) s += Wo[j*64 + h] * W1[h*64 + c];
        g_M[o] = s;
    } else {
        int e = o - 4096;
        int g = e >> 6, c = e & 63;
        float s = b1[c];
        #pragma unroll
        for (int d = 0; d < 4; d++) s += extra[g*4 + d] * W1[(64 + d)*64 + c];
        g_E[e] = s;
    }
    if (blockIdx.x == 0 && threadIdx.x < 64) {
        int tid = threadIdx.x;
        float s = 0.f, w = 0.f;
        #pragma unroll
        for (int h = 0; h < 64; h++) {
            s += bo[h] * W1[h*64 + tid];
            w += Wo[tid*64 + h] * Wv1[h];
        }
        g_c1[tid] = s;
        g_wv[tid] = w;
        if (tid == 0) {
            float bvv = 0.f;
            #pragma unroll
            for (int h = 0; h < 64; h++) bvv += bo[h] * Wv1[h];
            g_bv[0] = bvv;
        }
    }
}

// ---------------------------------------------------------------------------
// GRU scan only (T=4). One thread per (b,n). (unchanged, passing)
// ---------------------------------------------------------------------------
__global__ __launch_bounds__(128, 3)
void k_gru(const float* __restrict__ h0, const float* __restrict__ x,
           const uint32_t* __restrict__ dones,
           const float* __restrict__ Wi, const float* __restrict__ bi,
           const float* __restrict__ Wh, const float* __restrict__ bhn,
           float* __restrict__ hfin_out)
{
    extern __shared__ float smem[];
    float* sWh  = smem;              // 12288
    float* sWi  = sWh + 12288;       // 768
    float* sbi  = sWi + 768;         // 192
    float* sbhn = sbi + 192;         // 64

    for (int i = threadIdx.x; i < 12288; i += 128) sWh[i] = Wh[i];
    for (int i = threadIdx.x; i < 768;   i += 128) sWi[i] = Wi[i];
    for (int i = threadIdx.x; i < 192;   i += 128) sbi[i] = bi[i];
    for (int i = threadIdx.x; i < 64;    i += 128) sbhn[i] = bhn[i];
    __syncthreads();

    const float4* sWi4  = (const float4*)sWi;
    const float4* sbi4  = (const float4*)sbi;
    const float4* sbhn4 = (const float4*)sbhn;
    const ulonglong2* sWh2 = (const ulonglong2*)sWh;

    int gid = blockIdx.x * 128 + threadIdx.x;
    int b = gid >> 14;

    float h[64];
    {
        const float4* h04 = (const float4*)(h0 + (size_t)gid * 64);
        #pragma unroll
        for (int j = 0; j < 16; j++) {
            float4 v = h04[j];
            h[4*j] = v.x; h[4*j+1] = v.y; h[4*j+2] = v.z; h[4*j+3] = v.w;
        }
    }

    #pragma unroll 1
    for (int t = 0; t < Tt; t++) {
        if (dones[t * Bb + b] != 0u) {
            #pragma unroll
            for (int j = 0; j < 64; j++) h[j] = 0.f;
        }
        float4 xt4 = ((const float4*)x)[(size_t)t * BNc + gid];
        float xt[4] = {xt4.x, xt4.y, xt4.z, xt4.w};

        float hn[64];
        #pragma unroll
        for (int kk = 0; kk < 16; kk++) {
            unsigned long long ar0=0ULL, ar1=0ULL, az0=0ULL, az1=0ULL, an0=0ULL, an1=0ULL;
            #pragma unroll
            for (int j = 0; j < 64; j++) {
                unsigned long long h2 = packdup(h[j]);
                ulonglong2 wr = sWh2[j*48 + kk];
                ulonglong2 wz = sWh2[j*48 + 16 + kk];
                ulonglong2 wn = sWh2[j*48 + 32 + kk];
                ffma2(ar0, h2, wr.x); ffma2(ar1, h2, wr.y);
                ffma2(az0, h2, wz.x); ffma2(az1, h2, wz.y);
                ffma2(an0, h2, wn.x); ffma2(an1, h2, wn.y);
            }
            float2 arl = unpack2(ar0), arh = unpack2(ar1);
            float2 azl = unpack2(az0), azh = unpack2(az1);
            float2 anl = unpack2(an0), anh = unpack2(an1);
            float4 ar = {arl.x, arl.y, arh.x, arh.y};
            float4 az = {azl.x, azl.y, azh.x, azh.y};
            float4 an = {anl.x, anl.y, anh.x, anh.y};

            float4 gr = sbi4[kk], gz = sbi4[16 + kk], gn = sbi4[32 + kk];
            #pragma unroll
            for (int d = 0; d < 4; d++) {
                float xd = xt[d];
                fma4_(gr, xd, sWi4[d*48 + kk]);
                fma4_(gz, xd, sWi4[d*48 + 16 + kk]);
                fma4_(gn, xd, sWi4[d*48 + 32 + kk]);
            }
            float4 bn4 = sbhn4[kk];
            float r, z, nv;
            r = sigmoidf_(gr.x + ar.x); z = sigmoidf_(gz.x + az.x);
            nv = tanhf(gn.x + r * (an.x + bn4.x));
            hn[4*kk+0] = (1.f - z) * nv + z * h[4*kk+0];
            r = sigmoidf_(gr.y + ar.y); z = sigmoidf_(gz.y + az.y);
            nv = tanhf(gn.y + r * (an.y + bn4.y));
            hn[4*kk+1] = (1.f - z) * nv + z * h[4*kk+1];
            r = sigmoidf_(gr.z + ar.z); z = sigmoidf_(gz.z + az.z);
            nv = tanhf(gn.z + r * (an.z + bn4.z));
            hn[4*kk+2] = (1.f - z) * nv + z * h[4*kk+2];
            r = sigmoidf_(gr.w + ar.w); z = sigmoidf_(gz.w + az.w);
            nv = tanhf(gn.w + r * (an.w + bn4.w));
            hn[4*kk+3] = (1.f - z) * nv + z * h[4*kk+3];
        }
        #pragma unroll
        for (int j = 0; j < 64; j++) h[j] = hn[j];

        float4* hout = (float4*)(g_h + ((size_t)t * BNc + gid) * 64);
        #pragma unroll
        for (int j = 0; j < 16; j++)
            hout[j] = make_float4(h[4*j], h[4*j+1], h[4*j+2], h[4*j+3]);
    }

    float4* ho = (float4*)(hfin_out + (size_t)gid * 64);
    #pragma unroll
    for (int j = 0; j < 16; j++)
        ho[j] = make_float4(h[4*j], h[4*j+1], h[4*j+2], h[4*j+3]);
}

// ---------------------------------------------------------------------------
// QKV projection as register-tiled GEMM.
// Block: 128 rows x 192 cols, 512 threads; thread: 8 rows x 6 cols.
// sH row-major with stride 66 (conflict-free k-column reads),
// sW [k][192] q|k|v interleaved. FFMA2 throughout.
// ---------------------------------------------------------------------------
#define QT_HSTRIDE 66
__global__ __launch_bounds__(512)
void k_qkv(const float* __restrict__ Wq, const float* __restrict__ bq,
           const float* __restrict__ Wk, const float* __restrict__ bk,
           const float* __restrict__ Wv, const float* __restrict__ bv)
{
    extern __shared__ float qs[];
    float* sH = qs;                       // 128 * 66 = 8448 floats
    float* sW = sH + 128 * QT_HSTRIDE;    // 12288 floats
    float* sb = sW + 12288;               // 192

    int tid = threadIdx.x;
    size_t rowbase = (size_t)blockIdx.x * 128;

    // Stage weights/bias (interleaved q|k|v per k)
    for (int i = tid; i < 12288; i += 512) {
        int j = i / 192, e = i % 192;
        sW[i] = (e < 64) ? Wq[j*64 + e] : (e < 128) ? Wk[j*64 + e - 64] : Wv[j*64 + e - 128];
    }
    for (int i = tid; i < 192; i += 512)
        sb[i] = (i < 64) ? bq[i] : (i < 128) ? bk[i - 64] : bv[i - 128];

    // Stage h tile: 128 rows x 64 cols -> sH (stride 66), float2 coalesced
    {
        const float2* hsrc = (const float2*)(g_h + rowbase * 64);
        #pragma unroll
        for (int it = 0; it < 8; it++) {
            int i2 = it * 512 + tid;          // 0..4095
            int row = i2 >> 5, c2 = i2 & 31;
            float2 v = hsrc[i2];
            *(float2*)&sH[row * QT_HSTRIDE + c2 * 2] = v;
        }
    }
    __syncthreads();

    int rg = tid & 15;        // row group: rows rg + 16*i
    int cg = tid >> 4;        // col group: cols cg*6 .. cg*6+5

    unsigned long long acc[8][3];
    {
        float b0 = sb[cg*6], b1 = sb[cg*6+1], b2_ = sb[cg*6+2];
        float b3 = sb[cg*6+3], b4 = sb[cg*6+4], b5 = sb[cg*6+5];
        #pragma unroll
        for (int i = 0; i < 8; i++) {
            acc[i][0] = pack2(b0, b1);
            acc[i][1] = pack2(b2_, b3);
            acc[i][2] = pack2(b4, b5);
        }
    }

    const float* sWrow = sW + cg * 6;
    #pragma unroll 4
    for (int k = 0; k < 64; k++) {
        unsigned long long w0 = *(const unsigned long long*)(sWrow + k*192);
        unsigned long long w1 = *(const unsigned long long*)(sWrow + k*192 + 2);
        unsigned long long w2 = *(const unsigned long long*)(sWrow + k*192 + 4);
        #pragma unroll
        for (int i = 0; i < 8; i++) {
            float hv = sH[(rg + 16*i) * QT_HSTRIDE + k];
            unsigned long long h2 = packdup(hv);
            ffma2(acc[i][0], h2, w0);
            ffma2(acc[i][1], h2, w1);
            ffma2(acc[i][2], h2, w2);
        }
    }

    // Write out: rows rg+16i, cols cg*6..cg*6+5 (three 8B stores each)
    #pragma unroll
    for (int i = 0; i < 8; i++) {
        size_t row = rowbase + rg + 16*i;
        unsigned long long* dst = (unsigned long long*)(g_qkv + row * H3c + cg * 6);
        dst[0] = acc[i][0];
        dst[1] = acc[i][1];
        dst[2] = acc[i][2];
    }
}

// ---------------------------------------------------------------------------
// Attention per (t,b,f) (unchanged).
// ---------------------------------------------------------------------------
__global__ __launch_bounds__(256)
void k_attn(const int* __restrict__ indices)
{
    __shared__ __align__(16) float sR[8][3][192];
    __shared__ __align__(16) float sO[8][3][64];

    int warp = threadIdx.x >> 5, lane = threadIdx.x & 31;
    int inst = blockIdx.x * 8 + warp;
    int tb = inst >> 14;
    int f  = inst & 16383;

    int idx[3] = {__ldg(&indices[f*3]), __ldg(&indices[f*3+1]), __ldg(&indices[f*3+2])};

    const float* base = g_qkv + (size_t)tb * Nn * H3c;
    #pragma unroll
    for (int k = 0; k < 3; k++) {
        const float* row = base + (size_t)idx[k] * H3c;
        #pragma unroll
        for (int u = 0; u < 6; u++) sR[warp][k][u*32 + lane] = row[u*32 + lane];
    }
    __syncwarp();

    if (lane < 12) {
        int qr = lane >> 2, hh = lane & 3;
        const float* q = &sR[warp][qr][hh * 16];
        float l[3];
        #pragma unroll
        for (int kr = 0; kr < 3; kr++) {
            const float* kv = &sR[warp][kr][64 + hh * 16];
            float s = 0.f;
            #pragma unroll
            for (int d = 0; d < 16; d++) s += q[d] * kv[d];
            l[kr] = s * 0.25f;
        }
        float m = fmaxf(l[0], fmaxf(l[1], l[2]));
        float e0 = expf(l[0] - m), e1 = expf(l[1] - m), e2 = expf(l[2] - m);
        float inv = 1.f / (e0 + e1 + e2);
        e0 *= inv; e1 *= inv; e2 *= inv;
        const float* v0 = &sR[warp][0][128 + hh * 16];
        const float* v1 = &sR[warp][1][128 + hh * 16];
        const float* v2 = &sR[warp][2][128 + hh * 16];
        #pragma unroll
        for (int d = 0; d < 16; d++)
            sO[warp][qr][hh*16 + d] = e0 * v0[d] + e1 * v1[d] + e2 * v2[d];
    }
    __syncwarp();

    float4* yo = (float4*)g_yo + (size_t)tb * Nn * 16;
    if (lane < 16) {
        #pragma unroll
        for (int k = 0; k < 3; k++) {
            float4 v = ((const float4*)sO[warp][k])[lane];
            atomicAdd(&yo[(size_t)idx[k] * 16 + lane], v);
        }
    }
}

// ---------------------------------------------------------------------------
__global__ __launch_bounds__(256)
void k_sum(const float* __restrict__ nnz)
{
    __shared__ float red[4][64];
    __shared__ float red0[4];
    int blk = blockIdx.x;        // 0..255
    int g = blk >> 2, chunk = blk & 3;
    int tid = threadIdx.x;
    int r4 = tid >> 6;
    int col = tid & 63;

    float acc = 0.f, acc0 = 0.f;
    int nbase = (g & 3) * 4096;
    const float* yob = g_yo + (size_t)g * 4096 * 64;
    int rend = (chunk + 1) * 1024;
    for (int rr = chunk * 1024 + r4; rr < rend; rr += 4) {
        int n = nbase + rr;
        float inv = 1.f / nnz[n];
        acc += yob[(size_t)rr * 64 + col] * inv;
        if (col == 0) acc0 += (float)g_cnt[n] * inv;
    }
    red[r4][col] = acc;
    if (col == 0) red0[r4] = acc0;
    __syncthreads();
    if (tid < 64)
        atomicAdd(&g_s1[g * 64 + tid], red[0][tid] + red[1][tid] + red[2][tid] + red[3][tid]);
    if (tid == 0)
        atomicAdd(&g_s0[g], red0[0] + red0[1] + red0[2] + red0[3]);
}

// ---------------------------------------------------------------------------
// Logit head (unchanged from R5).
// ---------------------------------------------------------------------------
__global__ __launch_bounds__(256, 2)
void k_post(const float* __restrict__ nnz,
            const float* __restrict__ W2, const float* __restrict__ b2,
            float* __restrict__ logit_out)
{
    extern __shared__ float ps[];
    float4* sT4 = (float4*)ps;                 // 256 rows x 17 float4 (pad)
    float*  sM  = ps + 256*17*4;               // 4096
    float*  sc1 = sM + 4096;                   // 64
    float*  sE  = sc1 + 64;                    // 64
    float*  sW2 = sE + 64;                     // 64

    int tid = threadIdx.x;
    int rowbase = blockIdx.x * 256;
    int g = rowbase >> 12;

    const float4* yo4 = (const float4*)g_yo + (size_t)rowbase * 16;
    for (int i = tid; i < 4096; i += 256)
        sT4[(i >> 4) * 17 + (i & 15)] = yo4[i];
    for (int i = tid; i < 4096; i += 256) sM[i] = g_M[i];
    if (tid < 64) { sc1[tid] = g_c1[tid]; sE[tid] = g_E[g*64 + tid]; sW2[tid] = W2[tid]; }
    __syncthreads();

    int row = rowbase + tid;
    int n = row & 16383;
    float inv = 1.f / nnz[n];
    float cninv = (float)g_cnt[n] * inv;

    float yo[64];
    #pragma unroll
    for (int jj = 0; jj < 16; jj++) {
        float4 v = sT4[tid * 17 + jj];
        yo[4*jj] = v.x; yo[4*jj+1] = v.y; yo[4*jj+2] = v.z; yo[4*jj+3] = v.w;
    }

    const ulonglong2* sM2 = (const ulonglong2*)sM;
    float logit = 0.f;
    #pragma unroll 1
    for (int p = 0; p < 8; p++) {
        unsigned long long acc[4] = {0ULL, 0ULL, 0ULL, 0ULL};
        #pragma unroll
        for (int j = 0; j < 64; j++) {
            unsigned long long y2 = packdup(yo[j]);
            ulonglong2 w0 = sM2[j*16 + p*2];
            ulonglong2 w1 = sM2[j*16 + p*2 + 1];
            ffma2(acc[0], y2, w0.x);
            ffma2(acc[1], y2, w0.y);
            ffma2(acc[2], y2, w1.x);
            ffma2(acc[3], y2, w1.y);
        }
        #pragma unroll
        for (int q = 0; q < 4; q++) {
            float2 v = unpack2(acc[q]);
            int c = p*8 + q*2;
            float pre, rr;
            pre = inv*v.x + cninv*sc1[c]   + sE[c];   rr = fmaxf(pre, 0.f); logit += rr*sW2[c];
            pre = inv*v.y + cninv*sc1[c+1] + sE[c+1]; rr = fmaxf(pre, 0.f); logit += rr*sW2[c+1];
        }
    }
    logit_out[row] = logit + b2[0];
}

// ---------------------------------------------------------------------------
__global__ void k_value(const float* __restrict__ extra,
                        const float* __restrict__ Wv1, const float* __restrict__ bv1,
                        float* __restrict__ val_out)
{
    __shared__ float sv[64];
    int tid = threadIdx.x;                  // 64 = (tb,kall)
    float acc = 0.f;
    #pragma unroll
    for (int j = 0; j < 64; j++) acc += g_s1[tid*64 + j] * g_wv[j];
    acc += g_s0[tid] * g_bv[0];
    acc *= (1.f / (float)N0c);
    #pragma unroll
    for (int d = 0; d < 4; d++) acc += extra[tid*4 + d] * Wv1[64 + d];
    acc += bv1[0];
    sv[tid] = acc;
    __syncthreads();
    if (tid < 16)
        val_out[tid] = sv[tid*4] + sv[tid*4+1] + sv[tid*4+2] + sv[tid*4+3];
}

// ---------------------------------------------------------------------------
extern "C" void kernel_launch(void* const* d_in, const int* in_sizes, int n_in,
                              void* d_out, int out_size)
{
    const float* h0       = (const float*)d_in[0];
    const float* h_global = (const float*)d_in[1];
    const float* x        = (const float*)d_in[2];
    const float* extra    = (const float*)d_in[3];
    const uint32_t* dones = (const uint32_t*)d_in[4];
    const int*   indices  = (const int*)d_in[5];
    const float* nnz      = (const float*)d_in[6];
    const float* Wi  = (const float*)d_in[7];
    const float* bi  = (const float*)d_in[8];
    const float* Wh  = (const float*)d_in[9];
    const float* bhn = (const float*)d_in[10];
    const float* Wq  = (const float*)d_in[11];
    const float* bq  = (const float*)d_in[12];
    const float* Wk  = (const float*)d_in[13];
    const float* bk  = (const float*)d_in[14];
    const float* Wv  = (const float*)d_in[15];
    const float* bv  = (const float*)d_in[16];
    const float* Wo  = (const float*)d_in[17];
    const float* bo  = (const float*)d_in[18];
    const float* W1  = (const float*)d_in[19];
    const float* b1  = (const float*)d_in[20];
    const float* W2  = (const float*)d_in[21];
    const float* b2  = (const float*)d_in[22];
    const float* Wv1 = (const float*)d_in[23];
    const float* bv1 = (const float*)d_in[24];

    float* out       = (float*)d_out;
    float* out_hfin  = out;
    float* out_hg    = out + OFF_HG;
    float* out_logit = out + OFF_LOGIT;
    float* out_val   = out + OFF_VAL;

    void *yo_ptr, *cnt_ptr, *s1_ptr, *s0_ptr;
    cudaGetSymbolAddress(&yo_ptr,  g_yo);
    cudaGetSymbolAddress(&cnt_ptr, g_cnt);
    cudaGetSymbolAddress(&s1_ptr,  g_s1);
    cudaGetSymbolAddress(&s0_ptr,  g_s0);
    cudaMemsetAsync(yo_ptr,  0, sizeof(float) * (size_t)TBNc * Hh, 0);
    cudaMemsetAsync(cnt_ptr, 0, sizeof(int) * Nn, 0);
    cudaMemsetAsync(s1_ptr,  0, sizeof(float) * 64 * 64, 0);
    cudaMemsetAsync(s0_ptr,  0, sizeof(float) * 64, 0);

    cudaMemcpyAsync(out_hg, h_global, 1024 * sizeof(float), cudaMemcpyDeviceToDevice, 0);

    int smem_gru  = (12288 + 768 + 192 + 64) * 4;                 // 53248 B
    cudaFuncSetAttribute(k_gru, cudaFuncAttributeMaxDynamicSharedMemorySize, smem_gru);
    int smem_qkv  = (128*QT_HSTRIDE + 12288 + 192) * 4;            // 83712 B
    cudaFuncSetAttribute(k_qkv, cudaFuncAttributeMaxDynamicSharedMemorySize, smem_qkv);
    int smem_post = (256*17*4 + 4096 + 64 + 64 + 64) * 4;          // 87040 B
    cudaFuncSetAttribute(k_post, cudaFuncAttributeMaxDynamicSharedMemorySize, smem_post);

    k_count<<<(Ff * ORD + 255) / 256, 256>>>(indices);
    k_prep<<<32, 256>>>(Wo, bo, W1, b1, Wv1, extra);
    k_gru<<<BNc / 128, 128, smem_gru>>>(h0, x, dones, Wi, bi, Wh, bhn, out_hfin);
    k_qkv<<<TBNc / 128, 512, smem_qkv>>>(Wq, bq, Wk, bk, Wv, bv);
    k_attn<<<TBc * Ff / 8, 256>>>(indices);
    k_sum<<<256, 256>>>(nnz);
    k_post<<<TBNc / 256, 256, smem_post>>>(nnz, W2, b2, out_logit);
    k_value<<<1, 64>>>(extra, Wv1, bv1, out_val);
}

// round 8
// speedup vs baseline: 1.1163x; 1.1163x over previous
#include <cuda_runtime.h>
#include <math.h>
#include <stdint.h>

// Problem constants
#define Tt   4
#define Bb   4
#define Nn   16384
#define KALLc 4
#define Ff   16384
#define ORD  3
#define Hh   64
#define N0c  4096

#define TBc  (Tt*Bb)        // 16
#define BNc  (Bb*Nn)        // 65536
#define TBNc (TBc*Nn)       // 262144
#define H3c  (3*Hh)         // 192

// Output layout: h_fin [B,N,H] | h_global [B,K,64] | logit [T,B,N] | value [T,B]
#define OFF_HG    4194304
#define OFF_LOGIT (OFF_HG + 1024)
#define OFF_VAL   (OFF_LOGIT + 262144)

// Scratch
__device__ float g_h  [TBNc * Hh];    // [T,B,N,64] hidden states per step
__device__ float g_qkv[TBNc * H3c];   // [T,B,N,192]
__device__ float g_yo [TBNc * Hh];    // [T,B,N,64]
__device__ int   g_cnt[Nn];
__device__ float g_M  [64*64];        // Wo @ W1[:64]
__device__ float g_c1 [64];           // bo @ W1[:64]
__device__ float g_E  [64*64];        // per (tb,kall): b1 + extra@W1[64:]
__device__ float g_wv [64];           // Wo @ Wv1[:64]
__device__ float g_bv [1];            // bo @ Wv1[:64]
__device__ float g_s1 [64*64];        // per (tb,kall): sum_n yo*invnnz
__device__ float g_s0 [64];           // per (tb,kall): sum_n cnt*invnnz

__device__ __forceinline__ float sigmoidf_(float v) { return 1.f / (1.f + expf(-v)); }
__device__ __forceinline__ void fma4_(float4& a, float s, float4 w) {
    a.x += s * w.x; a.y += s * w.y; a.z += s * w.z; a.w += s * w.w;
}

// ---- packed fp32 helpers (fma.rn.f32x2) ----
__device__ __forceinline__ unsigned long long packdup(float v) {
    unsigned long long r;
    asm("mov.b64 %0, {%1, %1};" : "=l"(r) : "f"(v));
    return r;
}
__device__ __forceinline__ unsigned long long pack2(float a, float b) {
    unsigned long long r;
    asm("mov.b64 %0, {%1, %2};" : "=l"(r) : "f"(a), "f"(b));
    return r;
}
__device__ __forceinline__ void ffma2(unsigned long long& acc,
                                      unsigned long long a, unsigned long long b) {
    asm("fma.rn.f32x2 %0, %1, %2, %0;" : "+l"(acc) : "l"(a), "l"(b));
}
__device__ __forceinline__ float2 unpack2(unsigned long long v) {
    float lo, hi;
    asm("mov.b64 {%0, %1}, %2;" : "=f"(lo), "=f"(hi) : "l"(v));
    return make_float2(lo, hi);
}

// ---- cp.async helpers ----
__device__ __forceinline__ uint32_t smem_u32_(const void* p) {
    uint32_t a;
    asm("{ .reg .u64 t; cvta.to.shared.u64 t, %1; cvt.u32.u64 %0, t; }" : "=r"(a) : "l"(p));
    return a;
}
__device__ __forceinline__ void cpasync16(uint32_t dst, const void* src) {
    asm volatile("cp.async.cg.shared.global [%0], [%1], 16;" :: "r"(dst), "l"(src));
}
__device__ __forceinline__ void cpasync_commit() {
    asm volatile("cp.async.commit_group;" ::: "memory");
}
__device__ __forceinline__ void cpasync_wait0() {
    asm volatile("cp.async.wait_group 0;" ::: "memory");
}
__device__ __forceinline__ void cpasync_wait1() {
    asm volatile("cp.async.wait_group 1;" ::: "memory");
}

// ---------------------------------------------------------------------------
__global__ void k_count(const int* __restrict__ indices) {
    int i = blockIdx.x * 256 + threadIdx.x;
    if (i < Ff * ORD) atomicAdd(&g_cnt[indices[i]], 1);
}

// ---------------------------------------------------------------------------
__global__ void k_prep(const float* __restrict__ Wo, const float* __restrict__ bo,
                       const float* __restrict__ W1, const float* __restrict__ b1,
                       const float* __restrict__ Wv1,
                       const float* __restrict__ extra)
{
    int o = blockIdx.x * 256 + threadIdx.x;   // grid 32 x 256 = 8192
    if (o < 4096) {
        int j = o >> 6, c = o & 63;
        float s = 0.f;
        #pragma unroll
        for (int h = 0; h < 64; h++) s += Wo[j*64 + h] * W1[h*64 + c];
        g_M[o] = s;
    } else {
        int e = o - 4096;
        int g = e >> 6, c = e & 63;
        float s = b1[c];
        #pragma unroll
        for (int d = 0; d < 4; d++) s += extra[g*4 + d] * W1[(64 + d)*64 + c];
        g_E[e] = s;
    }
    if (blockIdx.x == 0 && threadIdx.x < 64) {
        int tid = threadIdx.x;
        float s = 0.f, w = 0.f;
        #pragma unroll
        for (int h = 0; h < 64; h++) {
            s += bo[h] * W1[h*64 + tid];
            w += Wo[tid*64 + h] * Wv1[h];
        }
        g_c1[tid] = s;
        g_wv[tid] = w;
        if (tid == 0) {
            float bvv = 0.f;
            #pragma unroll
            for (int h = 0; h < 64; h++) bvv += bo[h] * Wv1[h];
            g_bv[0] = bvv;
        }
    }
}

// ---------------------------------------------------------------------------
// GRU scan only (T=4). One thread per (b,n). (unchanged, passing)
// ---------------------------------------------------------------------------
__global__ __launch_bounds__(128, 3)
void k_gru(const float* __restrict__ h0, const float* __restrict__ x,
           const uint32_t* __restrict__ dones,
           const float* __restrict__ Wi, const float* __restrict__ bi,
           const float* __restrict__ Wh, const float* __restrict__ bhn,
           float* __restrict__ hfin_out)
{
    extern __shared__ float smem[];
    float* sWh  = smem;              // 12288
    float* sWi  = sWh + 12288;       // 768
    float* sbi  = sWi + 768;         // 192
    float* sbhn = sbi + 192;         // 64

    for (int i = threadIdx.x; i < 12288; i += 128) sWh[i] = Wh[i];
    for (int i = threadIdx.x; i < 768;   i += 128) sWi[i] = Wi[i];
    for (int i = threadIdx.x; i < 192;   i += 128) sbi[i] = bi[i];
    for (int i = threadIdx.x; i < 64;    i += 128) sbhn[i] = bhn[i];
    __syncthreads();

    const float4* sWi4  = (const float4*)sWi;
    const float4* sbi4  = (const float4*)sbi;
    const float4* sbhn4 = (const float4*)sbhn;
    const ulonglong2* sWh2 = (const ulonglong2*)sWh;

    int gid = blockIdx.x * 128 + threadIdx.x;
    int b = gid >> 14;

    float h[64];
    {
        const float4* h04 = (const float4*)(h0 + (size_t)gid * 64);
        #pragma unroll
        for (int j = 0; j < 16; j++) {
            float4 v = h04[j];
            h[4*j] = v.x; h[4*j+1] = v.y; h[4*j+2] = v.z; h[4*j+3] = v.w;
        }
    }

    #pragma unroll 1
    for (int t = 0; t < Tt; t++) {
        if (dones[t * Bb + b] != 0u) {
            #pragma unroll
            for (int j = 0; j < 64; j++) h[j] = 0.f;
        }
        float4 xt4 = ((const float4*)x)[(size_t)t * BNc + gid];
        float xt[4] = {xt4.x, xt4.y, xt4.z, xt4.w};

        float hn[64];
        #pragma unroll
        for (int kk = 0; kk < 16; kk++) {
            unsigned long long ar0=0ULL, ar1=0ULL, az0=0ULL, az1=0ULL, an0=0ULL, an1=0ULL;
            #pragma unroll
            for (int j = 0; j < 64; j++) {
                unsigned long long h2 = packdup(h[j]);
                ulonglong2 wr = sWh2[j*48 + kk];
                ulonglong2 wz = sWh2[j*48 + 16 + kk];
                ulonglong2 wn = sWh2[j*48 + 32 + kk];
                ffma2(ar0, h2, wr.x); ffma2(ar1, h2, wr.y);
                ffma2(az0, h2, wz.x); ffma2(az1, h2, wz.y);
                ffma2(an0, h2, wn.x); ffma2(an1, h2, wn.y);
            }
            float2 arl = unpack2(ar0), arh = unpack2(ar1);
            float2 azl = unpack2(az0), azh = unpack2(az1);
            float2 anl = unpack2(an0), anh = unpack2(an1);
            float4 ar = {arl.x, arl.y, arh.x, arh.y};
            float4 az = {azl.x, azl.y, azh.x, azh.y};
            float4 an = {anl.x, anl.y, anh.x, anh.y};

            float4 gr = sbi4[kk], gz = sbi4[16 + kk], gn = sbi4[32 + kk];
            #pragma unroll
            for (int d = 0; d < 4; d++) {
                float xd = xt[d];
                fma4_(gr, xd, sWi4[d*48 + kk]);
                fma4_(gz, xd, sWi4[d*48 + 16 + kk]);
                fma4_(gn, xd, sWi4[d*48 + 32 + kk]);
            }
            float4 bn4 = sbhn4[kk];
            float r, z, nv;
            r = sigmoidf_(gr.x + ar.x); z = sigmoidf_(gz.x + az.x);
            nv = tanhf(gn.x + r * (an.x + bn4.x));
            hn[4*kk+0] = (1.f - z) * nv + z * h[4*kk+0];
            r = sigmoidf_(gr.y + ar.y); z = sigmoidf_(gz.y + az.y);
            nv = tanhf(gn.y + r * (an.y + bn4.y));
            hn[4*kk+1] = (1.f - z) * nv + z * h[4*kk+1];
            r = sigmoidf_(gr.z + ar.z); z = sigmoidf_(gz.z + az.z);
            nv = tanhf(gn.z + r * (an.z + bn4.z));
            hn[4*kk+2] = (1.f - z) * nv + z * h[4*kk+2];
            r = sigmoidf_(gr.w + ar.w); z = sigmoidf_(gz.w + az.w);
            nv = tanhf(gn.w + r * (an.w + bn4.w));
            hn[4*kk+3] = (1.f - z) * nv + z * h[4*kk+3];
        }
        #pragma unroll
        for (int j = 0; j < 64; j++) h[j] = hn[j];

        float4* hout = (float4*)(g_h + ((size_t)t * BNc + gid) * 64);
        #pragma unroll
        for (int j = 0; j < 16; j++)
            hout[j] = make_float4(h[4*j], h[4*j+1], h[4*j+2], h[4*j+3]);
    }

    float4* ho = (float4*)(hfin_out + (size_t)gid * 64);
    #pragma unroll
    for (int j = 0; j < 16; j++)
        ho[j] = make_float4(h[4*j], h[4*j+1], h[4*j+2], h[4*j+3]);
}

// ---------------------------------------------------------------------------
// QKV projection: persistent register-tiled GEMM with cp.async double buffer.
// grid=148 x 512 threads. W (48KB) staged once; H tiles (128 rows, stride-68
// padded) prefetched into a 2-deep ring. Thread tile: 8 rows x 6 cols.
// Warp mapping: rg=tid>>5 (row group), cg=tid&31 (col group) ->
//   h reads = broadcast LDS.128 (per 4 k), stores = contiguous 768B per warp.
// ---------------------------------------------------------------------------
#define QKV_NT      2048          // 262144 / 128 tiles
#define QKV_HSTR    68            // floats; 68*4=272 B, 16B aligned per row
#define QKV_SH_W    0             // 12288 floats
#define QKV_SH_B    12288         // 192
#define QKV_SH_H0   12480         // 8704
#define QKV_SH_H1   21184         // 8704
#define QKV_SH_TOT  29888

__device__ __forceinline__ void qkv_prefetch(uint32_t sh_dst, const float* gsrc, int tid) {
    const float4* src = (const float4*)gsrc;
    #pragma unroll
    for (int c = 0; c < 4; c++) {
        int chunk = c * 512 + tid;           // 0..2047
        int row = chunk >> 4, c4 = chunk & 15;
        cpasync16(sh_dst + row * (QKV_HSTR*4) + c4 * 16, src + chunk);
    }
    cpasync_commit();
}

__global__ __launch_bounds__(512)
void k_qkv(const float* __restrict__ Wq, const float* __restrict__ bq,
           const float* __restrict__ Wk, const float* __restrict__ bk,
           const float* __restrict__ Wv, const float* __restrict__ bv)
{
    extern __shared__ float qs[];
    float* sW = qs + QKV_SH_W;
    float* sb = qs + QKV_SH_B;

    int tid = threadIdx.x;

    // Stage weights/bias once (interleaved q|k|v per k-row)
    for (int i = tid; i < 12288; i += 512) {
        int j = i / 192, e = i % 192;
        sW[i] = (e < 64) ? Wq[j*64 + e] : (e < 128) ? Wk[j*64 + e - 64] : Wv[j*64 + e - 128];
    }
    for (int i = tid; i < 192; i += 512)
        sb[i] = (i < 64) ? bq[i] : (i < 128) ? bk[i - 64] : bv[i - 128];

    uint32_t shbase = smem_u32_(qs);
    uint32_t shH[2] = {shbase + QKV_SH_H0*4, shbase + QKV_SH_H1*4};
    float*   sH[2]  = {qs + QKV_SH_H0, qs + QKV_SH_H1};

    int rg = tid >> 5;        // 0..15: rows rg + 16*i
    int cg = tid & 31;        // 0..31: cols cg*6 .. cg*6+5

    float bc[6];
    // bias regs loaded after sb staged; need sync first
    int t0 = blockIdx.x;
    if (t0 < QKV_NT)
        qkv_prefetch(shH[0], g_h + (size_t)t0 * 128 * 64, tid);
    __syncthreads();          // sW/sb visible (also orders prefetch issue)

    #pragma unroll
    for (int j = 0; j < 6; j++) bc[j] = sb[cg*6 + j];

    int buf = 0;
    for (int t = t0; t < QKV_NT; t += gridDim.x) {
        int nxt = t + gridDim.x;
        bool pf = (nxt < QKV_NT);
        if (pf) qkv_prefetch(shH[buf^1], g_h + (size_t)nxt * 128 * 64, tid);
        if (pf) cpasync_wait1(); else cpasync_wait0();
        __syncthreads();

        const float* H = sH[buf];
        unsigned long long acc[8][3];
        #pragma unroll
        for (int i = 0; i < 8; i++) {
            acc[i][0] = pack2(bc[0], bc[1]);
            acc[i][1] = pack2(bc[2], bc[3]);
            acc[i][2] = pack2(bc[4], bc[5]);
        }

        const float* sWrow = sW + cg * 6;
        #pragma unroll 1
        for (int k4 = 0; k4 < 16; k4++) {
            unsigned long long w[4][3];
            #pragma unroll
            for (int kk = 0; kk < 4; kk++) {
                const float* wr = sWrow + (k4*4 + kk) * 192;
                w[kk][0] = *(const unsigned long long*)(wr);
                w[kk][1] = *(const unsigned long long*)(wr + 2);
                w[kk][2] = *(const unsigned long long*)(wr + 4);
            }
            #pragma unroll
            for (int i = 0; i < 8; i++) {
                float4 hv = *(const float4*)&H[(rg + 16*i) * QKV_HSTR + k4*4];
                unsigned long long h0 = packdup(hv.x);
                ffma2(acc[i][0], h0, w[0][0]); ffma2(acc[i][1], h0, w[0][1]); ffma2(acc[i][2], h0, w[0][2]);
                unsigned long long h1 = packdup(hv.y);
                ffma2(acc[i][0], h1, w[1][0]); ffma2(acc[i][1], h1, w[1][1]); ffma2(acc[i][2], h1, w[1][2]);
                unsigned long long h2 = packdup(hv.z);
                ffma2(acc[i][0], h2, w[2][0]); ffma2(acc[i][1], h2, w[2][1]); ffma2(acc[i][2], h2, w[2][2]);
                unsigned long long h3 = packdup(hv.w);
                ffma2(acc[i][0], h3, w[3][0]); ffma2(acc[i][1], h3, w[3][1]); ffma2(acc[i][2], h3, w[3][2]);
            }
        }

        // Store: warp lanes cover cols 0..191 of one row -> contiguous 768B
        size_t rowbase = (size_t)t * 128;
        #pragma unroll
        for (int i = 0; i < 8; i++) {
            unsigned long long* dst =
                (unsigned long long*)(g_qkv + (rowbase + rg + 16*i) * H3c + cg * 6);
            dst[0] = acc[i][0];
            dst[1] = acc[i][1];
            dst[2] = acc[i][2];
        }
        __syncthreads();      // all reads of sH[buf] done before it is refilled
        buf ^= 1;
    }
}

// ---------------------------------------------------------------------------
// Attention per (t,b,f) (unchanged).
// ---------------------------------------------------------------------------
__global__ __launch_bounds__(256)
void k_attn(const int* __restrict__ indices)
{
    __shared__ __align__(16) float sR[8][3][192];
    __shared__ __align__(16) float sO[8][3][64];

    int warp = threadIdx.x >> 5, lane = threadIdx.x & 31;
    int inst = blockIdx.x * 8 + warp;
    int tb = inst >> 14;
    int f  = inst & 16383;

    int idx[3] = {__ldg(&indices[f*3]), __ldg(&indices[f*3+1]), __ldg(&indices[f*3+2])};

    const float* base = g_qkv + (size_t)tb * Nn * H3c;
    #pragma unroll
    for (int k = 0; k < 3; k++) {
        const float* row = base + (size_t)idx[k] * H3c;
        #pragma unroll
        for (int u = 0; u < 6; u++) sR[warp][k][u*32 + lane] = row[u*32 + lane];
    }
    __syncwarp();

    if (lane < 12) {
        int qr = lane >> 2, hh = lane & 3;
        const float* q = &sR[warp][qr][hh * 16];
        float l[3];
        #pragma unroll
        for (int kr = 0; kr < 3; kr++) {
            const float* kv = &sR[warp][kr][64 + hh * 16];
            float s = 0.f;
            #pragma unroll
            for (int d = 0; d < 16; d++) s += q[d] * kv[d];
            l[kr] = s * 0.25f;
        }
        float m = fmaxf(l[0], fmaxf(l[1], l[2]));
        float e0 = expf(l[0] - m), e1 = expf(l[1] - m), e2 = expf(l[2] - m);
        float inv = 1.f / (e0 + e1 + e2);
        e0 *= inv; e1 *= inv; e2 *= inv;
        const float* v0 = &sR[warp][0][128 + hh * 16];
        const float* v1 = &sR[warp][1][128 + hh * 16];
        const float* v2 = &sR[warp][2][128 + hh * 16];
        #pragma unroll
        for (int d = 0; d < 16; d++)
            sO[warp][qr][hh*16 + d] = e0 * v0[d] + e1 * v1[d] + e2 * v2[d];
    }
    __syncwarp();

    float4* yo = (float4*)g_yo + (size_t)tb * Nn * 16;
    if (lane < 16) {
        #pragma unroll
        for (int k = 0; k < 3; k++) {
            float4 v = ((const float4*)sO[warp][k])[lane];
            atomicAdd(&yo[(size_t)idx[k] * 16 + lane], v);
        }
    }
}

// ---------------------------------------------------------------------------
__global__ __launch_bounds__(256)
void k_sum(const float* __restrict__ nnz)
{
    __shared__ float red[4][64];
    __shared__ float red0[4];
    int blk = blockIdx.x;        // 0..255
    int g = blk >> 2, chunk = blk & 3;
    int tid = threadIdx.x;
    int r4 = tid >> 6;
    int col = tid & 63;

    float acc = 0.f, acc0 = 0.f;
    int nbase = (g & 3) * 4096;
    const float* yob = g_yo + (size_t)g * 4096 * 64;
    int rend = (chunk + 1) * 1024;
    for (int rr = chunk * 1024 + r4; rr < rend; rr += 4) {
        int n = nbase + rr;
        float inv = 1.f / nnz[n];
        acc += yob[(size_t)rr * 64 + col] * inv;
        if (col == 0) acc0 += (float)g_cnt[n] * inv;
    }
    red[r4][col] = acc;
    if (col == 0) red0[r4] = acc0;
    __syncthreads();
    if (tid < 64)
        atomicAdd(&g_s1[g * 64 + tid], red[0][tid] + red[1][tid] + red[2][tid] + red[3][tid]);
    if (tid == 0)
        atomicAdd(&g_s0[g], red0[0] + red0[1] + red0[2] + red0[3]);
}

// ---------------------------------------------------------------------------
// Logit head (unchanged from R5).
// ---------------------------------------------------------------------------
__global__ __launch_bounds__(256, 2)
void k_post(const float* __restrict__ nnz,
            const float* __restrict__ W2, const float* __restrict__ b2,
            float* __restrict__ logit_out)
{
    extern __shared__ float ps[];
    float4* sT4 = (float4*)ps;                 // 256 rows x 17 float4 (pad)
    float*  sM  = ps + 256*17*4;               // 4096
    float*  sc1 = sM + 4096;                   // 64
    float*  sE  = sc1 + 64;                    // 64
    float*  sW2 = sE + 64;                     // 64

    int tid = threadIdx.x;
    int rowbase = blockIdx.x * 256;
    int g = rowbase >> 12;

    const float4* yo4 = (const float4*)g_yo + (size_t)rowbase * 16;
    for (int i = tid; i < 4096; i += 256)
        sT4[(i >> 4) * 17 + (i & 15)] = yo4[i];
    for (int i = tid; i < 4096; i += 256) sM[i] = g_M[i];
    if (tid < 64) { sc1[tid] = g_c1[tid]; sE[tid] = g_E[g*64 + tid]; sW2[tid] = W2[tid]; }
    __syncthreads();

    int row = rowbase + tid;
    int n = row & 16383;
    float inv = 1.f / nnz[n];
    float cninv = (float)g_cnt[n] * inv;

    float yo[64];
    #pragma unroll
    for (int jj = 0; jj < 16; jj++) {
        float4 v = sT4[tid * 17 + jj];
        yo[4*jj] = v.x; yo[4*jj+1] = v.y; yo[4*jj+2] = v.z; yo[4*jj+3] = v.w;
    }

    const ulonglong2* sM2 = (const ulonglong2*)sM;
    float logit = 0.f;
    #pragma unroll 1
    for (int p = 0; p < 8; p++) {
        unsigned long long acc[4] = {0ULL, 0ULL, 0ULL, 0ULL};
        #pragma unroll
        for (int j = 0; j < 64; j++) {
            unsigned long long y2 = packdup(yo[j]);
            ulonglong2 w0 = sM2[j*16 + p*2];
            ulonglong2 w1 = sM2[j*16 + p*2 + 1];
            ffma2(acc[0], y2, w0.x);
            ffma2(acc[1], y2, w0.y);
            ffma2(acc[2], y2, w1.x);
            ffma2(acc[3], y2, w1.y);
        }
        #pragma unroll
        for (int q = 0; q < 4; q++) {
            float2 v = unpack2(acc[q]);
            int c = p*8 + q*2;
            float pre, rr;
            pre = inv*v.x + cninv*sc1[c]   + sE[c];   rr = fmaxf(pre, 0.f); logit += rr*sW2[c];
            pre = inv*v.y + cninv*sc1[c+1] + sE[c+1]; rr = fmaxf(pre, 0.f); logit += rr*sW2[c+1];
        }
    }
    logit_out[row] = logit + b2[0];
}

// ---------------------------------------------------------------------------
__global__ void k_value(const float* __restrict__ extra,
                        const float* __restrict__ Wv1, const float* __restrict__ bv1,
                        float* __restrict__ val_out)
{
    __shared__ float sv[64];
    int tid = threadIdx.x;                  // 64 = (tb,kall)
    float acc = 0.f;
    #pragma unroll
    for (int j = 0; j < 64; j++) acc += g_s1[tid*64 + j] * g_wv[j];
    acc += g_s0[tid] * g_bv[0];
    acc *= (1.f / (float)N0c);
    #pragma unroll
    for (int d = 0; d < 4; d++) acc += extra[tid*4 + d] * Wv1[64 + d];
    acc += bv1[0];
    sv[tid] = acc;
    __syncthreads();
    if (tid < 16)
        val_out[tid] = sv[tid*4] + sv[tid*4+1] + sv[tid*4+2] + sv[tid*4+3];
}

// ---------------------------------------------------------------------------
extern "C" void kernel_launch(void* const* d_in, const int* in_sizes, int n_in,
                              void* d_out, int out_size)
{
    const float* h0       = (const float*)d_in[0];
    const float* h_global = (const float*)d_in[1];
    const float* x        = (const float*)d_in[2];
    const float* extra    = (const float*)d_in[3];
    const uint32_t* dones = (const uint32_t*)d_in[4];
    const int*   indices  = (const int*)d_in[5];
    const float* nnz      = (const float*)d_in[6];
    const float* Wi  = (const float*)d_in[7];
    const float* bi  = (const float*)d_in[8];
    const float* Wh  = (const float*)d_in[9];
    const float* bhn = (const float*)d_in[10];
    const float* Wq  = (const float*)d_in[11];
    const float* bq  = (const float*)d_in[12];
    const float* Wk  = (const float*)d_in[13];
    const float* bk  = (const float*)d_in[14];
    const float* Wv  = (const float*)d_in[15];
    const float* bv  = (const float*)d_in[16];
    const float* Wo  = (const float*)d_in[17];
    const float* bo  = (const float*)d_in[18];
    const float* W1  = (const float*)d_in[19];
    const float* b1  = (const float*)d_in[20];
    const float* W2  = (const float*)d_in[21];
    const float* b2  = (const float*)d_in[22];
    const float* Wv1 = (const float*)d_in[23];
    const float* bv1 = (const float*)d_in[24];

    float* out       = (float*)d_out;
    float* out_hfin  = out;
    float* out_hg    = out + OFF_HG;
    float* out_logit = out + OFF_LOGIT;
    float* out_val   = out + OFF_VAL;

    void *yo_ptr, *cnt_ptr, *s1_ptr, *s0_ptr;
    cudaGetSymbolAddress(&yo_ptr,  g_yo);
    cudaGetSymbolAddress(&cnt_ptr, g_cnt);
    cudaGetSymbolAddress(&s1_ptr,  g_s1);
    cudaGetSymbolAddress(&s0_ptr,  g_s0);
    cudaMemsetAsync(yo_ptr,  0, sizeof(float) * (size_t)TBNc * Hh, 0);
    cudaMemsetAsync(cnt_ptr, 0, sizeof(int) * Nn, 0);
    cudaMemsetAsync(s1_ptr,  0, sizeof(float) * 64 * 64, 0);
    cudaMemsetAsync(s0_ptr,  0, sizeof(float) * 64, 0);

    cudaMemcpyAsync(out_hg, h_global, 1024 * sizeof(float), cudaMemcpyDeviceToDevice, 0);

    int smem_gru  = (12288 + 768 + 192 + 64) * 4;                 // 53248 B
    cudaFuncSetAttribute(k_gru, cudaFuncAttributeMaxDynamicSharedMemorySize, smem_gru);
    int smem_qkv  = QKV_SH_TOT * 4;                                // 119552 B
    cudaFuncSetAttribute(k_qkv, cudaFuncAttributeMaxDynamicSharedMemorySize, smem_qkv);
    int smem_post = (256*17*4 + 4096 + 64 + 64 + 64) * 4;          // 87040 B
    cudaFuncSetAttribute(k_post, cudaFuncAttributeMaxDynamicSharedMemorySize, smem_post);

    k_count<<<(Ff * ORD + 255) / 256, 256>>>(indices);
    k_prep<<<32, 256>>>(Wo, bo, W1, b1, Wv1, extra);
    k_gru<<<BNc / 128, 128, smem_gru>>>(h0, x, dones, Wi, bi, Wh, bhn, out_hfin);
    k_qkv<<<148, 512, smem_qkv>>>(Wq, bq, Wk, bk, Wv, bv);
    k_attn<<<TBc * Ff / 8, 256>>>(indices);
    k_sum<<<256, 256>>>(nnz);
    k_post<<<TBNc / 256, 256, smem_post>>>(nnz, W2, b2, out_logit);
    k_value<<<1, 64>>>(extra, Wv1, bv1, out_val);
}

// round 9
// speedup vs baseline: 1.3740x; 1.2309x over previous
#include <cuda_runtime.h>
#include <math.h>
#include <stdint.h>

// Problem constants
#define Tt   4
#define Bb   4
#define Nn   16384
#define KALLc 4
#define Ff   16384
#define ORD  3
#define Hh   64
#define N0c  4096

#define TBc  (Tt*Bb)        // 16
#define BNc  (Bb*Nn)        // 65536
#define TBNc (TBc*Nn)       // 262144
#define H3c  (3*Hh)         // 192

// Output layout: h_fin [B,N,H] | h_global [B,K,64] | logit [T,B,N] | value [T,B]
#define OFF_HG    4194304
#define OFF_LOGIT (OFF_HG + 1024)
#define OFF_VAL   (OFF_LOGIT + 262144)

// Scratch
__device__ float g_h  [TBNc * Hh];    // [T,B,N,64] hidden states per step
__device__ float g_qkv[TBNc * H3c];   // [T,B,N,192]
__device__ float g_yo [TBNc * Hh];    // [T,B,N,64]
__device__ int   g_cnt[Nn];
__device__ float g_M  [64*64];        // Wo @ W1[:64]
__device__ float g_c1 [64];           // bo @ W1[:64]
__device__ float g_E  [64*64];        // per (tb,kall): b1 + extra@W1[64:]
__device__ float g_wv [64];           // Wo @ Wv1[:64]
__device__ float g_bv [1];            // bo @ Wv1[:64]
__device__ float g_s1 [64*64];        // per (tb,kall): sum_n yo*invnnz
__device__ float g_s0 [64];           // per (tb,kall): sum_n cnt*invnnz

__device__ __forceinline__ float sigmoidf_(float v) { return 1.f / (1.f + expf(-v)); }

// ---- packed fp32 helpers (fma.rn.f32x2) ----
__device__ __forceinline__ unsigned long long packdup(float v) {
    unsigned long long r;
    asm("mov.b64 %0, {%1, %1};" : "=l"(r) : "f"(v));
    return r;
}
__device__ __forceinline__ unsigned long long pack2(float a, float b) {
    unsigned long long r;
    asm("mov.b64 %0, {%1, %2};" : "=l"(r) : "f"(a), "f"(b));
    return r;
}
__device__ __forceinline__ void ffma2(unsigned long long& acc,
                                      unsigned long long a, unsigned long long b) {
    asm("fma.rn.f32x2 %0, %1, %2, %0;" : "+l"(acc) : "l"(a), "l"(b));
}
__device__ __forceinline__ float2 unpack2(unsigned long long v) {
    float lo, hi;
    asm("mov.b64 {%0, %1}, %2;" : "=f"(lo), "=f"(hi) : "l"(v));
    return make_float2(lo, hi);
}

// ---- cp.async helpers ----
__device__ __forceinline__ uint32_t smem_u32_(const void* p) {
    uint32_t a;
    asm("{ .reg .u64 t; cvta.to.shared.u64 t, %1; cvt.u32.u64 %0, t; }" : "=r"(a) : "l"(p));
    return a;
}
__device__ __forceinline__ void cpasync16(uint32_t dst, const void* src) {
    asm volatile("cp.async.cg.shared.global [%0], [%1], 16;" :: "r"(dst), "l"(src));
}
__device__ __forceinline__ void cpasync_commit() {
    asm volatile("cp.async.commit_group;" ::: "memory");
}
__device__ __forceinline__ void cpasync_wait0() {
    asm volatile("cp.async.wait_group 0;" ::: "memory");
}
__device__ __forceinline__ void cpasync_wait1() {
    asm volatile("cp.async.wait_group 1;" ::: "memory");
}

// ---------------------------------------------------------------------------
__global__ void k_count(const int* __restrict__ indices) {
    int i = blockIdx.x * 256 + threadIdx.x;
    if (i < Ff * ORD) atomicAdd(&g_cnt[indices[i]], 1);
}

// ---------------------------------------------------------------------------
__global__ void k_prep(const float* __restrict__ Wo, const float* __restrict__ bo,
                       const float* __restrict__ W1, const float* __restrict__ b1,
                       const float* __restrict__ Wv1,
                       const float* __restrict__ extra)
{
    int o = blockIdx.x * 256 + threadIdx.x;   // grid 32 x 256 = 8192
    if (o < 4096) {
        int j = o >> 6, c = o & 63;
        float s = 0.f;
        #pragma unroll
        for (int h = 0; h < 64; h++) s += Wo[j*64 + h] * W1[h*64 + c];
        g_M[o] = s;
    } else {
        int e = o - 4096;
        int g = e >> 6, c = e & 63;
        float s = b1[c];
        #pragma unroll
        for (int d = 0; d < 4; d++) s += extra[g*4 + d] * W1[(64 + d)*64 + c];
        g_E[e] = s;
    }
    if (blockIdx.x == 0 && threadIdx.x < 64) {
        int tid = threadIdx.x;
        float s = 0.f, w = 0.f;
        #pragma unroll
        for (int h = 0; h < 64; h++) {
            s += bo[h] * W1[h*64 + tid];
            w += Wo[tid*64 + h] * Wv1[h];
        }
        g_c1[tid] = s;
        g_wv[tid] = w;
        if (tid == 0) {
            float bvv = 0.f;
            #pragma unroll
            for (int h = 0; h < 64; h++) bvv += bo[h] * Wv1[h];
            g_bv[0] = bvv;
        }
    }
}

// ---------------------------------------------------------------------------
// GRU as block-tiled GEMM. Block = 128 rows x all 4 timesteps, 512 threads.
// Per step: gates GEMM (8 rows x 6 cols per thread, FFMA2) into sG planes
// [r_sum | z_sum | gh_n | gi_n], then pointwise activations update sH.
// smem: Wh 48K | Wi 3K | bi/bhn | x 2K | sH 128x68 34K | sG 128x258 129K
// ---------------------------------------------------------------------------
#define GRU_HSTR  68
#define GRU_GSTR  258
#define GRU_OFF_WI   12288
#define GRU_OFF_BI   (GRU_OFF_WI + 768)
#define GRU_OFF_BHN  (GRU_OFF_BI + 192)
#define GRU_OFF_X    (GRU_OFF_BHN + 64)
#define GRU_OFF_H    (GRU_OFF_X + 512)
#define GRU_OFF_G    (GRU_OFF_H + 128*GRU_HSTR)
#define GRU_SM_TOT   (GRU_OFF_G + 128*GRU_GSTR)   // 55552 floats = 222208 B

__global__ __launch_bounds__(512)
void k_gru(const float* __restrict__ h0, const float* __restrict__ x,
           const uint32_t* __restrict__ dones,
           const float* __restrict__ Wi, const float* __restrict__ bi,
           const float* __restrict__ Wh, const float* __restrict__ bhn,
           float* __restrict__ hfin_out)
{
    extern __shared__ float gs[];
    float* sWh  = gs;
    float* sWi  = gs + GRU_OFF_WI;
    float* sbi  = gs + GRU_OFF_BI;
    float* sbhn = gs + GRU_OFF_BHN;
    float* sX   = gs + GRU_OFF_X;
    float* sH   = gs + GRU_OFF_H;
    float* sG   = gs + GRU_OFF_G;

    int tid = threadIdx.x;
    size_t rowbase = (size_t)blockIdx.x * 128;
    int b = (int)(rowbase >> 14);

    // Stage weights/bias and h0 tile
    for (int i = tid; i < 12288; i += 512) sWh[i] = Wh[i];
    for (int i = tid; i < 768;   i += 512) sWi[i] = Wi[i];
    if (tid < 192) sbi[tid] = bi[tid];
    if (tid < 64)  sbhn[tid] = bhn[tid];
    for (int i = tid; i < 8192; i += 512) {
        int r = i >> 6, c = i & 63;
        sH[r*GRU_HSTR + c] = h0[rowbase*64 + i];
    }

    int rg = tid >> 5;          // 0..15: rows rg + 16*i
    int cg = tid & 31;          // 0..31: cols cg*6 .. cg*6+5
    int c0 = cg * 6;

    #pragma unroll 1
    for (int t = 0; t < Tt; t++) {
        __syncthreads();        // staging / previous pointwise complete

        // stage x_t (128 rows x 4) and reset carry on done
        sX[tid] = x[((size_t)t * BNc + rowbase) * 4 + tid];
        if (dones[t * Bb + b] != 0u) {
            for (int i = tid; i < 8192; i += 512) {
                int r = i >> 6, c = i & 63;
                sH[r*GRU_HSTR + c] = 0.f;
            }
        }
        __syncthreads();

        // ---- gates GEMM: gh[row][c] = sum_k h[row][k] * Wh[k][c] ----
        unsigned long long acc[8][3];
        #pragma unroll
        for (int i = 0; i < 8; i++) { acc[i][0] = 0ULL; acc[i][1] = 0ULL; acc[i][2] = 0ULL; }

        const float* sWrow = sWh + c0;
        #pragma unroll 1
        for (int k4 = 0; k4 < 16; k4++) {
            unsigned long long w[4][3];
            #pragma unroll
            for (int kk = 0; kk < 4; kk++) {
                const float* wr = sWrow + (k4*4 + kk) * 192;
                w[kk][0] = *(const unsigned long long*)(wr);
                w[kk][1] = *(const unsigned long long*)(wr + 2);
                w[kk][2] = *(const unsigned long long*)(wr + 4);
            }
            #pragma unroll
            for (int i = 0; i < 8; i++) {
                float4 hv = *(const float4*)&sH[(rg + 16*i) * GRU_HSTR + k4*4];
                unsigned long long hh0 = packdup(hv.x);
                ffma2(acc[i][0], hh0, w[0][0]); ffma2(acc[i][1], hh0, w[0][1]); ffma2(acc[i][2], hh0, w[0][2]);
                unsigned long long hh1 = packdup(hv.y);
                ffma2(acc[i][0], hh1, w[1][0]); ffma2(acc[i][1], hh1, w[1][1]); ffma2(acc[i][2], hh1, w[1][2]);
                unsigned long long hh2 = packdup(hv.z);
                ffma2(acc[i][0], hh2, w[2][0]); ffma2(acc[i][1], hh2, w[2][1]); ffma2(acc[i][2], hh2, w[2][2]);
                unsigned long long hh3 = packdup(hv.w);
                ffma2(acc[i][0], hh3, w[3][0]); ffma2(acc[i][1], hh3, w[3][1]); ffma2(acc[i][2], hh3, w[3][2]);
            }
        }

        // ---- gi per row + store planes ----
        #pragma unroll
        for (int i = 0; i < 8; i++) {
            int row = rg + 16*i;
            unsigned long long g0 = *(const unsigned long long*)(sbi + c0);
            unsigned long long g1 = *(const unsigned long long*)(sbi + c0 + 2);
            unsigned long long g2 = *(const unsigned long long*)(sbi + c0 + 4);
            #pragma unroll
            for (int d = 0; d < 4; d++) {
                unsigned long long xv = packdup(sX[row*4 + d]);
                const float* wr = sWi + d*192 + c0;
                ffma2(g0, xv, *(const unsigned long long*)(wr));
                ffma2(g1, xv, *(const unsigned long long*)(wr + 2));
                ffma2(g2, xv, *(const unsigned long long*)(wr + 4));
            }
            float av[6], gv[6];
            float2 p;
            p = unpack2(acc[i][0]); av[0] = p.x; av[1] = p.y;
            p = unpack2(acc[i][1]); av[2] = p.x; av[3] = p.y;
            p = unpack2(acc[i][2]); av[4] = p.x; av[5] = p.y;
            p = unpack2(g0); gv[0] = p.x; gv[1] = p.y;
            p = unpack2(g1); gv[2] = p.x; gv[3] = p.y;
            p = unpack2(g2); gv[4] = p.x; gv[5] = p.y;
            float* grow = sG + row * GRU_GSTR;
            #pragma unroll
            for (int j = 0; j < 6; j++) {
                int c = c0 + j;
                if (c < 128) grow[c] = av[j] + gv[j];          // r_sum / z_sum
                else { grow[c] = av[j]; grow[c + 64] = gv[j]; } // gh_n | gi_n
            }
        }
        __syncthreads();

        // ---- pointwise: row = tid>>2, cols (tid&3)*16 .. +15 ----
        {
            int row = tid >> 2;
            int cq = (tid & 3) * 16;
            const float* grow = sG + row * GRU_GSTR;
            float* hrow = sH + row * GRU_HSTR;
            float* gout = g_h + ((size_t)t * BNc + rowbase + row) * 64;
            #pragma unroll
            for (int j = 0; j < 16; j++) {
                int c = cq + j;
                float r = sigmoidf_(grow[c]);
                float z = sigmoidf_(grow[64 + c]);
                float nv = tanhf(grow[192 + c] + r * (grow[128 + c] + sbhn[c]));
                float hv = (1.f - z) * nv + z * hrow[c];
                hrow[c] = hv;
                gout[c] = hv;
            }
        }
    }
    __syncthreads();
    for (int i = tid; i < 8192; i += 512) {
        int r = i >> 6, c = i & 63;
        hfin_out[rowbase*64 + i] = sH[r*GRU_HSTR + c];
    }
}

// ---------------------------------------------------------------------------
// QKV projection: persistent register-tiled GEMM with cp.async double buffer.
// (unchanged from R8, passing, 202us)
// ---------------------------------------------------------------------------
#define QKV_NT      2048          // 262144 / 128 tiles
#define QKV_HSTR    68
#define QKV_SH_W    0
#define QKV_SH_B    12288
#define QKV_SH_H0   12480
#define QKV_SH_H1   21184
#define QKV_SH_TOT  29888

__device__ __forceinline__ void qkv_prefetch(uint32_t sh_dst, const float* gsrc, int tid) {
    const float4* src = (const float4*)gsrc;
    #pragma unroll
    for (int c = 0; c < 4; c++) {
        int chunk = c * 512 + tid;
        int row = chunk >> 4, c4 = chunk & 15;
        cpasync16(sh_dst + row * (QKV_HSTR*4) + c4 * 16, src + chunk);
    }
    cpasync_commit();
}

__global__ __launch_bounds__(512)
void k_qkv(const float* __restrict__ Wq, const float* __restrict__ bq,
           const float* __restrict__ Wk, const float* __restrict__ bk,
           const float* __restrict__ Wv, const float* __restrict__ bv)
{
    extern __shared__ float qs[];
    float* sW = qs + QKV_SH_W;
    float* sb = qs + QKV_SH_B;

    int tid = threadIdx.x;

    for (int i = tid; i < 12288; i += 512) {
        int j = i / 192, e = i % 192;
        sW[i] = (e < 64) ? Wq[j*64 + e] : (e < 128) ? Wk[j*64 + e - 64] : Wv[j*64 + e - 128];
    }
    for (int i = tid; i < 192; i += 512)
        sb[i] = (i < 64) ? bq[i] : (i < 128) ? bk[i - 64] : bv[i - 128];

    uint32_t shbase = smem_u32_(qs);
    uint32_t shH[2] = {shbase + QKV_SH_H0*4, shbase + QKV_SH_H1*4};
    float*   sH[2]  = {qs + QKV_SH_H0, qs + QKV_SH_H1};

    int rg = tid >> 5;
    int cg = tid & 31;

    float bc[6];
    int t0 = blockIdx.x;
    if (t0 < QKV_NT)
        qkv_prefetch(shH[0], g_h + (size_t)t0 * 128 * 64, tid);
    __syncthreads();

    #pragma unroll
    for (int j = 0; j < 6; j++) bc[j] = sb[cg*6 + j];

    int buf = 0;
    for (int t = t0; t < QKV_NT; t += gridDim.x) {
        int nxt = t + gridDim.x;
        bool pf = (nxt < QKV_NT);
        if (pf) qkv_prefetch(shH[buf^1], g_h + (size_t)nxt * 128 * 64, tid);
        if (pf) cpasync_wait1(); else cpasync_wait0();
        __syncthreads();

        const float* H = sH[buf];
        unsigned long long acc[8][3];
        #pragma unroll
        for (int i = 0; i < 8; i++) {
            acc[i][0] = pack2(bc[0], bc[1]);
            acc[i][1] = pack2(bc[2], bc[3]);
            acc[i][2] = pack2(bc[4], bc[5]);
        }

        const float* sWrow = sW + cg * 6;
        #pragma unroll 1
        for (int k4 = 0; k4 < 16; k4++) {
            unsigned long long w[4][3];
            #pragma unroll
            for (int kk = 0; kk < 4; kk++) {
                const float* wr = sWrow + (k4*4 + kk) * 192;
                w[kk][0] = *(const unsigned long long*)(wr);
                w[kk][1] = *(const unsigned long long*)(wr + 2);
                w[kk][2] = *(const unsigned long long*)(wr + 4);
            }
            #pragma unroll
            for (int i = 0; i < 8; i++) {
                float4 hv = *(const float4*)&H[(rg + 16*i) * QKV_HSTR + k4*4];
                unsigned long long h0 = packdup(hv.x);
                ffma2(acc[i][0], h0, w[0][0]); ffma2(acc[i][1], h0, w[0][1]); ffma2(acc[i][2], h0, w[0][2]);
                unsigned long long h1 = packdup(hv.y);
                ffma2(acc[i][0], h1, w[1][0]); ffma2(acc[i][1], h1, w[1][1]); ffma2(acc[i][2], h1, w[1][2]);
                unsigned long long h2 = packdup(hv.z);
                ffma2(acc[i][0], h2, w[2][0]); ffma2(acc[i][1], h2, w[2][1]); ffma2(acc[i][2], h2, w[2][2]);
                unsigned long long h3 = packdup(hv.w);
                ffma2(acc[i][0], h3, w[3][0]); ffma2(acc[i][1], h3, w[3][1]); ffma2(acc[i][2], h3, w[3][2]);
            }
        }

        size_t rowbase = (size_t)t * 128;
        #pragma unroll
        for (int i = 0; i < 8; i++) {
            unsigned long long* dst =
                (unsigned long long*)(g_qkv + (rowbase + rg + 16*i) * H3c + cg * 6);
            dst[0] = acc[i][0];
            dst[1] = acc[i][1];
            dst[2] = acc[i][2];
        }
        __syncthreads();
        buf ^= 1;
    }
}

// ---------------------------------------------------------------------------
// Attention per (t,b,f) (unchanged).
// ---------------------------------------------------------------------------
__global__ __launch_bounds__(256)
void k_attn(const int* __restrict__ indices)
{
    __shared__ __align__(16) float sR[8][3][192];
    __shared__ __align__(16) float sO[8][3][64];

    int warp = threadIdx.x >> 5, lane = threadIdx.x & 31;
    int inst = blockIdx.x * 8 + warp;
    int tb = inst >> 14;
    int f  = inst & 16383;

    int idx[3] = {__ldg(&indices[f*3]), __ldg(&indices[f*3+1]), __ldg(&indices[f*3+2])};

    const float* base = g_qkv + (size_t)tb * Nn * H3c;
    #pragma unroll
    for (int k = 0; k < 3; k++) {
        const float* row = base + (size_t)idx[k] * H3c;
        #pragma unroll
        for (int u = 0; u < 6; u++) sR[warp][k][u*32 + lane] = row[u*32 + lane];
    }
    __syncwarp();

    if (lane < 12) {
        int qr = lane >> 2, hh = lane & 3;
        const float* q = &sR[warp][qr][hh * 16];
        float l[3];
        #pragma unroll
        for (int kr = 0; kr < 3; kr++) {
            const float* kv = &sR[warp][kr][64 + hh * 16];
            float s = 0.f;
            #pragma unroll
            for (int d = 0; d < 16; d++) s += q[d] * kv[d];
            l[kr] = s * 0.25f;
        }
        float m = fmaxf(l[0], fmaxf(l[1], l[2]));
        float e0 = expf(l[0] - m), e1 = expf(l[1] - m), e2 = expf(l[2] - m);
        float inv = 1.f / (e0 + e1 + e2);
        e0 *= inv; e1 *= inv; e2 *= inv;
        const float* v0 = &sR[warp][0][128 + hh * 16];
        const float* v1 = &sR[warp][1][128 + hh * 16];
        const float* v2 = &sR[warp][2][128 + hh * 16];
        #pragma unroll
        for (int d = 0; d < 16; d++)
            sO[warp][qr][hh*16 + d] = e0 * v0[d] + e1 * v1[d] + e2 * v2[d];
    }
    __syncwarp();

    float4* yo = (float4*)g_yo + (size_t)tb * Nn * 16;
    if (lane < 16) {
        #pragma unroll
        for (int k = 0; k < 3; k++) {
            float4 v = ((const float4*)sO[warp][k])[lane];
            atomicAdd(&yo[(size_t)idx[k] * 16 + lane], v);
        }
    }
}

// ---------------------------------------------------------------------------
__global__ __launch_bounds__(256)
void k_sum(const float* __restrict__ nnz)
{
    __shared__ float red[4][64];
    __shared__ float red0[4];
    int blk = blockIdx.x;        // 0..255
    int g = blk >> 2, chunk = blk & 3;
    int tid = threadIdx.x;
    int r4 = tid >> 6;
    int col = tid & 63;

    float acc = 0.f, acc0 = 0.f;
    int nbase = (g & 3) * 4096;
    const float* yob = g_yo + (size_t)g * 4096 * 64;
    int rend = (chunk + 1) * 1024;
    for (int rr = chunk * 1024 + r4; rr < rend; rr += 4) {
        int n = nbase + rr;
        float inv = 1.f / nnz[n];
        acc += yob[(size_t)rr * 64 + col] * inv;
        if (col == 0) acc0 += (float)g_cnt[n] * inv;
    }
    red[r4][col] = acc;
    if (col == 0) red0[r4] = acc0;
    __syncthreads();
    if (tid < 64)
        atomicAdd(&g_s1[g * 64 + tid], red[0][tid] + red[1][tid] + red[2][tid] + red[3][tid]);
    if (tid == 0)
        atomicAdd(&g_s0[g], red0[0] + red0[1] + red0[2] + red0[3]);
}

// ---------------------------------------------------------------------------
// Logit head (unchanged from R5).
// ---------------------------------------------------------------------------
__global__ __launch_bounds__(256, 2)
void k_post(const float* __restrict__ nnz,
            const float* __restrict__ W2, const float* __restrict__ b2,
            float* __restrict__ logit_out)
{
    extern __shared__ float ps[];
    float4* sT4 = (float4*)ps;                 // 256 rows x 17 float4 (pad)
    float*  sM  = ps + 256*17*4;               // 4096
    float*  sc1 = sM + 4096;                   // 64
    float*  sE  = sc1 + 64;                    // 64
    float*  sW2 = sE + 64;                     // 64

    int tid = threadIdx.x;
    int rowbase = blockIdx.x * 256;
    int g = rowbase >> 12;

    const float4* yo4 = (const float4*)g_yo + (size_t)rowbase * 16;
    for (int i = tid; i < 4096; i += 256)
        sT4[(i >> 4) * 17 + (i & 15)] = yo4[i];
    for (int i = tid; i < 4096; i += 256) sM[i] = g_M[i];
    if (tid < 64) { sc1[tid] = g_c1[tid]; sE[tid] = g_E[g*64 + tid]; sW2[tid] = W2[tid]; }
    __syncthreads();

    int row = rowbase + tid;
    int n = row & 16383;
    float inv = 1.f / nnz[n];
    float cninv = (float)g_cnt[n] * inv;

    float yo[64];
    #pragma unroll
    for (int jj = 0; jj < 16; jj++) {
        float4 v = sT4[tid * 17 + jj];
        yo[4*jj] = v.x; yo[4*jj+1] = v.y; yo[4*jj+2] = v.z; yo[4*jj+3] = v.w;
    }

    const ulonglong2* sM2 = (const ulonglong2*)sM;
    float logit = 0.f;
    #pragma unroll 1
    for (int p = 0; p < 8; p++) {
        unsigned long long acc[4] = {0ULL, 0ULL, 0ULL, 0ULL};
        #pragma unroll
        for (int j = 0; j < 64; j++) {
            unsigned long long y2 = packdup(yo[j]);
            ulonglong2 w0 = sM2[j*16 + p*2];
            ulonglong2 w1 = sM2[j*16 + p*2 + 1];
            ffma2(acc[0], y2, w0.x);
            ffma2(acc[1], y2, w0.y);
            ffma2(acc[2], y2, w1.x);
            ffma2(acc[3], y2, w1.y);
        }
        #pragma unroll
        for (int q = 0; q < 4; q++) {
            float2 v = unpack2(acc[q]);
            int c = p*8 + q*2;
            float pre, rr;
            pre = inv*v.x + cninv*sc1[c]   + sE[c];   rr = fmaxf(pre, 0.f); logit += rr*sW2[c];
            pre = inv*v.y + cninv*sc1[c+1] + sE[c+1]; rr = fmaxf(pre, 0.f); logit += rr*sW2[c+1];
        }
    }
    logit_out[row] = logit + b2[0];
}

// ---------------------------------------------------------------------------
__global__ void k_value(const float* __restrict__ extra,
                        const float* __restrict__ Wv1, const float* __restrict__ bv1,
                        float* __restrict__ val_out)
{
    __shared__ float sv[64];
    int tid = threadIdx.x;                  // 64 = (tb,kall)
    float acc = 0.f;
    #pragma unroll
    for (int j = 0; j < 64; j++) acc += g_s1[tid*64 + j] * g_wv[j];
    acc += g_s0[tid] * g_bv[0];
    acc *= (1.f / (float)N0c);
    #pragma unroll
    for (int d = 0; d < 4; d++) acc += extra[tid*4 + d] * Wv1[64 + d];
    acc += bv1[0];
    sv[tid] = acc;
    __syncthreads();
    if (tid < 16)
        val_out[tid] = sv[tid*4] + sv[tid*4+1] + sv[tid*4+2] + sv[tid*4+3];
}

// ---------------------------------------------------------------------------
extern "C" void kernel_launch(void* const* d_in, const int* in_sizes, int n_in,
                              void* d_out, int out_size)
{
    const float* h0       = (const float*)d_in[0];
    const float* h_global = (const float*)d_in[1];
    const float* x        = (const float*)d_in[2];
    const float* extra    = (const float*)d_in[3];
    const uint32_t* dones = (const uint32_t*)d_in[4];
    const int*   indices  = (const int*)d_in[5];
    const float* nnz      = (const float*)d_in[6];
    const float* Wi  = (const float*)d_in[7];
    const float* bi  = (const float*)d_in[8];
    const float* Wh  = (const float*)d_in[9];
    const float* bhn = (const float*)d_in[10];
    const float* Wq  = (const float*)d_in[11];
    const float* bq  = (const float*)d_in[12];
    const float* Wk  = (const float*)d_in[13];
    const float* bk  = (const float*)d_in[14];
    const float* Wv  = (const float*)d_in[15];
    const float* bv  = (const float*)d_in[16];
    const float* Wo  = (const float*)d_in[17];
    const float* bo  = (const float*)d_in[18];
    const float* W1  = (const float*)d_in[19];
    const float* b1  = (const float*)d_in[20];
    const float* W2  = (const float*)d_in[21];
    const float* b2  = (const float*)d_in[22];
    const float* Wv1 = (const float*)d_in[23];
    const float* bv1 = (const float*)d_in[24];

    float* out       = (float*)d_out;
    float* out_hfin  = out;
    float* out_hg    = out + OFF_HG;
    float* out_logit = out + OFF_LOGIT;
    float* out_val   = out + OFF_VAL;

    void *yo_ptr, *cnt_ptr, *s1_ptr, *s0_ptr;
    cudaGetSymbolAddress(&yo_ptr,  g_yo);
    cudaGetSymbolAddress(&cnt_ptr, g_cnt);
    cudaGetSymbolAddress(&s1_ptr,  g_s1);
    cudaGetSymbolAddress(&s0_ptr,  g_s0);
    cudaMemsetAsync(yo_ptr,  0, sizeof(float) * (size_t)TBNc * Hh, 0);
    cudaMemsetAsync(cnt_ptr, 0, sizeof(int) * Nn, 0);
    cudaMemsetAsync(s1_ptr,  0, sizeof(float) * 64 * 64, 0);
    cudaMemsetAsync(s0_ptr,  0, sizeof(float) * 64, 0);

    cudaMemcpyAsync(out_hg, h_global, 1024 * sizeof(float), cudaMemcpyDeviceToDevice, 0);

    int smem_gru  = GRU_SM_TOT * 4;                                // 222208 B
    cudaFuncSetAttribute(k_gru, cudaFuncAttributeMaxDynamicSharedMemorySize, smem_gru);
    int smem_qkv  = QKV_SH_TOT * 4;                                // 119552 B
    cudaFuncSetAttribute(k_qkv, cudaFuncAttributeMaxDynamicSharedMemorySize, smem_qkv);
    int smem_post = (256*17*4 + 4096 + 64 + 64 + 64) * 4;          // 87040 B
    cudaFuncSetAttribute(k_post, cudaFuncAttributeMaxDynamicSharedMemorySize, smem_post);

    k_count<<<(Ff * ORD + 255) / 256, 256>>>(indices);
    k_prep<<<32, 256>>>(Wo, bo, W1, b1, Wv1, extra);
    k_gru<<<BNc / 128, 512, smem_gru>>>(h0, x, dones, Wi, bi, Wh, bhn, out_hfin);
    k_qkv<<<148, 512, smem_qkv>>>(Wq, bq, Wk, bk, Wv, bv);
    k_attn<<<TBc * Ff / 8, 256>>>(indices);
    k_sum<<<256, 256>>>(nnz);
    k_post<<<TBNc / 256, 256, smem_post>>>(nnz, W2, b2, out_logit);
    k_value<<<1, 64>>>(extra, Wv1, bv1, out_val);
}

// round 10
// speedup vs baseline: 1.4773x; 1.0752x over previous
#include <cuda_runtime.h>
#include <math.h>
#include <stdint.h>

// Problem constants
#define Tt   4
#define Bb   4
#define Nn   16384
#define KALLc 4
#define Ff   16384
#define ORD  3
#define Hh   64
#define N0c  4096

#define TBc  (Tt*Bb)        // 16
#define BNc  (Bb*Nn)        // 65536
#define TBNc (TBc*Nn)       // 262144
#define H3c  (3*Hh)         // 192

// Output layout: h_fin [B,N,H] | h_global [B,K,64] | logit [T,B,N] | value [T,B]
#define OFF_HG    4194304
#define OFF_LOGIT (OFF_HG + 1024)
#define OFF_VAL   (OFF_LOGIT + 262144)

// Scratch
__device__ float g_qkv[TBNc * H3c];   // [T,B,N,192]
__device__ float g_yo [TBNc * Hh];    // [T,B,N,64]
__device__ int   g_cnt[Nn];
__device__ float g_M  [64*64];        // Wo @ W1[:64]
__device__ float g_c1 [64];           // bo @ W1[:64]
__device__ float g_E  [64*64];        // per (tb,kall): b1 + extra@W1[64:]
__device__ float g_wv [64];           // Wo @ Wv1[:64]
__device__ float g_bv [1];            // bo @ Wv1[:64]
__device__ float g_s1 [64*64];        // per (tb,kall): sum_n yo*invnnz
__device__ float g_s0 [64];           // per (tb,kall): sum_n cnt*invnnz

__device__ __forceinline__ float sigmoidf_(float v) { return 1.f / (1.f + expf(-v)); }

// ---- packed fp32 helpers (fma.rn.f32x2) ----
__device__ __forceinline__ unsigned long long packdup(float v) {
    unsigned long long r;
    asm("mov.b64 %0, {%1, %1};" : "=l"(r) : "f"(v));
    return r;
}
__device__ __forceinline__ unsigned long long pack2(float a, float b) {
    unsigned long long r;
    asm("mov.b64 %0, {%1, %2};" : "=l"(r) : "f"(a), "f"(b));
    return r;
}
__device__ __forceinline__ void ffma2(unsigned long long& acc,
                                      unsigned long long a, unsigned long long b) {
    asm("fma.rn.f32x2 %0, %1, %2, %0;" : "+l"(acc) : "l"(a), "l"(b));
}
__device__ __forceinline__ float2 unpack2(unsigned long long v) {
    float lo, hi;
    asm("mov.b64 {%0, %1}, %2;" : "=f"(lo), "=f"(hi) : "l"(v));
    return make_float2(lo, hi);
}

// ---------------------------------------------------------------------------
__global__ void k_count(const int* __restrict__ indices) {
    int i = blockIdx.x * 256 + threadIdx.x;
    if (i < Ff * ORD) atomicAdd(&g_cnt[indices[i]], 1);
}

// ---------------------------------------------------------------------------
__global__ void k_prep(const float* __restrict__ Wo, const float* __restrict__ bo,
                       const float* __restrict__ W1, const float* __restrict__ b1,
                       const float* __restrict__ Wv1,
                       const float* __restrict__ extra)
{
    int o = blockIdx.x * 256 + threadIdx.x;   // grid 32 x 256 = 8192
    if (o < 4096) {
        int j = o >> 6, c = o & 63;
        float s = 0.f;
        #pragma unroll
        for (int h = 0; h < 64; h++) s += Wo[j*64 + h] * W1[h*64 + c];
        g_M[o] = s;
    } else {
        int e = o - 4096;
        int g = e >> 6, c = e & 63;
        float s = b1[c];
        #pragma unroll
        for (int d = 0; d < 4; d++) s += extra[g*4 + d] * W1[(64 + d)*64 + c];
        g_E[e] = s;
    }
    if (blockIdx.x == 0 && threadIdx.x < 64) {
        int tid = threadIdx.x;
        float s = 0.f, w = 0.f;
        #pragma unroll
        for (int h = 0; h < 64; h++) {
            s += bo[h] * W1[h*64 + tid];
            w += Wo[tid*64 + h] * Wv1[h];
        }
        g_c1[tid] = s;
        g_wv[tid] = w;
        if (tid == 0) {
            float bvv = 0.f;
            #pragma unroll
            for (int h = 0; h < 64; h++) bvv += bo[h] * Wv1[h];
            g_bv[0] = bvv;
        }
    }
}

// ---------------------------------------------------------------------------
// Fused GRU scan + QKV projection, block-tiled GEMM form.
// Block = 128 rows, 512 threads, 4 timesteps in-block (h stays in sH).
// Gate weights column-REORDERED at staging to (r,z,n) triples (newcol=3c+g)
// so each thread's 6 GEMM cols = full gate triples of 2 hidden units ->
// pointwise is done in registers, no gate staging buffer.
// After each step's sH update, the qkv GEMM (same 8x6 tile) writes g_qkv.
// smem ~137KB: Wh 48K | Wi/bi/bhn | Wqkv 48K | bqkv | x 2K | sH 128x68 34K
// ---------------------------------------------------------------------------
#define GRU_HSTR     68
#define GRU_OFF_WI   12288
#define GRU_OFF_BI   (GRU_OFF_WI + 768)       // 13056
#define GRU_OFF_BHN  (GRU_OFF_BI + 192)       // 13248
#define GRU_OFF_WQ   (GRU_OFF_BHN + 64)       // 13312
#define GRU_OFF_BQ   (GRU_OFF_WQ + 12288)     // 25600
#define GRU_OFF_X    (GRU_OFF_BQ + 192)       // 25792
#define GRU_OFF_H    (GRU_OFF_X + 512)        // 26304
#define GRU_SM_TOT   (GRU_OFF_H + 128*GRU_HSTR) // 35008 floats = 140032 B

__global__ __launch_bounds__(512)
void k_gru_qkv(const float* __restrict__ h0, const float* __restrict__ x,
               const uint32_t* __restrict__ dones,
               const float* __restrict__ Wi, const float* __restrict__ bi,
               const float* __restrict__ Wh, const float* __restrict__ bhn,
               const float* __restrict__ Wq, const float* __restrict__ bq,
               const float* __restrict__ Wk, const float* __restrict__ bk,
               const float* __restrict__ Wv, const float* __restrict__ bv,
               float* __restrict__ hfin_out)
{
    extern __shared__ float gs[];
    float* sWh   = gs;                    // reordered: [k][3c+g]
    float* sWi   = gs + GRU_OFF_WI;       // reordered
    float* sbi   = gs + GRU_OFF_BI;       // reordered
    float* sbhn  = gs + GRU_OFF_BHN;      // natural unit order
    float* sWq   = gs + GRU_OFF_WQ;       // [k][q|k|v 192]
    float* sbq   = gs + GRU_OFF_BQ;
    float* sX    = gs + GRU_OFF_X;
    float* sH    = gs + GRU_OFF_H;

    int tid = threadIdx.x;
    size_t rowbase = (size_t)blockIdx.x * 128;
    int b = (int)(rowbase >> 14);

    // Stage weights (gate columns reordered), qkv weights, biases, h0
    for (int i = tid; i < 12288; i += 512) {
        int k = i / 192, e = i % 192;
        int c = e / 3, g = e % 3;
        sWh[i] = Wh[k*192 + g*64 + c];
    }
    for (int i = tid; i < 768; i += 512) {
        int k = i / 192, e = i % 192;
        int c = e / 3, g = e % 3;
        sWi[i] = Wi[k*192 + g*64 + c];
    }
    if (tid < 192) {
        int c = tid / 3, g = tid % 3;
        sbi[tid] = bi[g*64 + c];
    }
    if (tid < 64) sbhn[tid] = bhn[tid];
    for (int i = tid; i < 12288; i += 512) {
        int k = i / 192, e = i % 192;
        sWq[i] = (e < 64) ? Wq[k*64 + e] : (e < 128) ? Wk[k*64 + e - 64] : Wv[k*64 + e - 128];
    }
    if (tid < 192)
        sbq[tid] = (tid < 64) ? bq[tid] : (tid < 128) ? bk[tid - 64] : bv[tid - 128];
    for (int i = tid; i < 8192; i += 512) {
        int r = i >> 6, c = i & 63;
        sH[r*GRU_HSTR + c] = h0[rowbase*64 + i];
    }

    int rg = tid >> 5;          // 0..15: rows rg + 16*i
    int cg = tid & 31;          // 0..31
    int c0 = cg * 6;            // gate cols (reordered) / qkv cols
    int u0 = cg * 2;            // hidden units owned (pointwise)

    #pragma unroll 1
    for (int t = 0; t < Tt; t++) {
        __syncthreads();        // sH stable (staging or prev qkv reads done)

        sX[tid] = x[((size_t)t * BNc + rowbase) * 4 + tid];
        if (dones[t * Bb + b] != 0u) {
            for (int i = tid; i < 8192; i += 512) {
                int r = i >> 6, c = i & 63;
                sH[r*GRU_HSTR + c] = 0.f;
            }
        }
        __syncthreads();

        // ---- gates GEMM (reordered cols): acc[i] = sH[row] @ Wh[:, c0..c0+5]
        unsigned long long acc[8][3];
        #pragma unroll
        for (int i = 0; i < 8; i++) { acc[i][0] = 0ULL; acc[i][1] = 0ULL; acc[i][2] = 0ULL; }

        const float* sWrow = sWh + c0;
        #pragma unroll 1
        for (int k4 = 0; k4 < 16; k4++) {
            unsigned long long w[4][3];
            #pragma unroll
            for (int kk = 0; kk < 4; kk++) {
                const float* wr = sWrow + (k4*4 + kk) * 192;
                w[kk][0] = *(const unsigned long long*)(wr);
                w[kk][1] = *(const unsigned long long*)(wr + 2);
                w[kk][2] = *(const unsigned long long*)(wr + 4);
            }
            #pragma unroll
            for (int i = 0; i < 8; i++) {
                float4 hv = *(const float4*)&sH[(rg + 16*i) * GRU_HSTR + k4*4];
                unsigned long long hh0 = packdup(hv.x);
                ffma2(acc[i][0], hh0, w[0][0]); ffma2(acc[i][1], hh0, w[0][1]); ffma2(acc[i][2], hh0, w[0][2]);
                unsigned long long hh1 = packdup(hv.y);
                ffma2(acc[i][0], hh1, w[1][0]); ffma2(acc[i][1], hh1, w[1][1]); ffma2(acc[i][2], hh1, w[1][2]);
                unsigned long long hh2 = packdup(hv.z);
                ffma2(acc[i][0], hh2, w[2][0]); ffma2(acc[i][1], hh2, w[2][1]); ffma2(acc[i][2], hh2, w[2][2]);
                unsigned long long hh3 = packdup(hv.w);
                ffma2(acc[i][0], hh3, w[3][0]); ffma2(acc[i][1], hh3, w[3][1]); ffma2(acc[i][2], hh3, w[3][2]);
            }
        }
        __syncthreads();        // all GEMM reads of sH done before writes

        // ---- pointwise in registers; write h_new (2 units) to sH ----
        float2 bh2 = *(const float2*)&sbhn[u0];
        #pragma unroll
        for (int i = 0; i < 8; i++) {
            int row = rg + 16*i;
            // gi for this row's 6 reordered cols
            unsigned long long g0 = *(const unsigned long long*)(sbi + c0);
            unsigned long long g1 = *(const unsigned long long*)(sbi + c0 + 2);
            unsigned long long g2 = *(const unsigned long long*)(sbi + c0 + 4);
            #pragma unroll
            for (int d = 0; d < 4; d++) {
                unsigned long long xv = packdup(sX[row*4 + d]);
                const float* wr = sWi + d*192 + c0;
                ffma2(g0, xv, *(const unsigned long long*)(wr));
                ffma2(g1, xv, *(const unsigned long long*)(wr + 2));
                ffma2(g2, xv, *(const unsigned long long*)(wr + 4));
            }
            float2 a0 = unpack2(acc[i][0]);   // gh_r0, gh_z0
            float2 a1 = unpack2(acc[i][1]);   // gh_n0, gh_r1
            float2 a2 = unpack2(acc[i][2]);   // gh_z1, gh_n1
            float2 i0 = unpack2(g0);          // gi_r0, gi_z0
            float2 i1 = unpack2(g1);          // gi_n0, gi_r1
            float2 i2 = unpack2(g2);          // gi_z1, gi_n1

            float2 hold = *(const float2*)&sH[row*GRU_HSTR + u0];
            float r0 = sigmoidf_(i0.x + a0.x);
            float z0 = sigmoidf_(i0.y + a0.y);
            float n0 = tanhf(i1.x + r0 * (a1.x + bh2.x));
            float h0n = (1.f - z0) * n0 + z0 * hold.x;
            float r1 = sigmoidf_(i1.y + a1.y);
            float z1 = sigmoidf_(i2.x + a2.x);
            float n1 = tanhf(i2.y + r1 * (a2.y + bh2.y));
            float h1n = (1.f - z1) * n1 + z1 * hold.y;
            *(float2*)&sH[row*GRU_HSTR + u0] = make_float2(h0n, h1n);
        }
        __syncthreads();        // h_new visible

        // ---- qkv GEMM: out[row][c0..c0+5] = sH[row] @ Wqkv + b ----
        {
            unsigned long long qa[8][3];
            float2 b01 = *(const float2*)&sbq[c0];
            float2 b23 = *(const float2*)&sbq[c0 + 2];
            float2 b45 = *(const float2*)&sbq[c0 + 4];
            #pragma unroll
            for (int i = 0; i < 8; i++) {
                qa[i][0] = pack2(b01.x, b01.y);
                qa[i][1] = pack2(b23.x, b23.y);
                qa[i][2] = pack2(b45.x, b45.y);
            }
            const float* sQrow = sWq + c0;
            #pragma unroll 1
            for (int k4 = 0; k4 < 16; k4++) {
                unsigned long long w[4][3];
                #pragma unroll
                for (int kk = 0; kk < 4; kk++) {
                    const float* wr = sQrow + (k4*4 + kk) * 192;
                    w[kk][0] = *(const unsigned long long*)(wr);
                    w[kk][1] = *(const unsigned long long*)(wr + 2);
                    w[kk][2] = *(const unsigned long long*)(wr + 4);
                }
                #pragma unroll
                for (int i = 0; i < 8; i++) {
                    float4 hv = *(const float4*)&sH[(rg + 16*i) * GRU_HSTR + k4*4];
                    unsigned long long hh0 = packdup(hv.x);
                    ffma2(qa[i][0], hh0, w[0][0]); ffma2(qa[i][1], hh0, w[0][1]); ffma2(qa[i][2], hh0, w[0][2]);
                    unsigned long long hh1 = packdup(hv.y);
                    ffma2(qa[i][0], hh1, w[1][0]); ffma2(qa[i][1], hh1, w[1][1]); ffma2(qa[i][2], hh1, w[1][2]);
                    unsigned long long hh2 = packdup(hv.z);
                    ffma2(qa[i][0], hh2, w[2][0]); ffma2(qa[i][1], hh2, w[2][1]); ffma2(qa[i][2], hh2, w[2][2]);
                    unsigned long long hh3 = packdup(hv.w);
                    ffma2(qa[i][0], hh3, w[3][0]); ffma2(qa[i][1], hh3, w[3][1]); ffma2(qa[i][2], hh3, w[3][2]);
                }
            }
            size_t orow0 = (size_t)t * BNc + rowbase;
            #pragma unroll
            for (int i = 0; i < 8; i++) {
                unsigned long long* dst =
                    (unsigned long long*)(g_qkv + (orow0 + rg + 16*i) * H3c + c0);
                dst[0] = qa[i][0];
                dst[1] = qa[i][1];
                dst[2] = qa[i][2];
            }
        }
    }

    __syncthreads();
    for (int i = tid; i < 8192; i += 512) {
        int r = i >> 6, c = i & 63;
        hfin_out[rowbase*64 + i] = sH[r*GRU_HSTR + c];
    }
}

// ---------------------------------------------------------------------------
// Attention per (t,b,f) (unchanged).
// ---------------------------------------------------------------------------
__global__ __launch_bounds__(256)
void k_attn(const int* __restrict__ indices)
{
    __shared__ __align__(16) float sR[8][3][192];
    __shared__ __align__(16) float sO[8][3][64];

    int warp = threadIdx.x >> 5, lane = threadIdx.x & 31;
    int inst = blockIdx.x * 8 + warp;
    int tb = inst >> 14;
    int f  = inst & 16383;

    int idx[3] = {__ldg(&indices[f*3]), __ldg(&indices[f*3+1]), __ldg(&indices[f*3+2])};

    const float* base = g_qkv + (size_t)tb * Nn * H3c;
    #pragma unroll
    for (int k = 0; k < 3; k++) {
        const float* row = base + (size_t)idx[k] * H3c;
        #pragma unroll
        for (int u = 0; u < 6; u++) sR[warp][k][u*32 + lane] = row[u*32 + lane];
    }
    __syncwarp();

    if (lane < 12) {
        int qr = lane >> 2, hh = lane & 3;
        const float* q = &sR[warp][qr][hh * 16];
        float l[3];
        #pragma unroll
        for (int kr = 0; kr < 3; kr++) {
            const float* kv = &sR[warp][kr][64 + hh * 16];
            float s = 0.f;
            #pragma unroll
            for (int d = 0; d < 16; d++) s += q[d] * kv[d];
            l[kr] = s * 0.25f;
        }
        float m = fmaxf(l[0], fmaxf(l[1], l[2]));
        float e0 = expf(l[0] - m), e1 = expf(l[1] - m), e2 = expf(l[2] - m);
        float inv = 1.f / (e0 + e1 + e2);
        e0 *= inv; e1 *= inv; e2 *= inv;
        const float* v0 = &sR[warp][0][128 + hh * 16];
        const float* v1 = &sR[warp][1][128 + hh * 16];
        const float* v2 = &sR[warp][2][128 + hh * 16];
        #pragma unroll
        for (int d = 0; d < 16; d++)
            sO[warp][qr][hh*16 + d] = e0 * v0[d] + e1 * v1[d] + e2 * v2[d];
    }
    __syncwarp();

    float4* yo = (float4*)g_yo + (size_t)tb * Nn * 16;
    if (lane < 16) {
        #pragma unroll
        for (int k = 0; k < 3; k++) {
            float4 v = ((const float4*)sO[warp][k])[lane];
            atomicAdd(&yo[(size_t)idx[k] * 16 + lane], v);
        }
    }
}

// ---------------------------------------------------------------------------
__global__ __launch_bounds__(256)
void k_sum(const float* __restrict__ nnz)
{
    __shared__ float red[4][64];
    __shared__ float red0[4];
    int blk = blockIdx.x;        // 0..255
    int g = blk >> 2, chunk = blk & 3;
    int tid = threadIdx.x;
    int r4 = tid >> 6;
    int col = tid & 63;

    float acc = 0.f, acc0 = 0.f;
    int nbase = (g & 3) * 4096;
    const float* yob = g_yo + (size_t)g * 4096 * 64;
    int rend = (chunk + 1) * 1024;
    for (int rr = chunk * 1024 + r4; rr < rend; rr += 4) {
        int n = nbase + rr;
        float inv = 1.f / nnz[n];
        acc += yob[(size_t)rr * 64 + col] * inv;
        if (col == 0) acc0 += (float)g_cnt[n] * inv;
    }
    red[r4][col] = acc;
    if (col == 0) red0[r4] = acc0;
    __syncthreads();
    if (tid < 64)
        atomicAdd(&g_s1[g * 64 + tid], red[0][tid] + red[1][tid] + red[2][tid] + red[3][tid]);
    if (tid == 0)
        atomicAdd(&g_s0[g], red0[0] + red0[1] + red0[2] + red0[3]);
}

// ---------------------------------------------------------------------------
// Logit head (unchanged).
// ---------------------------------------------------------------------------
__global__ __launch_bounds__(256, 2)
void k_post(const float* __restrict__ nnz,
            const float* __restrict__ W2, const float* __restrict__ b2,
            float* __restrict__ logit_out)
{
    extern __shared__ float ps[];
    float4* sT4 = (float4*)ps;                 // 256 rows x 17 float4 (pad)
    float*  sM  = ps + 256*17*4;               // 4096
    float*  sc1 = sM + 4096;                   // 64
    float*  sE  = sc1 + 64;                    // 64
    float*  sW2 = sE + 64;                     // 64

    int tid = threadIdx.x;
    int rowbase = blockIdx.x * 256;
    int g = rowbase >> 12;

    const float4* yo4 = (const float4*)g_yo + (size_t)rowbase * 16;
    for (int i = tid; i < 4096; i += 256)
        sT4[(i >> 4) * 17 + (i & 15)] = yo4[i];
    for (int i = tid; i < 4096; i += 256) sM[i] = g_M[i];
    if (tid < 64) { sc1[tid] = g_c1[tid]; sE[tid] = g_E[g*64 + tid]; sW2[tid] = W2[tid]; }
    __syncthreads();

    int row = rowbase + tid;
    int n = row & 16383;
    float inv = 1.f / nnz[n];
    float cninv = (float)g_cnt[n] * inv;

    float yo[64];
    #pragma unroll
    for (int jj = 0; jj < 16; jj++) {
        float4 v = sT4[tid * 17 + jj];
        yo[4*jj] = v.x; yo[4*jj+1] = v.y; yo[4*jj+2] = v.z; yo[4*jj+3] = v.w;
    }

    const ulonglong2* sM2 = (const ulonglong2*)sM;
    float logit = 0.f;
    #pragma unroll 1
    for (int p = 0; p < 8; p++) {
        unsigned long long acc[4] = {0ULL, 0ULL, 0ULL, 0ULL};
        #pragma unroll
        for (int j = 0; j < 64; j++) {
            unsigned long long y2 = packdup(yo[j]);
            ulonglong2 w0 = sM2[j*16 + p*2];
            ulonglong2 w1 = sM2[j*16 + p*2 + 1];
            ffma2(acc[0], y2, w0.x);
            ffma2(acc[1], y2, w0.y);
            ffma2(acc[2], y2, w1.x);
            ffma2(acc[3], y2, w1.y);
        }
        #pragma unroll
        for (int q = 0; q < 4; q++) {
            float2 v = unpack2(acc[q]);
            int c = p*8 + q*2;
            float pre, rr;
            pre = inv*v.x + cninv*sc1[c]   + sE[c];   rr = fmaxf(pre, 0.f); logit += rr*sW2[c];
            pre = inv*v.y + cninv*sc1[c+1] + sE[c+1]; rr = fmaxf(pre, 0.f); logit += rr*sW2[c+1];
        }
    }
    logit_out[row] = logit + b2[0];
}

// ---------------------------------------------------------------------------
__global__ void k_value(const float* __restrict__ extra,
                        const float* __restrict__ Wv1, const float* __restrict__ bv1,
                        float* __restrict__ val_out)
{
    __shared__ float sv[64];
    int tid = threadIdx.x;                  // 64 = (tb,kall)
    float acc = 0.f;
    #pragma unroll
    for (int j = 0; j < 64; j++) acc += g_s1[tid*64 + j] * g_wv[j];
    acc += g_s0[tid] * g_bv[0];
    acc *= (1.f / (float)N0c);
    #pragma unroll
    for (int d = 0; d < 4; d++) acc += extra[tid*4 + d] * Wv1[64 + d];
    acc += bv1[0];
    sv[tid] = acc;
    __syncthreads();
    if (tid < 16)
        val_out[tid] = sv[tid*4] + sv[tid*4+1] + sv[tid*4+2] + sv[tid*4+3];
}

// ---------------------------------------------------------------------------
extern "C" void kernel_launch(void* const* d_in, const int* in_sizes, int n_in,
                              void* d_out, int out_size)
{
    const float* h0       = (const float*)d_in[0];
    const float* h_global = (const float*)d_in[1];
    const float* x        = (const float*)d_in[2];
    const float* extra    = (const float*)d_in[3];
    const uint32_t* dones = (const uint32_t*)d_in[4];
    const int*   indices  = (const int*)d_in[5];
    const float* nnz      = (const float*)d_in[6];
    const float* Wi  = (const float*)d_in[7];
    const float* bi  = (const float*)d_in[8];
    const float* Wh  = (const float*)d_in[9];
    const float* bhn = (const float*)d_in[10];
    const float* Wq  = (const float*)d_in[11];
    const float* bq  = (const float*)d_in[12];
    const float* Wk  = (const float*)d_in[13];
    const float* bk  = (const float*)d_in[14];
    const float* Wv  = (const float*)d_in[15];
    const float* bv  = (const float*)d_in[16];
    const float* Wo  = (const float*)d_in[17];
    const float* bo  = (const float*)d_in[18];
    const float* W1  = (const float*)d_in[19];
    const float* b1  = (const float*)d_in[20];
    const float* W2  = (const float*)d_in[21];
    const float* b2  = (const float*)d_in[22];
    const float* Wv1 = (const float*)d_in[23];
    const float* bv1 = (const float*)d_in[24];

    float* out       = (float*)d_out;
    float* out_hfin  = out;
    float* out_hg    = out + OFF_HG;
    float* out_logit = out + OFF_LOGIT;
    float* out_val   = out + OFF_VAL;

    void *yo_ptr, *cnt_ptr, *s1_ptr, *s0_ptr;
    cudaGetSymbolAddress(&yo_ptr,  g_yo);
    cudaGetSymbolAddress(&cnt_ptr, g_cnt);
    cudaGetSymbolAddress(&s1_ptr,  g_s1);
    cudaGetSymbolAddress(&s0_ptr,  g_s0);
    cudaMemsetAsync(yo_ptr,  0, sizeof(float) * (size_t)TBNc * Hh, 0);
    cudaMemsetAsync(cnt_ptr, 0, sizeof(int) * Nn, 0);
    cudaMemsetAsync(s1_ptr,  0, sizeof(float) * 64 * 64, 0);
    cudaMemsetAsync(s0_ptr,  0, sizeof(float) * 64, 0);

    cudaMemcpyAsync(out_hg, h_global, 1024 * sizeof(float), cudaMemcpyDeviceToDevice, 0);

    int smem_gru  = GRU_SM_TOT * 4;                                // 140032 B
    cudaFuncSetAttribute(k_gru_qkv, cudaFuncAttributeMaxDynamicSharedMemorySize, smem_gru);
    int smem_post = (256*17*4 + 4096 + 64 + 64 + 64) * 4;          // 87040 B
    cudaFuncSetAttribute(k_post, cudaFuncAttributeMaxDynamicSharedMemorySize, smem_post);

    k_count<<<(Ff * ORD + 255) / 256, 256>>>(indices);
    k_prep<<<32, 256>>>(Wo, bo, W1, b1, Wv1, extra);
    k_gru_qkv<<<BNc / 128, 512, smem_gru>>>(h0, x, dones, Wi, bi, Wh, bhn,
                                            Wq, bq, Wk, bk, Wv, bv, out_hfin);
    k_attn<<<TBc * Ff / 8, 256>>>(indices);
    k_sum<<<256, 256>>>(nnz);
    k_post<<<TBNc / 256, 256, smem_post>>>(nnz, W2, b2, out_logit);
    k_value<<<1, 64>>>(extra, Wv1, bv1, out_val);
}

// round 11
// speedup vs baseline: 1.5295x; 1.0353x over previous
#include <cuda_runtime.h>
#include <math.h>
#include <stdint.h>

// Problem constants
#define Tt   4
#define Bb   4
#define Nn   16384
#define KALLc 4
#define Ff   16384
#define ORD  3
#define Hh   64
#define N0c  4096

#define TBc  (Tt*Bb)        // 16
#define BNc  (Bb*Nn)        // 65536
#define TBNc (TBc*Nn)       // 262144
#define H3c  (3*Hh)         // 192

// Output layout: h_fin [B,N,H] | h_global [B,K,64] | logit [T,B,N] | value [T,B]
#define OFF_HG    4194304
#define OFF_LOGIT (OFF_HG + 1024)
#define OFF_VAL   (OFF_LOGIT + 262144)

// Scratch
__device__ float g_qkv[TBNc * H3c];   // [T,B,N,192]
__device__ float g_yo [TBNc * Hh];    // [T,B,N,64]
__device__ int   g_cnt[Nn];
__device__ float g_M  [64*64];        // Wo @ W1[:64]
__device__ float g_c1 [64];           // bo @ W1[:64]
__device__ float g_E  [64*64];        // per (tb,kall): b1 + extra@W1[64:]
__device__ float g_wv [64];           // Wo @ Wv1[:64]
__device__ float g_bv [1];            // bo @ Wv1[:64]
__device__ float g_s1 [64*64];        // per (tb,kall): sum_n yo*invnnz
__device__ float g_s0 [64];           // per (tb,kall): sum_n cnt*invnnz

__device__ __forceinline__ float sigmoidf_(float v) { return 1.f / (1.f + expf(-v)); }

// ---- packed fp32 helpers (fma.rn.f32x2) ----
__device__ __forceinline__ unsigned long long packdup(float v) {
    unsigned long long r;
    asm("mov.b64 %0, {%1, %1};" : "=l"(r) : "f"(v));
    return r;
}
__device__ __forceinline__ unsigned long long pack2(float a, float b) {
    unsigned long long r;
    asm("mov.b64 %0, {%1, %2};" : "=l"(r) : "f"(a), "f"(b));
    return r;
}
__device__ __forceinline__ void ffma2(unsigned long long& acc,
                                      unsigned long long a, unsigned long long b) {
    asm("fma.rn.f32x2 %0, %1, %2, %0;" : "+l"(acc) : "l"(a), "l"(b));
}
__device__ __forceinline__ float2 unpack2(unsigned long long v) {
    float lo, hi;
    asm("mov.b64 {%0, %1}, %2;" : "=f"(lo), "=f"(hi) : "l"(v));
    return make_float2(lo, hi);
}

// ---------------------------------------------------------------------------
__global__ void k_count(const int* __restrict__ indices) {
    int i = blockIdx.x * 256 + threadIdx.x;
    if (i < Ff * ORD) atomicAdd(&g_cnt[indices[i]], 1);
}

// ---------------------------------------------------------------------------
__global__ void k_prep(const float* __restrict__ Wo, const float* __restrict__ bo,
                       const float* __restrict__ W1, const float* __restrict__ b1,
                       const float* __restrict__ Wv1,
                       const float* __restrict__ extra)
{
    int o = blockIdx.x * 256 + threadIdx.x;   // grid 32 x 256 = 8192
    if (o < 4096) {
        int j = o >> 6, c = o & 63;
        float s = 0.f;
        #pragma unroll
        for (int h = 0; h < 64; h++) s += Wo[j*64 + h] * W1[h*64 + c];
        g_M[o] = s;
    } else {
        int e = o - 4096;
        int g = e >> 6, c = e & 63;
        float s = b1[c];
        #pragma unroll
        for (int d = 0; d < 4; d++) s += extra[g*4 + d] * W1[(64 + d)*64 + c];
        g_E[e] = s;
    }
    if (blockIdx.x == 0 && threadIdx.x < 64) {
        int tid = threadIdx.x;
        float s = 0.f, w = 0.f;
        #pragma unroll
        for (int h = 0; h < 64; h++) {
            s += bo[h] * W1[h*64 + tid];
            w += Wo[tid*64 + h] * Wv1[h];
        }
        g_c1[tid] = s;
        g_wv[tid] = w;
        if (tid == 0) {
            float bvv = 0.f;
            #pragma unroll
            for (int h = 0; h < 64; h++) bvv += bo[h] * Wv1[h];
            g_bv[0] = bvv;
        }
    }
}

// ---------------------------------------------------------------------------
// Fused GRU scan + QKV projection (unchanged from R10, passing).
// ---------------------------------------------------------------------------
#define GRU_HSTR     68
#define GRU_OFF_WI   12288
#define GRU_OFF_BI   (GRU_OFF_WI + 768)       // 13056
#define GRU_OFF_BHN  (GRU_OFF_BI + 192)       // 13248
#define GRU_OFF_WQ   (GRU_OFF_BHN + 64)       // 13312
#define GRU_OFF_BQ   (GRU_OFF_WQ + 12288)     // 25600
#define GRU_OFF_X    (GRU_OFF_BQ + 192)       // 25792
#define GRU_OFF_H    (GRU_OFF_X + 512)        // 26304
#define GRU_SM_TOT   (GRU_OFF_H + 128*GRU_HSTR) // 35008 floats = 140032 B

__global__ __launch_bounds__(512)
void k_gru_qkv(const float* __restrict__ h0, const float* __restrict__ x,
               const uint32_t* __restrict__ dones,
               const float* __restrict__ Wi, const float* __restrict__ bi,
               const float* __restrict__ Wh, const float* __restrict__ bhn,
               const float* __restrict__ Wq, const float* __restrict__ bq,
               const float* __restrict__ Wk, const float* __restrict__ bk,
               const float* __restrict__ Wv, const float* __restrict__ bv,
               float* __restrict__ hfin_out)
{
    extern __shared__ float gs[];
    float* sWh   = gs;                    // reordered: [k][3c+g]
    float* sWi   = gs + GRU_OFF_WI;       // reordered
    float* sbi   = gs + GRU_OFF_BI;       // reordered
    float* sbhn  = gs + GRU_OFF_BHN;      // natural unit order
    float* sWq   = gs + GRU_OFF_WQ;       // [k][q|k|v 192]
    float* sbq   = gs + GRU_OFF_BQ;
    float* sX    = gs + GRU_OFF_X;
    float* sH    = gs + GRU_OFF_H;

    int tid = threadIdx.x;
    size_t rowbase = (size_t)blockIdx.x * 128;
    int b = (int)(rowbase >> 14);

    for (int i = tid; i < 12288; i += 512) {
        int k = i / 192, e = i % 192;
        int c = e / 3, g = e % 3;
        sWh[i] = Wh[k*192 + g*64 + c];
    }
    for (int i = tid; i < 768; i += 512) {
        int k = i / 192, e = i % 192;
        int c = e / 3, g = e % 3;
        sWi[i] = Wi[k*192 + g*64 + c];
    }
    if (tid < 192) {
        int c = tid / 3, g = tid % 3;
        sbi[tid] = bi[g*64 + c];
    }
    if (tid < 64) sbhn[tid] = bhn[tid];
    for (int i = tid; i < 12288; i += 512) {
        int k = i / 192, e = i % 192;
        sWq[i] = (e < 64) ? Wq[k*64 + e] : (e < 128) ? Wk[k*64 + e - 64] : Wv[k*64 + e - 128];
    }
    if (tid < 192)
        sbq[tid] = (tid < 64) ? bq[tid] : (tid < 128) ? bk[tid - 64] : bv[tid - 128];
    for (int i = tid; i < 8192; i += 512) {
        int r = i >> 6, c = i & 63;
        sH[r*GRU_HSTR + c] = h0[rowbase*64 + i];
    }

    int rg = tid >> 5;
    int cg = tid & 31;
    int c0 = cg * 6;
    int u0 = cg * 2;

    #pragma unroll 1
    for (int t = 0; t < Tt; t++) {
        __syncthreads();

        sX[tid] = x[((size_t)t * BNc + rowbase) * 4 + tid];
        if (dones[t * Bb + b] != 0u) {
            for (int i = tid; i < 8192; i += 512) {
                int r = i >> 6, c = i & 63;
                sH[r*GRU_HSTR + c] = 0.f;
            }
        }
        __syncthreads();

        unsigned long long acc[8][3];
        #pragma unroll
        for (int i = 0; i < 8; i++) { acc[i][0] = 0ULL; acc[i][1] = 0ULL; acc[i][2] = 0ULL; }

        const float* sWrow = sWh + c0;
        #pragma unroll 1
        for (int k4 = 0; k4 < 16; k4++) {
            unsigned long long w[4][3];
            #pragma unroll
            for (int kk = 0; kk < 4; kk++) {
                const float* wr = sWrow + (k4*4 + kk) * 192;
                w[kk][0] = *(const unsigned long long*)(wr);
                w[kk][1] = *(const unsigned long long*)(wr + 2);
                w[kk][2] = *(const unsigned long long*)(wr + 4);
            }
            #pragma unroll
            for (int i = 0; i < 8; i++) {
                float4 hv = *(const float4*)&sH[(rg + 16*i) * GRU_HSTR + k4*4];
                unsigned long long hh0 = packdup(hv.x);
                ffma2(acc[i][0], hh0, w[0][0]); ffma2(acc[i][1], hh0, w[0][1]); ffma2(acc[i][2], hh0, w[0][2]);
                unsigned long long hh1 = packdup(hv.y);
                ffma2(acc[i][0], hh1, w[1][0]); ffma2(acc[i][1], hh1, w[1][1]); ffma2(acc[i][2], hh1, w[1][2]);
                unsigned long long hh2 = packdup(hv.z);
                ffma2(acc[i][0], hh2, w[2][0]); ffma2(acc[i][1], hh2, w[2][1]); ffma2(acc[i][2], hh2, w[2][2]);
                unsigned long long hh3 = packdup(hv.w);
                ffma2(acc[i][0], hh3, w[3][0]); ffma2(acc[i][1], hh3, w[3][1]); ffma2(acc[i][2], hh3, w[3][2]);
            }
        }
        __syncthreads();

        float2 bh2 = *(const float2*)&sbhn[u0];
        #pragma unroll
        for (int i = 0; i < 8; i++) {
            int row = rg + 16*i;
            unsigned long long g0 = *(const unsigned long long*)(sbi + c0);
            unsigned long long g1 = *(const unsigned long long*)(sbi + c0 + 2);
            unsigned long long g2 = *(const unsigned long long*)(sbi + c0 + 4);
            #pragma unroll
            for (int d = 0; d < 4; d++) {
                unsigned long long xv = packdup(sX[row*4 + d]);
                const float* wr = sWi + d*192 + c0;
                ffma2(g0, xv, *(const unsigned long long*)(wr));
                ffma2(g1, xv, *(const unsigned long long*)(wr + 2));
                ffma2(g2, xv, *(const unsigned long long*)(wr + 4));
            }
            float2 a0 = unpack2(acc[i][0]);
            float2 a1 = unpack2(acc[i][1]);
            float2 a2 = unpack2(acc[i][2]);
            float2 i0 = unpack2(g0);
            float2 i1 = unpack2(g1);
            float2 i2 = unpack2(g2);

            float2 hold = *(const float2*)&sH[row*GRU_HSTR + u0];
            float r0 = sigmoidf_(i0.x + a0.x);
            float z0 = sigmoidf_(i0.y + a0.y);
            float n0 = tanhf(i1.x + r0 * (a1.x + bh2.x));
            float h0n = (1.f - z0) * n0 + z0 * hold.x;
            float r1 = sigmoidf_(i1.y + a1.y);
            float z1 = sigmoidf_(i2.x + a2.x);
            float n1 = tanhf(i2.y + r1 * (a2.y + bh2.y));
            float h1n = (1.f - z1) * n1 + z1 * hold.y;
            *(float2*)&sH[row*GRU_HSTR + u0] = make_float2(h0n, h1n);
        }
        __syncthreads();

        {
            unsigned long long qa[8][3];
            float2 b01 = *(const float2*)&sbq[c0];
            float2 b23 = *(const float2*)&sbq[c0 + 2];
            float2 b45 = *(const float2*)&sbq[c0 + 4];
            #pragma unroll
            for (int i = 0; i < 8; i++) {
                qa[i][0] = pack2(b01.x, b01.y);
                qa[i][1] = pack2(b23.x, b23.y);
                qa[i][2] = pack2(b45.x, b45.y);
            }
            const float* sQrow = sWq + c0;
            #pragma unroll 1
            for (int k4 = 0; k4 < 16; k4++) {
                unsigned long long w[4][3];
                #pragma unroll
                for (int kk = 0; kk < 4; kk++) {
                    const float* wr = sQrow + (k4*4 + kk) * 192;
                    w[kk][0] = *(const unsigned long long*)(wr);
                    w[kk][1] = *(const unsigned long long*)(wr + 2);
                    w[kk][2] = *(const unsigned long long*)(wr + 4);
                }
                #pragma unroll
                for (int i = 0; i < 8; i++) {
                    float4 hv = *(const float4*)&sH[(rg + 16*i) * GRU_HSTR + k4*4];
                    unsigned long long hh0 = packdup(hv.x);
                    ffma2(qa[i][0], hh0, w[0][0]); ffma2(qa[i][1], hh0, w[0][1]); ffma2(qa[i][2], hh0, w[0][2]);
                    unsigned long long hh1 = packdup(hv.y);
                    ffma2(qa[i][0], hh1, w[1][0]); ffma2(qa[i][1], hh1, w[1][1]); ffma2(qa[i][2], hh1, w[1][2]);
                    unsigned long long hh2 = packdup(hv.z);
                    ffma2(qa[i][0], hh2, w[2][0]); ffma2(qa[i][1], hh2, w[2][1]); ffma2(qa[i][2], hh2, w[2][2]);
                    unsigned long long hh3 = packdup(hv.w);
                    ffma2(qa[i][0], hh3, w[3][0]); ffma2(qa[i][1], hh3, w[3][1]); ffma2(qa[i][2], hh3, w[3][2]);
                }
            }
            size_t orow0 = (size_t)t * BNc + rowbase;
            #pragma unroll
            for (int i = 0; i < 8; i++) {
                unsigned long long* dst =
                    (unsigned long long*)(g_qkv + (orow0 + rg + 16*i) * H3c + c0);
                dst[0] = qa[i][0];
                dst[1] = qa[i][1];
                dst[2] = qa[i][2];
            }
        }
    }

    __syncthreads();
    for (int i = tid; i < 8192; i += 512) {
        int r = i >> 6, c = i & 63;
        hfin_out[rowbase*64 + i] = sH[r*GRU_HSTR + c];
    }
}

// ---------------------------------------------------------------------------
// Attention: 2 instances per warp. Gather float2, padded sR/sO strides
// (196 / 68 floats) for low-conflict LDS, 24-lane compute, 32-lane scatter.
// ---------------------------------------------------------------------------
#define ATT_RSTR 196
#define ATT_OSTR 68
__global__ __launch_bounds__(256)
void k_attn(const int* __restrict__ indices)
{
    __shared__ __align__(16) float sR[8][2][3*ATT_RSTR];
    __shared__ __align__(16) float sO[8][2][3*ATT_OSTR];
    __shared__ int sIdx[8][2][3];

    int warp = threadIdx.x >> 5, lane = threadIdx.x & 31;
    int ip = blockIdx.x * 16 + warp * 2;      // instance pair base
    int tb0 = ip >> 14;                       // pair never crosses tb boundary
    int f0  = ip & 16383;

    if (lane < 6) {
        int i = lane >> 1, k3 = lane - 2*i;   // careful: need (i,k) covering 2x3
    }
    // 6 index loads: lane 0..5 -> i = lane/3, k = lane%3
    if (lane < 6) {
        int i = lane / 3, k = lane % 3;
        sIdx[warp][i][k] = __ldg(&indices[(f0 + i)*3 + k]);
    }
    __syncwarp();

    // Gather 6 rows (2 inst x 3 slots), float2
    #pragma unroll
    for (int i = 0; i < 2; i++) {
        const float* base = g_qkv + (size_t)tb0 * Nn * H3c;
        #pragma unroll
        for (int k = 0; k < 3; k++) {
            const float2* src = (const float2*)(base + (size_t)sIdx[warp][i][k] * H3c);
            float2* dst = (float2*)&sR[warp][i][k*ATT_RSTR];
            #pragma unroll
            for (int it = 0; it < 3; it++)
                dst[it*32 + lane] = src[it*32 + lane];
        }
    }
    __syncwarp();

    // Compute: 24 lanes = 2 inst x 12 (qr,head)
    if (lane < 24) {
        int i = lane / 12, w12 = lane % 12;
        int qr = w12 >> 2, hh = w12 & 3;
        const float* R = sR[warp][i];
        const float* q = R + qr*ATT_RSTR + hh*16;
        float l[3];
        #pragma unroll
        for (int kr = 0; kr < 3; kr++) {
            const float* kv = R + kr*ATT_RSTR + 64 + hh*16;
            float s = 0.f;
            #pragma unroll
            for (int d = 0; d < 16; d++) s += q[d] * kv[d];
            l[kr] = s * 0.25f;
        }
        float m = fmaxf(l[0], fmaxf(l[1], l[2]));
        float e0 = __expf(l[0] - m), e1 = __expf(l[1] - m), e2 = __expf(l[2] - m);
        float inv = 1.f / (e0 + e1 + e2);
        e0 *= inv; e1 *= inv; e2 *= inv;
        const float* v0 = R + 0*ATT_RSTR + 128 + hh*16;
        const float* v1 = R + 1*ATT_RSTR + 128 + hh*16;
        const float* v2 = R + 2*ATT_RSTR + 128 + hh*16;
        float* o = &sO[warp][i][qr*ATT_OSTR + hh*16];
        #pragma unroll
        for (int d = 0; d < 16; d++)
            o[d] = e0 * v0[d] + e1 * v1[d] + e2 * v2[d];
    }
    __syncwarp();

    // Scatter: 32 lanes = 2 inst x 16 float4-columns
    {
        int i = lane >> 4, l = lane & 15;
        float4* yo = (float4*)g_yo + (size_t)tb0 * Nn * 16;
        #pragma unroll
        for (int k = 0; k < 3; k++) {
            float4 v = *(const float4*)&sO[warp][i][k*ATT_OSTR + l*4];
            atomicAdd(&yo[(size_t)sIdx[warp][i][k] * 16 + l], v);
        }
    }
}

// ---------------------------------------------------------------------------
__global__ __launch_bounds__(256)
void k_sum(const float* __restrict__ nnz)
{
    __shared__ float red[4][64];
    __shared__ float red0[4];
    int blk = blockIdx.x;        // 0..255
    int g = blk >> 2, chunk = blk & 3;
    int tid = threadIdx.x;
    int r4 = tid >> 6;
    int col = tid & 63;

    float acc = 0.f, acc0 = 0.f;
    int nbase = (g & 3) * 4096;
    const float* yob = g_yo + (size_t)g * 4096 * 64;
    int rend = (chunk + 1) * 1024;
    for (int rr = chunk * 1024 + r4; rr < rend; rr += 4) {
        int n = nbase + rr;
        float inv = 1.f / nnz[n];
        acc += yob[(size_t)rr * 64 + col] * inv;
        if (col == 0) acc0 += (float)g_cnt[n] * inv;
    }
    red[r4][col] = acc;
    if (col == 0) red0[r4] = acc0;
    __syncthreads();
    if (tid < 64)
        atomicAdd(&g_s1[g * 64 + tid], red[0][tid] + red[1][tid] + red[2][tid] + red[3][tid]);
    if (tid == 0)
        atomicAdd(&g_s0[g], red0[0] + red0[1] + red0[2] + red0[3]);
}

// ---------------------------------------------------------------------------
// Logit head (unchanged).
// ---------------------------------------------------------------------------
__global__ __launch_bounds__(256, 2)
void k_post(const float* __restrict__ nnz,
            const float* __restrict__ W2, const float* __restrict__ b2,
            float* __restrict__ logit_out)
{
    extern __shared__ float ps[];
    float4* sT4 = (float4*)ps;                 // 256 rows x 17 float4 (pad)
    float*  sM  = ps + 256*17*4;               // 4096
    float*  sc1 = sM + 4096;                   // 64
    float*  sE  = sc1 + 64;                    // 64
    float*  sW2 = sE + 64;                     // 64

    int tid = threadIdx.x;
    int rowbase = blockIdx.x * 256;
    int g = rowbase >> 12;

    const float4* yo4 = (const float4*)g_yo + (size_t)rowbase * 16;
    for (int i = tid; i < 4096; i += 256)
        sT4[(i >> 4) * 17 + (i & 15)] = yo4[i];
    for (int i = tid; i < 4096; i += 256) sM[i] = g_M[i];
    if (tid < 64) { sc1[tid] = g_c1[tid]; sE[tid] = g_E[g*64 + tid]; sW2[tid] = W2[tid]; }
    __syncthreads();

    int row = rowbase + tid;
    int n = row & 16383;
    float inv = 1.f / nnz[n];
    float cninv = (float)g_cnt[n] * inv;

    float yo[64];
    #pragma unroll
    for (int jj = 0; jj < 16; jj++) {
        float4 v = sT4[tid * 17 + jj];
        yo[4*jj] = v.x; yo[4*jj+1] = v.y; yo[4*jj+2] = v.z; yo[4*jj+3] = v.w;
    }

    const ulonglong2* sM2 = (const ulonglong2*)sM;
    float logit = 0.f;
    #pragma unroll 1
    for (int p = 0; p < 8; p++) {
        unsigned long long acc[4] = {0ULL, 0ULL, 0ULL, 0ULL};
        #pragma unroll
        for (int j = 0; j < 64; j++) {
            unsigned long long y2 = packdup(yo[j]);
            ulonglong2 w0 = sM2[j*16 + p*2];
            ulonglong2 w1 = sM2[j*16 + p*2 + 1];
            ffma2(acc[0], y2, w0.x);
            ffma2(acc[1], y2, w0.y);
            ffma2(acc[2], y2, w1.x);
            ffma2(acc[3], y2, w1.y);
        }
        #pragma unroll
        for (int q = 0; q < 4; q++) {
            float2 v = unpack2(acc[q]);
            int c = p*8 + q*2;
            float pre, rr;
            pre = inv*v.x + cninv*sc1[c]   + sE[c];   rr = fmaxf(pre, 0.f); logit += rr*sW2[c];
            pre = inv*v.y + cninv*sc1[c+1] + sE[c+1]; rr = fmaxf(pre, 0.f); logit += rr*sW2[c+1];
        }
    }
    logit_out[row] = logit + b2[0];
}

// ---------------------------------------------------------------------------
__global__ void k_value(const float* __restrict__ extra,
                        const float* __restrict__ Wv1, const float* __restrict__ bv1,
                        float* __restrict__ val_out)
{
    __shared__ float sv[64];
    int tid = threadIdx.x;                  // 64 = (tb,kall)
    float acc = 0.f;
    #pragma unroll
    for (int j = 0; j < 64; j++) acc += g_s1[tid*64 + j] * g_wv[j];
    acc += g_s0[tid] * g_bv[0];
    acc *= (1.f / (float)N0c);
    #pragma unroll
    for (int d = 0; d < 4; d++) acc += extra[tid*4 + d] * Wv1[64 + d];
    acc += bv1[0];
    sv[tid] = acc;
    __syncthreads();
    if (tid < 16)
        val_out[tid] = sv[tid*4] + sv[tid*4+1] + sv[tid*4+2] + sv[tid*4+3];
}

// ---------------------------------------------------------------------------
extern "C" void kernel_launch(void* const* d_in, const int* in_sizes, int n_in,
                              void* d_out, int out_size)
{
    const float* h0       = (const float*)d_in[0];
    const float* h_global = (const float*)d_in[1];
    const float* x        = (const float*)d_in[2];
    const float* extra    = (const float*)d_in[3];
    const uint32_t* dones = (const uint32_t*)d_in[4];
    const int*   indices  = (const int*)d_in[5];
    const float* nnz      = (const float*)d_in[6];
    const float* Wi  = (const float*)d_in[7];
    const float* bi  = (const float*)d_in[8];
    const float* Wh  = (const float*)d_in[9];
    const float* bhn = (const float*)d_in[10];
    const float* Wq  = (const float*)d_in[11];
    const float* bq  = (const float*)d_in[12];
    const float* Wk  = (const float*)d_in[13];
    const float* bk  = (const float*)d_in[14];
    const float* Wv  = (const float*)d_in[15];
    const float* bv  = (const float*)d_in[16];
    const float* Wo  = (const float*)d_in[17];
    const float* bo  = (const float*)d_in[18];
    const float* W1  = (const float*)d_in[19];
    const float* b1  = (const float*)d_in[20];
    const float* W2  = (const float*)d_in[21];
    const float* b2  = (const float*)d_in[22];
    const float* Wv1 = (const float*)d_in[23];
    const float* bv1 = (const float*)d_in[24];

    float* out       = (float*)d_out;
    float* out_hfin  = out;
    float* out_hg    = out + OFF_HG;
    float* out_logit = out + OFF_LOGIT;
    float* out_val   = out + OFF_VAL;

    void *yo_ptr, *cnt_ptr, *s1_ptr, *s0_ptr;
    cudaGetSymbolAddress(&yo_ptr,  g_yo);
    cudaGetSymbolAddress(&cnt_ptr, g_cnt);
    cudaGetSymbolAddress(&s1_ptr,  g_s1);
    cudaGetSymbolAddress(&s0_ptr,  g_s0);
    cudaMemsetAsync(yo_ptr,  0, sizeof(float) * (size_t)TBNc * Hh, 0);
    cudaMemsetAsync(cnt_ptr, 0, sizeof(int) * Nn, 0);
    cudaMemsetAsync(s1_ptr,  0, sizeof(float) * 64 * 64, 0);
    cudaMemsetAsync(s0_ptr,  0, sizeof(float) * 64, 0);

    cudaMemcpyAsync(out_hg, h_global, 1024 * sizeof(float), cudaMemcpyDeviceToDevice, 0);

    int smem_gru  = GRU_SM_TOT * 4;                                // 140032 B
    cudaFuncSetAttribute(k_gru_qkv, cudaFuncAttributeMaxDynamicSharedMemorySize, smem_gru);
    int smem_post = (256*17*4 + 4096 + 64 + 64 + 64) * 4;          // 87040 B
    cudaFuncSetAttribute(k_post, cudaFuncAttributeMaxDynamicSharedMemorySize, smem_post);

    k_count<<<(Ff * ORD + 255) / 256, 256>>>(indices);
    k_prep<<<32, 256>>>(Wo, bo, W1, b1, Wv1, extra);
    k_gru_qkv<<<BNc / 128, 512, smem_gru>>>(h0, x, dones, Wi, bi, Wh, bhn,
                                            Wq, bq, Wk, bk, Wv, bv, out_hfin);
    k_attn<<<TBc * Ff / 16, 256>>>(indices);
    k_sum<<<256, 256>>>(nnz);
    k_post<<<TBNc / 256, 256, smem_post>>>(nnz, W2, b2, out_logit);
    k_value<<<1, 64>>>(extra, Wv1, bv1, out_val);
}

// round 12
// speedup vs baseline: 1.7109x; 1.1186x over previous
#include <cuda_runtime.h>
#include <math.h>
#include <stdint.h>

// Problem constants
#define Tt   4
#define Bb   4
#define Nn   16384
#define KALLc 4
#define Ff   16384
#define ORD  3
#define Hh   64
#define N0c  4096

#define TBc  (Tt*Bb)        // 16
#define BNc  (Bb*Nn)        // 65536
#define TBNc (TBc*Nn)       // 262144
#define H3c  (3*Hh)         // 192

// Output layout: h_fin [B,N,H] | h_global [B,K,64] | logit [T,B,N] | value [T,B]
#define OFF_HG    4194304
#define OFF_LOGIT (OFF_HG + 1024)
#define OFF_VAL   (OFF_LOGIT + 262144)

// Scratch
__device__ float g_qkv[TBNc * H3c];   // [T,B,N,192]
__device__ float g_yo [TBNc * Hh];    // [T,B,N,64]
__device__ int   g_cnt[Nn];
__device__ float g_M  [64*64];        // Wo @ W1[:64]
__device__ float g_c1 [64];           // bo @ W1[:64]
__device__ float g_E  [64*64];        // per (tb,kall): b1 + extra@W1[64:]
__device__ float g_wv [64];           // Wo @ Wv1[:64]
__device__ float g_bv [1];            // bo @ Wv1[:64]
__device__ float g_s1 [64*64];        // per (tb,kall): sum_n yo*invnnz
__device__ float g_s0 [64];           // per (tb,kall): sum_n cnt*invnnz

__device__ __forceinline__ float sigmoidf_(float v) { return 1.f / (1.f + expf(-v)); }

// ---- packed fp32 helpers (fma.rn.f32x2) ----
__device__ __forceinline__ unsigned long long packdup(float v) {
    unsigned long long r;
    asm("mov.b64 %0, {%1, %1};" : "=l"(r) : "f"(v));
    return r;
}
__device__ __forceinline__ unsigned long long pack2(float a, float b) {
    unsigned long long r;
    asm("mov.b64 %0, {%1, %2};" : "=l"(r) : "f"(a), "f"(b));
    return r;
}
__device__ __forceinline__ void ffma2(unsigned long long& acc,
                                      unsigned long long a, unsigned long long b) {
    asm("fma.rn.f32x2 %0, %1, %2, %0;" : "+l"(acc) : "l"(a), "l"(b));
}
__device__ __forceinline__ float2 unpack2(unsigned long long v) {
    float lo, hi;
    asm("mov.b64 {%0, %1}, %2;" : "=f"(lo), "=f"(hi) : "l"(v));
    return make_float2(lo, hi);
}

// ---------------------------------------------------------------------------
__global__ void k_count(const int* __restrict__ indices) {
    int i = blockIdx.x * 256 + threadIdx.x;
    if (i < Ff * ORD) atomicAdd(&g_cnt[indices[i]], 1);
}

// ---------------------------------------------------------------------------
__global__ void k_prep(const float* __restrict__ Wo, const float* __restrict__ bo,
                       const float* __restrict__ W1, const float* __restrict__ b1,
                       const float* __restrict__ Wv1,
                       const float* __restrict__ extra)
{
    int o = blockIdx.x * 256 + threadIdx.x;   // grid 32 x 256 = 8192
    if (o < 4096) {
        int j = o >> 6, c = o & 63;
        float s = 0.f;
        #pragma unroll
        for (int h = 0; h < 64; h++) s += Wo[j*64 + h] * W1[h*64 + c];
        g_M[o] = s;
    } else {
        int e = o - 4096;
        int g = e >> 6, c = e & 63;
        float s = b1[c];
        #pragma unroll
        for (int d = 0; d < 4; d++) s += extra[g*4 + d] * W1[(64 + d)*64 + c];
        g_E[e] = s;
    }
    if (blockIdx.x == 0 && threadIdx.x < 64) {
        int tid = threadIdx.x;
        float s = 0.f, w = 0.f;
        #pragma unroll
        for (int h = 0; h < 64; h++) {
            s += bo[h] * W1[h*64 + tid];
            w += Wo[tid*64 + h] * Wv1[h];
        }
        g_c1[tid] = s;
        g_wv[tid] = w;
        if (tid == 0) {
            float bvv = 0.f;
            #pragma unroll
            for (int h = 0; h < 64; h++) bvv += bo[h] * Wv1[h];
            g_bv[0] = bvv;
        }
    }
}

// ---------------------------------------------------------------------------
// Fused GRU scan + QKV projection (unchanged, passing).
// ---------------------------------------------------------------------------
#define GRU_HSTR     68
#define GRU_OFF_WI   12288
#define GRU_OFF_BI   (GRU_OFF_WI + 768)       // 13056
#define GRU_OFF_BHN  (GRU_OFF_BI + 192)       // 13248
#define GRU_OFF_WQ   (GRU_OFF_BHN + 64)       // 13312
#define GRU_OFF_BQ   (GRU_OFF_WQ + 12288)     // 25600
#define GRU_OFF_X    (GRU_OFF_BQ + 192)       // 25792
#define GRU_OFF_H    (GRU_OFF_X + 512)        // 26304
#define GRU_SM_TOT   (GRU_OFF_H + 128*GRU_HSTR) // 35008 floats = 140032 B

__global__ __launch_bounds__(512)
void k_gru_qkv(const float* __restrict__ h0, const float* __restrict__ x,
               const uint32_t* __restrict__ dones,
               const float* __restrict__ Wi, const float* __restrict__ bi,
               const float* __restrict__ Wh, const float* __restrict__ bhn,
               const float* __restrict__ Wq, const float* __restrict__ bq,
               const float* __restrict__ Wk, const float* __restrict__ bk,
               const float* __restrict__ Wv, const float* __restrict__ bv,
               float* __restrict__ hfin_out)
{
    extern __shared__ float gs[];
    float* sWh   = gs;                    // reordered: [k][3c+g]
    float* sWi   = gs + GRU_OFF_WI;       // reordered
    float* sbi   = gs + GRU_OFF_BI;       // reordered
    float* sbhn  = gs + GRU_OFF_BHN;      // natural unit order
    float* sWq   = gs + GRU_OFF_WQ;       // [k][q|k|v 192]
    float* sbq   = gs + GRU_OFF_BQ;
    float* sX    = gs + GRU_OFF_X;
    float* sH    = gs + GRU_OFF_H;

    int tid = threadIdx.x;
    size_t rowbase = (size_t)blockIdx.x * 128;
    int b = (int)(rowbase >> 14);

    for (int i = tid; i < 12288; i += 512) {
        int k = i / 192, e = i % 192;
        int c = e / 3, g = e % 3;
        sWh[i] = Wh[k*192 + g*64 + c];
    }
    for (int i = tid; i < 768; i += 512) {
        int k = i / 192, e = i % 192;
        int c = e / 3, g = e % 3;
        sWi[i] = Wi[k*192 + g*64 + c];
    }
    if (tid < 192) {
        int c = tid / 3, g = tid % 3;
        sbi[tid] = bi[g*64 + c];
    }
    if (tid < 64) sbhn[tid] = bhn[tid];
    for (int i = tid; i < 12288; i += 512) {
        int k = i / 192, e = i % 192;
        sWq[i] = (e < 64) ? Wq[k*64 + e] : (e < 128) ? Wk[k*64 + e - 64] : Wv[k*64 + e - 128];
    }
    if (tid < 192)
        sbq[tid] = (tid < 64) ? bq[tid] : (tid < 128) ? bk[tid - 64] : bv[tid - 128];
    for (int i = tid; i < 8192; i += 512) {
        int r = i >> 6, c = i & 63;
        sH[r*GRU_HSTR + c] = h0[rowbase*64 + i];
    }

    int rg = tid >> 5;
    int cg = tid & 31;
    int c0 = cg * 6;
    int u0 = cg * 2;

    #pragma unroll 1
    for (int t = 0; t < Tt; t++) {
        __syncthreads();

        sX[tid] = x[((size_t)t * BNc + rowbase) * 4 + tid];
        if (dones[t * Bb + b] != 0u) {
            for (int i = tid; i < 8192; i += 512) {
                int r = i >> 6, c = i & 63;
                sH[r*GRU_HSTR + c] = 0.f;
            }
        }
        __syncthreads();

        unsigned long long acc[8][3];
        #pragma unroll
        for (int i = 0; i < 8; i++) { acc[i][0] = 0ULL; acc[i][1] = 0ULL; acc[i][2] = 0ULL; }

        const float* sWrow = sWh + c0;
        #pragma unroll 1
        for (int k4 = 0; k4 < 16; k4++) {
            unsigned long long w[4][3];
            #pragma unroll
            for (int kk = 0; kk < 4; kk++) {
                const float* wr = sWrow + (k4*4 + kk) * 192;
                w[kk][0] = *(const unsigned long long*)(wr);
                w[kk][1] = *(const unsigned long long*)(wr + 2);
                w[kk][2] = *(const unsigned long long*)(wr + 4);
            }
            #pragma unroll
            for (int i = 0; i < 8; i++) {
                float4 hv = *(const float4*)&sH[(rg + 16*i) * GRU_HSTR + k4*4];
                unsigned long long hh0 = packdup(hv.x);
                ffma2(acc[i][0], hh0, w[0][0]); ffma2(acc[i][1], hh0, w[0][1]); ffma2(acc[i][2], hh0, w[0][2]);
                unsigned long long hh1 = packdup(hv.y);
                ffma2(acc[i][0], hh1, w[1][0]); ffma2(acc[i][1], hh1, w[1][1]); ffma2(acc[i][2], hh1, w[1][2]);
                unsigned long long hh2 = packdup(hv.z);
                ffma2(acc[i][0], hh2, w[2][0]); ffma2(acc[i][1], hh2, w[2][1]); ffma2(acc[i][2], hh2, w[2][2]);
                unsigned long long hh3 = packdup(hv.w);
                ffma2(acc[i][0], hh3, w[3][0]); ffma2(acc[i][1], hh3, w[3][1]); ffma2(acc[i][2], hh3, w[3][2]);
            }
        }
        __syncthreads();

        float2 bh2 = *(const float2*)&sbhn[u0];
        #pragma unroll
        for (int i = 0; i < 8; i++) {
            int row = rg + 16*i;
            unsigned long long g0 = *(const unsigned long long*)(sbi + c0);
            unsigned long long g1 = *(const unsigned long long*)(sbi + c0 + 2);
            unsigned long long g2 = *(const unsigned long long*)(sbi + c0 + 4);
            #pragma unroll
            for (int d = 0; d < 4; d++) {
                unsigned long long xv = packdup(sX[row*4 + d]);
                const float* wr = sWi + d*192 + c0;
                ffma2(g0, xv, *(const unsigned long long*)(wr));
                ffma2(g1, xv, *(const unsigned long long*)(wr + 2));
                ffma2(g2, xv, *(const unsigned long long*)(wr + 4));
            }
            float2 a0 = unpack2(acc[i][0]);
            float2 a1 = unpack2(acc[i][1]);
            float2 a2 = unpack2(acc[i][2]);
            float2 i0 = unpack2(g0);
            float2 i1 = unpack2(g1);
            float2 i2 = unpack2(g2);

            float2 hold = *(const float2*)&sH[row*GRU_HSTR + u0];
            float r0 = sigmoidf_(i0.x + a0.x);
            float z0 = sigmoidf_(i0.y + a0.y);
            float n0 = tanhf(i1.x + r0 * (a1.x + bh2.x));
            float h0n = (1.f - z0) * n0 + z0 * hold.x;
            float r1 = sigmoidf_(i1.y + a1.y);
            float z1 = sigmoidf_(i2.x + a2.x);
            float n1 = tanhf(i2.y + r1 * (a2.y + bh2.y));
            float h1n = (1.f - z1) * n1 + z1 * hold.y;
            *(float2*)&sH[row*GRU_HSTR + u0] = make_float2(h0n, h1n);
        }
        __syncthreads();

        {
            unsigned long long qa[8][3];
            float2 b01 = *(const float2*)&sbq[c0];
            float2 b23 = *(const float2*)&sbq[c0 + 2];
            float2 b45 = *(const float2*)&sbq[c0 + 4];
            #pragma unroll
            for (int i = 0; i < 8; i++) {
                qa[i][0] = pack2(b01.x, b01.y);
                qa[i][1] = pack2(b23.x, b23.y);
                qa[i][2] = pack2(b45.x, b45.y);
            }
            const float* sQrow = sWq + c0;
            #pragma unroll 1
            for (int k4 = 0; k4 < 16; k4++) {
                unsigned long long w[4][3];
                #pragma unroll
                for (int kk = 0; kk < 4; kk++) {
                    const float* wr = sQrow + (k4*4 + kk) * 192;
                    w[kk][0] = *(const unsigned long long*)(wr);
                    w[kk][1] = *(const unsigned long long*)(wr + 2);
                    w[kk][2] = *(const unsigned long long*)(wr + 4);
                }
                #pragma unroll
                for (int i = 0; i < 8; i++) {
                    float4 hv = *(const float4*)&sH[(rg + 16*i) * GRU_HSTR + k4*4];
                    unsigned long long hh0 = packdup(hv.x);
                    ffma2(qa[i][0], hh0, w[0][0]); ffma2(qa[i][1], hh0, w[0][1]); ffma2(qa[i][2], hh0, w[0][2]);
                    unsigned long long hh1 = packdup(hv.y);
                    ffma2(qa[i][0], hh1, w[1][0]); ffma2(qa[i][1], hh1, w[1][1]); ffma2(qa[i][2], hh1, w[1][2]);
                    unsigned long long hh2 = packdup(hv.z);
                    ffma2(qa[i][0], hh2, w[2][0]); ffma2(qa[i][1], hh2, w[2][1]); ffma2(qa[i][2], hh2, w[2][2]);
                    unsigned long long hh3 = packdup(hv.w);
                    ffma2(qa[i][0], hh3, w[3][0]); ffma2(qa[i][1], hh3, w[3][1]); ffma2(qa[i][2], hh3, w[3][2]);
                }
            }
            size_t orow0 = (size_t)t * BNc + rowbase;
            #pragma unroll
            for (int i = 0; i < 8; i++) {
                unsigned long long* dst =
                    (unsigned long long*)(g_qkv + (orow0 + rg + 16*i) * H3c + c0);
                dst[0] = qa[i][0];
                dst[1] = qa[i][1];
                dst[2] = qa[i][2];
            }
        }
    }

    __syncthreads();
    for (int i = tid; i < 8192; i += 512) {
        int r = i >> 6, c = i & 63;
        hfin_out[rowbase*64 + i] = sH[r*GRU_HSTR + c];
    }
}

// ---------------------------------------------------------------------------
// Attention: 2 instances per warp; flat float4 gather (9 LDG.128/lane).
// ---------------------------------------------------------------------------
#define ATT_RSTR 196
#define ATT_OSTR 68
__global__ __launch_bounds__(256)
void k_attn(const int* __restrict__ indices)
{
    __shared__ __align__(16) float sR[8][2][3*ATT_RSTR];
    __shared__ __align__(16) float sO[8][2][3*ATT_OSTR];
    __shared__ int sIdx[8][2][3];

    int warp = threadIdx.x >> 5, lane = threadIdx.x & 31;
    int ip = blockIdx.x * 16 + warp * 2;      // instance pair base
    int tb0 = ip >> 14;                       // pair never crosses tb boundary
    int f0  = ip & 16383;

    if (lane < 6) {
        int i = lane / 3, k = lane % 3;
        sIdx[warp][i][k] = __ldg(&indices[(f0 + i)*3 + k]);
    }
    __syncwarp();

    // Flat gather: 6 rows x 48 float4 = 288 chunks, 9 per lane
    {
        const float* base = g_qkv + (size_t)tb0 * Nn * H3c;
        #pragma unroll
        for (int it = 0; it < 9; it++) {
            int idx = it * 32 + lane;        // 0..287
            int rowi = idx / 48;             // 0..5
            int e4 = idx % 48;               // float4 index within row
            int i = rowi / 3, k = rowi % 3;
            const float4* src = (const float4*)(base + (size_t)sIdx[warp][i][k] * H3c);
            *(float4*)&sR[warp][i][k*ATT_RSTR + e4*4] = src[e4];
        }
    }
    __syncwarp();

    // Compute: 24 lanes = 2 inst x 12 (qr,head)
    if (lane < 24) {
        int i = lane / 12, w12 = lane % 12;
        int qr = w12 >> 2, hh = w12 & 3;
        const float* R = sR[warp][i];
        const float* q = R + qr*ATT_RSTR + hh*16;
        float l[3];
        #pragma unroll
        for (int kr = 0; kr < 3; kr++) {
            const float* kv = R + kr*ATT_RSTR + 64 + hh*16;
            float s = 0.f;
            #pragma unroll
            for (int d = 0; d < 16; d++) s += q[d] * kv[d];
            l[kr] = s * 0.25f;
        }
        float m = fmaxf(l[0], fmaxf(l[1], l[2]));
        float e0 = __expf(l[0] - m), e1 = __expf(l[1] - m), e2 = __expf(l[2] - m);
        float inv = 1.f / (e0 + e1 + e2);
        e0 *= inv; e1 *= inv; e2 *= inv;
        const float* v0 = R + 0*ATT_RSTR + 128 + hh*16;
        const float* v1 = R + 1*ATT_RSTR + 128 + hh*16;
        const float* v2 = R + 2*ATT_RSTR + 128 + hh*16;
        float* o = &sO[warp][i][qr*ATT_OSTR + hh*16];
        #pragma unroll
        for (int d = 0; d < 16; d++)
            o[d] = e0 * v0[d] + e1 * v1[d] + e2 * v2[d];
    }
    __syncwarp();

    // Scatter: 32 lanes = 2 inst x 16 float4-columns
    {
        int i = lane >> 4, l = lane & 15;
        float4* yo = (float4*)g_yo + (size_t)tb0 * Nn * 16;
        #pragma unroll
        for (int k = 0; k < 3; k++) {
            float4 v = *(const float4*)&sO[warp][i][k*ATT_OSTR + l*4];
            atomicAdd(&yo[(size_t)sIdx[warp][i][k] * 16 + l], v);
        }
    }
}

// ---------------------------------------------------------------------------
// Logit head + fused value-head segment sums (k_sum eliminated).
// ---------------------------------------------------------------------------
__global__ __launch_bounds__(256, 2)
void k_post(const float* __restrict__ nnz,
            const float* __restrict__ W2, const float* __restrict__ b2,
            float* __restrict__ logit_out)
{
    extern __shared__ float ps[];
    float4* sT4 = (float4*)ps;                 // 256 rows x 17 float4 (pad)
    float*  sM  = ps + 256*17*4;               // 4096
    float*  sc1 = sM + 4096;                   // 64
    float*  sE  = sc1 + 64;                    // 64
    float*  sW2 = sE + 64;                     // 64
    float*  sRed = sW2 + 64;                   // 4*64 = 256
    float*  sR0  = sRed + 256;                 // 8

    int tid = threadIdx.x;
    int rowbase = blockIdx.x * 256;
    int g = rowbase >> 12;

    const float4* yo4 = (const float4*)g_yo + (size_t)rowbase * 16;
    for (int i = tid; i < 4096; i += 256)
        sT4[(i >> 4) * 17 + (i & 15)] = yo4[i];
    for (int i = tid; i < 4096; i += 256) sM[i] = g_M[i];
    if (tid < 64) { sc1[tid] = g_c1[tid]; sE[tid] = g_E[g*64 + tid]; sW2[tid] = W2[tid]; }
    __syncthreads();

    int row = rowbase + tid;
    int n = row & 16383;
    float inv = 1.f / nnz[n];
    float cninv = (float)g_cnt[n] * inv;

    float yo[64];
    #pragma unroll
    for (int jj = 0; jj < 16; jj++) {
        float4 v = sT4[tid * 17 + jj];
        yo[4*jj] = v.x; yo[4*jj+1] = v.y; yo[4*jj+2] = v.z; yo[4*jj+3] = v.w;
    }

    const ulonglong2* sM2 = (const ulonglong2*)sM;
    float logit = 0.f;
    #pragma unroll 1
    for (int p = 0; p < 8; p++) {
        unsigned long long acc[4] = {0ULL, 0ULL, 0ULL, 0ULL};
        #pragma unroll
        for (int j = 0; j < 64; j++) {
            unsigned long long y2 = packdup(yo[j]);
            ulonglong2 w0 = sM2[j*16 + p*2];
            ulonglong2 w1 = sM2[j*16 + p*2 + 1];
            ffma2(acc[0], y2, w0.x);
            ffma2(acc[1], y2, w0.y);
            ffma2(acc[2], y2, w1.x);
            ffma2(acc[3], y2, w1.y);
        }
        #pragma unroll
        for (int q = 0; q < 4; q++) {
            float2 v = unpack2(acc[q]);
            int c = p*8 + q*2;
            float pre, rr;
            pre = inv*v.x + cninv*sc1[c]   + sE[c];   rr = fmaxf(pre, 0.f); logit += rr*sW2[c];
            pre = inv*v.y + cninv*sc1[c+1] + sE[c+1]; rr = fmaxf(pre, 0.f); logit += rr*sW2[c+1];
        }
    }
    logit_out[row] = logit + b2[0];

    // ---- fused value-head partial sums ----
    __syncthreads();               // all logit reads of sT4 finished (regs only, but cheap)
    // overwrite own staged row with yo*invnnz
    #pragma unroll
    for (int jj = 0; jj < 16; jj++) {
        sT4[tid * 17 + jj] = make_float4(yo[4*jj]*inv, yo[4*jj+1]*inv,
                                         yo[4*jj+2]*inv, yo[4*jj+3]*inv);
    }
    __syncthreads();
    {
        int col = tid & 63, part = tid >> 6;   // 4 partials per column
        const float* sS = ps;                   // rows stride 68 floats
        float s = 0.f;
        #pragma unroll 4
        for (int r = part*64; r < part*64 + 64; r++)
            s += sS[r*68 + col];
        sRed[part*64 + col] = s;
    }
    // cnt*invnnz reduction over 256 threads
    {
        float v = cninv;
        #pragma unroll
        for (int off = 16; off; off >>= 1) v += __shfl_xor_sync(0xffffffffu, v, off);
        if ((tid & 31) == 0) sR0[tid >> 5] = v;
    }
    __syncthreads();
    if (tid < 64)
        atomicAdd(&g_s1[g*64 + tid], sRed[tid] + sRed[64 + tid] + sRed[128 + tid] + sRed[192 + tid]);
    if (tid == 0) {
        float s0 = 0.f;
        #pragma unroll
        for (int w = 0; w < 8; w++) s0 += sR0[w];
        atomicAdd(&g_s0[g], s0);
    }
}

// ---------------------------------------------------------------------------
__global__ void k_value(const float* __restrict__ extra,
                        const float* __restrict__ Wv1, const float* __restrict__ bv1,
                        float* __restrict__ val_out)
{
    __shared__ float sv[64];
    int tid = threadIdx.x;                  // 64 = (tb,kall)
    float acc = 0.f;
    #pragma unroll
    for (int j = 0; j < 64; j++) acc += g_s1[tid*64 + j] * g_wv[j];
    acc += g_s0[tid] * g_bv[0];
    acc *= (1.f / (float)N0c);
    #pragma unroll
    for (int d = 0; d < 4; d++) acc += extra[tid*4 + d] * Wv1[64 + d];
    acc += bv1[0];
    sv[tid] = acc;
    __syncthreads();
    if (tid < 16)
        val_out[tid] = sv[tid*4] + sv[tid*4+1] + sv[tid*4+2] + sv[tid*4+3];
}

// ---------------------------------------------------------------------------
extern "C" void kernel_launch(void* const* d_in, const int* in_sizes, int n_in,
                              void* d_out, int out_size)
{
    const float* h0       = (const float*)d_in[0];
    const float* h_global = (const float*)d_in[1];
    const float* x        = (const float*)d_in[2];
    const float* extra    = (const float*)d_in[3];
    const uint32_t* dones = (const uint32_t*)d_in[4];
    const int*   indices  = (const int*)d_in[5];
    const float* nnz      = (const float*)d_in[6];
    const float* Wi  = (const float*)d_in[7];
    const float* bi  = (const float*)d_in[8];
    const float* Wh  = (const float*)d_in[9];
    const float* bhn = (const float*)d_in[10];
    const float* Wq  = (const float*)d_in[11];
    const float* bq  = (const float*)d_in[12];
    const float* Wk  = (const float*)d_in[13];
    const float* bk  = (const float*)d_in[14];
    const float* Wv  = (const float*)d_in[15];
    const float* bv  = (const float*)d_in[16];
    const float* Wo  = (const float*)d_in[17];
    const float* bo  = (const float*)d_in[18];
    const float* W1  = (const float*)d_in[19];
    const float* b1  = (const float*)d_in[20];
    const float* W2  = (const float*)d_in[21];
    const float* b2  = (const float*)d_in[22];
    const float* Wv1 = (const float*)d_in[23];
    const float* bv1 = (const float*)d_in[24];

    float* out       = (float*)d_out;
    float* out_hfin  = out;
    float* out_hg    = out + OFF_HG;
    float* out_logit = out + OFF_LOGIT;
    float* out_val   = out + OFF_VAL;

    void *yo_ptr, *cnt_ptr, *s1_ptr, *s0_ptr;
    cudaGetSymbolAddress(&yo_ptr,  g_yo);
    cudaGetSymbolAddress(&cnt_ptr, g_cnt);
    cudaGetSymbolAddress(&s1_ptr,  g_s1);
    cudaGetSymbolAddress(&s0_ptr,  g_s0);
    cudaMemsetAsync(yo_ptr,  0, sizeof(float) * (size_t)TBNc * Hh, 0);
    cudaMemsetAsync(cnt_ptr, 0, sizeof(int) * Nn, 0);
    cudaMemsetAsync(s1_ptr,  0, sizeof(float) * 64 * 64, 0);
    cudaMemsetAsync(s0_ptr,  0, sizeof(float) * 64, 0);

    cudaMemcpyAsync(out_hg, h_global, 1024 * sizeof(float), cudaMemcpyDeviceToDevice, 0);

    int smem_gru  = GRU_SM_TOT * 4;                                // 140032 B
    cudaFuncSetAttribute(k_gru_qkv, cudaFuncAttributeMaxDynamicSharedMemorySize, smem_gru);
    int smem_post = (256*17*4 + 4096 + 64 + 64 + 64 + 256 + 8) * 4; // 88112 B
    cudaFuncSetAttribute(k_post, cudaFuncAttributeMaxDynamicSharedMemorySize, smem_post);

    k_count<<<(Ff * ORD + 255) / 256, 256>>>(indices);
    k_prep<<<32, 256>>>(Wo, bo, W1, b1, Wv1, extra);
    k_gru_qkv<<<BNc / 128, 512, smem_gru>>>(h0, x, dones, Wi, bi, Wh, bhn,
                                            Wq, bq, Wk, bk, Wv, bv, out_hfin);
    k_attn<<<TBc * Ff / 16, 256>>>(indices);
    k_post<<<TBNc / 256, 256, smem_post>>>(nnz, W2, b2, out_logit);
    k_value<<<1, 64>>>(extra, Wv1, bv1, out_val);
}

// round 13
// speedup vs baseline: 1.8265x; 1.0675x over previous
#include <cuda_runtime.h>
#include <math.h>
#include <stdint.h>

// Problem constants
#define Tt   4
#define Bb   4
#define Nn   16384
#define KALLc 4
#define Ff   16384
#define ORD  3
#define Hh   64
#define N0c  4096

#define TBc  (Tt*Bb)        // 16
#define BNc  (Bb*Nn)        // 65536
#define TBNc (TBc*Nn)       // 262144
#define H3c  (3*Hh)         // 192

// Output layout: h_fin [B,N,H] | h_global [B,K,64] | logit [T,B,N] | value [T,B]
#define OFF_HG    4194304
#define OFF_LOGIT (OFF_HG + 1024)
#define OFF_VAL   (OFF_LOGIT + 262144)

// Scratch
__device__ float g_qkv[TBNc * H3c];   // [T,B,N,192]
__device__ float g_yo [TBNc * Hh];    // [T,B,N,64]
__device__ int   g_cnt[Nn];
__device__ float g_M  [64*64];        // Wo @ W1[:64]
__device__ float g_c1 [64];           // bo @ W1[:64]
__device__ float g_E  [64*64];        // per (tb,kall): b1 + extra@W1[64:]
__device__ float g_wv [64];           // Wo @ Wv1[:64]
__device__ float g_bv [1];            // bo @ Wv1[:64]
__device__ float g_s1 [64*64];        // per (tb,kall): sum_n yo*invnnz
__device__ float g_s0 [64];           // per (tb,kall): sum_n cnt*invnnz

__device__ __forceinline__ float sigmoidf_(float v) { return 1.f / (1.f + expf(-v)); }

// ---- packed fp32 helpers (fma.rn.f32x2) ----
__device__ __forceinline__ unsigned long long packdup(float v) {
    unsigned long long r;
    asm("mov.b64 %0, {%1, %1};" : "=l"(r) : "f"(v));
    return r;
}
__device__ __forceinline__ unsigned long long pack2(float a, float b) {
    unsigned long long r;
    asm("mov.b64 %0, {%1, %2};" : "=l"(r) : "f"(a), "f"(b));
    return r;
}
__device__ __forceinline__ void ffma2(unsigned long long& acc,
                                      unsigned long long a, unsigned long long b) {
    asm("fma.rn.f32x2 %0, %1, %2, %0;" : "+l"(acc) : "l"(a), "l"(b));
}
__device__ __forceinline__ float2 unpack2(unsigned long long v) {
    float lo, hi;
    asm("mov.b64 {%0, %1}, %2;" : "=f"(lo), "=f"(hi) : "l"(v));
    return make_float2(lo, hi);
}

// ---------------------------------------------------------------------------
__global__ void k_count(const int* __restrict__ indices) {
    int i = blockIdx.x * 256 + threadIdx.x;
    if (i < Ff * ORD) atomicAdd(&g_cnt[indices[i]], 1);
}

// ---------------------------------------------------------------------------
__global__ void k_prep(const float* __restrict__ Wo, const float* __restrict__ bo,
                       const float* __restrict__ W1, const float* __restrict__ b1,
                       const float* __restrict__ Wv1,
                       const float* __restrict__ extra)
{
    int o = blockIdx.x * 256 + threadIdx.x;   // grid 32 x 256 = 8192
    if (o < 4096) {
        int j = o >> 6, c = o & 63;
        float s = 0.f;
        #pragma unroll
        for (int h = 0; h < 64; h++) s += Wo[j*64 + h] * W1[h*64 + c];
        g_M[o] = s;
    } else {
        int e = o - 4096;
        int g = e >> 6, c = e & 63;
        float s = b1[c];
        #pragma unroll
        for (int d = 0; d < 4; d++) s += extra[g*4 + d] * W1[(64 + d)*64 + c];
        g_E[e] = s;
    }
    if (blockIdx.x == 0 && threadIdx.x < 64) {
        int tid = threadIdx.x;
        float s = 0.f, w = 0.f;
        #pragma unroll
        for (int h = 0; h < 64; h++) {
            s += bo[h] * W1[h*64 + tid];
            w += Wo[tid*64 + h] * Wv1[h];
        }
        g_c1[tid] = s;
        g_wv[tid] = w;
        if (tid == 0) {
            float bvv = 0.f;
            #pragma unroll
            for (int h = 0; h < 64; h++) bvv += bo[h] * Wv1[h];
            g_bv[0] = bvv;
        }
    }
}

// ---------------------------------------------------------------------------
// Fused GRU scan + QKV projection, PERSISTENT: 148 blocks loop over tiles,
// weights staged once per block.
// ---------------------------------------------------------------------------
#define GRU_HSTR     68
#define GRU_OFF_WI   12288
#define GRU_OFF_BI   (GRU_OFF_WI + 768)       // 13056
#define GRU_OFF_BHN  (GRU_OFF_BI + 192)       // 13248
#define GRU_OFF_WQ   (GRU_OFF_BHN + 64)       // 13312
#define GRU_OFF_BQ   (GRU_OFF_WQ + 12288)     // 25600
#define GRU_OFF_X    (GRU_OFF_BQ + 192)       // 25792
#define GRU_OFF_H    (GRU_OFF_X + 512)        // 26304
#define GRU_SM_TOT   (GRU_OFF_H + 128*GRU_HSTR) // 35008 floats = 140032 B
#define GRU_NT       512                       // 65536/128 tiles

__global__ __launch_bounds__(512)
void k_gru_qkv(const float* __restrict__ h0, const float* __restrict__ x,
               const uint32_t* __restrict__ dones,
               const float* __restrict__ Wi, const float* __restrict__ bi,
               const float* __restrict__ Wh, const float* __restrict__ bhn,
               const float* __restrict__ Wq, const float* __restrict__ bq,
               const float* __restrict__ Wk, const float* __restrict__ bk,
               const float* __restrict__ Wv, const float* __restrict__ bv,
               float* __restrict__ hfin_out)
{
    extern __shared__ float gs[];
    float* sWh   = gs;                    // reordered: [k][3c+g]
    float* sWi   = gs + GRU_OFF_WI;       // reordered
    float* sbi   = gs + GRU_OFF_BI;       // reordered
    float* sbhn  = gs + GRU_OFF_BHN;      // natural unit order
    float* sWq   = gs + GRU_OFF_WQ;       // [k][q|k|v 192]
    float* sbq   = gs + GRU_OFF_BQ;
    float* sX    = gs + GRU_OFF_X;
    float* sH    = gs + GRU_OFF_H;

    int tid = threadIdx.x;

    // Stage weights ONCE per block
    for (int i = tid; i < 12288; i += 512) {
        int k = i / 192, e = i % 192;
        int c = e / 3, g = e % 3;
        sWh[i] = Wh[k*192 + g*64 + c];
    }
    for (int i = tid; i < 768; i += 512) {
        int k = i / 192, e = i % 192;
        int c = e / 3, g = e % 3;
        sWi[i] = Wi[k*192 + g*64 + c];
    }
    if (tid < 192) {
        int c = tid / 3, g = tid % 3;
        sbi[tid] = bi[g*64 + c];
    }
    if (tid < 64) sbhn[tid] = bhn[tid];
    for (int i = tid; i < 12288; i += 512) {
        int k = i / 192, e = i % 192;
        sWq[i] = (e < 64) ? Wq[k*64 + e] : (e < 128) ? Wk[k*64 + e - 64] : Wv[k*64 + e - 128];
    }
    if (tid < 192)
        sbq[tid] = (tid < 64) ? bq[tid] : (tid < 128) ? bk[tid - 64] : bv[tid - 128];

    int rg = tid >> 5;
    int cg = tid & 31;
    int c0 = cg * 6;
    int u0 = cg * 2;

    #pragma unroll 1
    for (int tile = blockIdx.x; tile < GRU_NT; tile += gridDim.x) {
        size_t rowbase = (size_t)tile * 128;
        int b = (int)(rowbase >> 14);

        __syncthreads();   // previous tile's reads of sH/sX done; weights staged
        for (int i = tid; i < 8192; i += 512) {
            int r = i >> 6, c = i & 63;
            sH[r*GRU_HSTR + c] = h0[rowbase*64 + i];
        }

        #pragma unroll 1
        for (int t = 0; t < Tt; t++) {
            __syncthreads();

            sX[tid] = x[((size_t)t * BNc + rowbase) * 4 + tid];
            if (dones[t * Bb + b] != 0u) {
                for (int i = tid; i < 8192; i += 512) {
                    int r = i >> 6, c = i & 63;
                    sH[r*GRU_HSTR + c] = 0.f;
                }
            }
            __syncthreads();

            unsigned long long acc[8][3];
            #pragma unroll
            for (int i = 0; i < 8; i++) { acc[i][0] = 0ULL; acc[i][1] = 0ULL; acc[i][2] = 0ULL; }

            const float* sWrow = sWh + c0;
            #pragma unroll 1
            for (int k4 = 0; k4 < 16; k4++) {
                unsigned long long w[4][3];
                #pragma unroll
                for (int kk = 0; kk < 4; kk++) {
                    const float* wr = sWrow + (k4*4 + kk) * 192;
                    w[kk][0] = *(const unsigned long long*)(wr);
                    w[kk][1] = *(const unsigned long long*)(wr + 2);
                    w[kk][2] = *(const unsigned long long*)(wr + 4);
                }
                #pragma unroll
                for (int i = 0; i < 8; i++) {
                    float4 hv = *(const float4*)&sH[(rg + 16*i) * GRU_HSTR + k4*4];
                    unsigned long long hh0 = packdup(hv.x);
                    ffma2(acc[i][0], hh0, w[0][0]); ffma2(acc[i][1], hh0, w[0][1]); ffma2(acc[i][2], hh0, w[0][2]);
                    unsigned long long hh1 = packdup(hv.y);
                    ffma2(acc[i][0], hh1, w[1][0]); ffma2(acc[i][1], hh1, w[1][1]); ffma2(acc[i][2], hh1, w[1][2]);
                    unsigned long long hh2 = packdup(hv.z);
                    ffma2(acc[i][0], hh2, w[2][0]); ffma2(acc[i][1], hh2, w[2][1]); ffma2(acc[i][2], hh2, w[2][2]);
                    unsigned long long hh3 = packdup(hv.w);
                    ffma2(acc[i][0], hh3, w[3][0]); ffma2(acc[i][1], hh3, w[3][1]); ffma2(acc[i][2], hh3, w[3][2]);
                }
            }
            __syncthreads();

            float2 bh2 = *(const float2*)&sbhn[u0];
            #pragma unroll
            for (int i = 0; i < 8; i++) {
                int row = rg + 16*i;
                unsigned long long g0 = *(const unsigned long long*)(sbi + c0);
                unsigned long long g1 = *(const unsigned long long*)(sbi + c0 + 2);
                unsigned long long g2 = *(const unsigned long long*)(sbi + c0 + 4);
                #pragma unroll
                for (int d = 0; d < 4; d++) {
                    unsigned long long xv = packdup(sX[row*4 + d]);
                    const float* wr = sWi + d*192 + c0;
                    ffma2(g0, xv, *(const unsigned long long*)(wr));
                    ffma2(g1, xv, *(const unsigned long long*)(wr + 2));
                    ffma2(g2, xv, *(const unsigned long long*)(wr + 4));
                }
                float2 a0 = unpack2(acc[i][0]);
                float2 a1 = unpack2(acc[i][1]);
                float2 a2 = unpack2(acc[i][2]);
                float2 i0 = unpack2(g0);
                float2 i1 = unpack2(g1);
                float2 i2 = unpack2(g2);

                float2 hold = *(const float2*)&sH[row*GRU_HSTR + u0];
                float r0 = sigmoidf_(i0.x + a0.x);
                float z0 = sigmoidf_(i0.y + a0.y);
                float n0 = tanhf(i1.x + r0 * (a1.x + bh2.x));
                float h0n = (1.f - z0) * n0 + z0 * hold.x;
                float r1 = sigmoidf_(i1.y + a1.y);
                float z1 = sigmoidf_(i2.x + a2.x);
                float n1 = tanhf(i2.y + r1 * (a2.y + bh2.y));
                float h1n = (1.f - z1) * n1 + z1 * hold.y;
                *(float2*)&sH[row*GRU_HSTR + u0] = make_float2(h0n, h1n);
            }
            __syncthreads();

            {
                unsigned long long qa[8][3];
                float2 b01 = *(const float2*)&sbq[c0];
                float2 b23 = *(const float2*)&sbq[c0 + 2];
                float2 b45 = *(const float2*)&sbq[c0 + 4];
                #pragma unroll
                for (int i = 0; i < 8; i++) {
                    qa[i][0] = pack2(b01.x, b01.y);
                    qa[i][1] = pack2(b23.x, b23.y);
                    qa[i][2] = pack2(b45.x, b45.y);
                }
                const float* sQrow = sWq + c0;
                #pragma unroll 1
                for (int k4 = 0; k4 < 16; k4++) {
                    unsigned long long w[4][3];
                    #pragma unroll
                    for (int kk = 0; kk < 4; kk++) {
                        const float* wr = sQrow + (k4*4 + kk) * 192;
                        w[kk][0] = *(const unsigned long long*)(wr);
                        w[kk][1] = *(const unsigned long long*)(wr + 2);
                        w[kk][2] = *(const unsigned long long*)(wr + 4);
                    }
                    #pragma unroll
                    for (int i = 0; i < 8; i++) {
                        float4 hv = *(const float4*)&sH[(rg + 16*i) * GRU_HSTR + k4*4];
                        unsigned long long hh0 = packdup(hv.x);
                        ffma2(qa[i][0], hh0, w[0][0]); ffma2(qa[i][1], hh0, w[0][1]); ffma2(qa[i][2], hh0, w[0][2]);
                        unsigned long long hh1 = packdup(hv.y);
                        ffma2(qa[i][0], hh1, w[1][0]); ffma2(qa[i][1], hh1, w[1][1]); ffma2(qa[i][2], hh1, w[1][2]);
                        unsigned long long hh2 = packdup(hv.z);
                        ffma2(qa[i][0], hh2, w[2][0]); ffma2(qa[i][1], hh2, w[2][1]); ffma2(qa[i][2], hh2, w[2][2]);
                        unsigned long long hh3 = packdup(hv.w);
                        ffma2(qa[i][0], hh3, w[3][0]); ffma2(qa[i][1], hh3, w[3][1]); ffma2(qa[i][2], hh3, w[3][2]);
                    }
                }
                size_t orow0 = (size_t)t * BNc + rowbase;
                #pragma unroll
                for (int i = 0; i < 8; i++) {
                    unsigned long long* dst =
                        (unsigned long long*)(g_qkv + (orow0 + rg + 16*i) * H3c + c0);
                    dst[0] = qa[i][0];
                    dst[1] = qa[i][1];
                    dst[2] = qa[i][2];
                }
            }
        }

        __syncthreads();
        for (int i = tid; i < 8192; i += 512) {
            int r = i >> 6, c = i & 63;
            hfin_out[rowbase*64 + i] = sH[r*GRU_HSTR + c];
        }
    }
}

// ---------------------------------------------------------------------------
// Attention: 2 instances per warp, float2 gather (R11 form), o overlaid
// into sR's q-region (dead after logits) -> no sO buffer, 38KB smem.
// ---------------------------------------------------------------------------
#define ATT_RSTR 196
__global__ __launch_bounds__(256)
void k_attn(const int* __restrict__ indices)
{
    __shared__ __align__(16) float sR[8][2][3*ATT_RSTR];
    __shared__ int sIdx[8][2][3];

    int warp = threadIdx.x >> 5, lane = threadIdx.x & 31;
    int ip = blockIdx.x * 16 + warp * 2;      // instance pair base
    int tb0 = ip >> 14;                       // pair never crosses tb boundary
    int f0  = ip & 16383;

    if (lane < 6) {
        int i = lane / 3, k = lane % 3;
        sIdx[warp][i][k] = __ldg(&indices[(f0 + i)*3 + k]);
    }
    __syncwarp();

    // Gather 6 rows (2 inst x 3 slots), float2
    #pragma unroll
    for (int i = 0; i < 2; i++) {
        const float* base = g_qkv + (size_t)tb0 * Nn * H3c;
        #pragma unroll
        for (int k = 0; k < 3; k++) {
            const float2* src = (const float2*)(base + (size_t)sIdx[warp][i][k] * H3c);
            float2* dst = (float2*)&sR[warp][i][k*ATT_RSTR];
            #pragma unroll
            for (int it = 0; it < 3; it++)
                dst[it*32 + lane] = src[it*32 + lane];
        }
    }
    __syncwarp();

    // Compute: 24 lanes = 2 inst x 12 (qr,head); write o into q-region
    if (lane < 24) {
        int i = lane / 12, w12 = lane % 12;
        int qr = w12 >> 2, hh = w12 & 3;
        float* R = sR[warp][i];
        const float* q = R + qr*ATT_RSTR + hh*16;
        float l[3];
        #pragma unroll
        for (int kr = 0; kr < 3; kr++) {
            const float* kv = R + kr*ATT_RSTR + 64 + hh*16;
            float s = 0.f;
            #pragma unroll
            for (int d = 0; d < 16; d++) s += q[d] * kv[d];
            l[kr] = s * 0.25f;
        }
        float m = fmaxf(l[0], fmaxf(l[1], l[2]));
        float e0 = __expf(l[0] - m), e1 = __expf(l[1] - m), e2 = __expf(l[2] - m);
        float inv = 1.f / (e0 + e1 + e2);
        e0 *= inv; e1 *= inv; e2 *= inv;
        const float* v0 = R + 0*ATT_RSTR + 128 + hh*16;
        const float* v1 = R + 1*ATT_RSTR + 128 + hh*16;
        const float* v2 = R + 2*ATT_RSTR + 128 + hh*16;
        float* o = R + qr*ATT_RSTR + hh*16;       // overwrite q slice (dead)
        #pragma unroll
        for (int d = 0; d < 16; d++)
            o[d] = e0 * v0[d] + e1 * v1[d] + e2 * v2[d];
    }
    __syncwarp();

    // Scatter: 32 lanes = 2 inst x 16 float4-columns (o lives in q-region)
    {
        int i = lane >> 4, l = lane & 15;
        float4* yo = (float4*)g_yo + (size_t)tb0 * Nn * 16;
        #pragma unroll
        for (int k = 0; k < 3; k++) {
            float4 v = *(const float4*)&sR[warp][i][k*ATT_RSTR + l*4];
            atomicAdd(&yo[(size_t)sIdx[warp][i][k] * 16 + l], v);
        }
    }
}

// ---------------------------------------------------------------------------
// Logit head + fused value-head segment sums (unchanged from R12, passing).
// ---------------------------------------------------------------------------
__global__ __launch_bounds__(256, 2)
void k_post(const float* __restrict__ nnz,
            const float* __restrict__ W2, const float* __restrict__ b2,
            float* __restrict__ logit_out)
{
    extern __shared__ float ps[];
    float4* sT4 = (float4*)ps;                 // 256 rows x 17 float4 (pad)
    float*  sM  = ps + 256*17*4;               // 4096
    float*  sc1 = sM + 4096;                   // 64
    float*  sE  = sc1 + 64;                    // 64
    float*  sW2 = sE + 64;                     // 64
    float*  sRed = sW2 + 64;                   // 4*64 = 256
    float*  sR0  = sRed + 256;                 // 8

    int tid = threadIdx.x;
    int rowbase = blockIdx.x * 256;
    int g = rowbase >> 12;

    const float4* yo4 = (const float4*)g_yo + (size_t)rowbase * 16;
    for (int i = tid; i < 4096; i += 256)
        sT4[(i >> 4) * 17 + (i & 15)] = yo4[i];
    for (int i = tid; i < 4096; i += 256) sM[i] = g_M[i];
    if (tid < 64) { sc1[tid] = g_c1[tid]; sE[tid] = g_E[g*64 + tid]; sW2[tid] = W2[tid]; }
    __syncthreads();

    int row = rowbase + tid;
    int n = row & 16383;
    float inv = 1.f / nnz[n];
    float cninv = (float)g_cnt[n] * inv;

    float yo[64];
    #pragma unroll
    for (int jj = 0; jj < 16; jj++) {
        float4 v = sT4[tid * 17 + jj];
        yo[4*jj] = v.x; yo[4*jj+1] = v.y; yo[4*jj+2] = v.z; yo[4*jj+3] = v.w;
    }

    const ulonglong2* sM2 = (const ulonglong2*)sM;
    float logit = 0.f;
    #pragma unroll 1
    for (int p = 0; p < 8; p++) {
        unsigned long long acc[4] = {0ULL, 0ULL, 0ULL, 0ULL};
        #pragma unroll
        for (int j = 0; j < 64; j++) {
            unsigned long long y2 = packdup(yo[j]);
            ulonglong2 w0 = sM2[j*16 + p*2];
            ulonglong2 w1 = sM2[j*16 + p*2 + 1];
            ffma2(acc[0], y2, w0.x);
            ffma2(acc[1], y2, w0.y);
            ffma2(acc[2], y2, w1.x);
            ffma2(acc[3], y2, w1.y);
        }
        #pragma unroll
        for (int q = 0; q < 4; q++) {
            float2 v = unpack2(acc[q]);
            int c = p*8 + q*2;
            float pre, rr;
            pre = inv*v.x + cninv*sc1[c]   + sE[c];   rr = fmaxf(pre, 0.f); logit += rr*sW2[c];
            pre = inv*v.y + cninv*sc1[c+1] + sE[c+1]; rr = fmaxf(pre, 0.f); logit += rr*sW2[c+1];
        }
    }
    logit_out[row] = logit + b2[0];

    // ---- fused value-head partial sums ----
    __syncthreads();
    #pragma unroll
    for (int jj = 0; jj < 16; jj++) {
        sT4[tid * 17 + jj] = make_float4(yo[4*jj]*inv, yo[4*jj+1]*inv,
                                         yo[4*jj+2]*inv, yo[4*jj+3]*inv);
    }
    __syncthreads();
    {
        int col = tid & 63, part = tid >> 6;
        const float* sS = ps;
        float s = 0.f;
        #pragma unroll 4
        for (int r = part*64; r < part*64 + 64; r++)
            s += sS[r*68 + col];
        sRed[part*64 + col] = s;
    }
    {
        float v = cninv;
        #pragma unroll
        for (int off = 16; off; off >>= 1) v += __shfl_xor_sync(0xffffffffu, v, off);
        if ((tid & 31) == 0) sR0[tid >> 5] = v;
    }
    __syncthreads();
    if (tid < 64)
        atomicAdd(&g_s1[g*64 + tid], sRed[tid] + sRed[64 + tid] + sRed[128 + tid] + sRed[192 + tid]);
    if (tid == 0) {
        float s0 = 0.f;
        #pragma unroll
        for (int w = 0; w < 8; w++) s0 += sR0[w];
        atomicAdd(&g_s0[g], s0);
    }
}

// ---------------------------------------------------------------------------
__global__ void k_value(const float* __restrict__ extra,
                        const float* __restrict__ Wv1, const float* __restrict__ bv1,
                        float* __restrict__ val_out)
{
    __shared__ float sv[64];
    int tid = threadIdx.x;                  // 64 = (tb,kall)
    float acc = 0.f;
    #pragma unroll
    for (int j = 0; j < 64; j++) acc += g_s1[tid*64 + j] * g_wv[j];
    acc += g_s0[tid] * g_bv[0];
    acc *= (1.f / (float)N0c);
    #pragma unroll
    for (int d = 0; d < 4; d++) acc += extra[tid*4 + d] * Wv1[64 + d];
    acc += bv1[0];
    sv[tid] = acc;
    __syncthreads();
    if (tid < 16)
        val_out[tid] = sv[tid*4] + sv[tid*4+1] + sv[tid*4+2] + sv[tid*4+3];
}

// ---------------------------------------------------------------------------
extern "C" void kernel_launch(void* const* d_in, const int* in_sizes, int n_in,
                              void* d_out, int out_size)
{
    const float* h0       = (const float*)d_in[0];
    const float* h_global = (const float*)d_in[1];
    const float* x        = (const float*)d_in[2];
    const float* extra    = (const float*)d_in[3];
    const uint32_t* dones = (const uint32_t*)d_in[4];
    const int*   indices  = (const int*)d_in[5];
    const float* nnz      = (const float*)d_in[6];
    const float* Wi  = (const float*)d_in[7];
    const float* bi  = (const float*)d_in[8];
    const float* Wh  = (const float*)d_in[9];
    const float* bhn = (const float*)d_in[10];
    const float* Wq  = (const float*)d_in[11];
    const float* bq  = (const float*)d_in[12];
    const float* Wk  = (const float*)d_in[13];
    const float* bk  = (const float*)d_in[14];
    const float* Wv  = (const float*)d_in[15];
    const float* bv  = (const float*)d_in[16];
    const float* Wo  = (const float*)d_in[17];
    const float* bo  = (const float*)d_in[18];
    const float* W1  = (const float*)d_in[19];
    const float* b1  = (const float*)d_in[20];
    const float* W2  = (const float*)d_in[21];
    const float* b2  = (const float*)d_in[22];
    const float* Wv1 = (const float*)d_in[23];
    const float* bv1 = (const float*)d_in[24];

    float* out       = (float*)d_out;
    float* out_hfin  = out;
    float* out_hg    = out + OFF_HG;
    float* out_logit = out + OFF_LOGIT;
    float* out_val   = out + OFF_VAL;

    void *yo_ptr, *cnt_ptr, *s1_ptr, *s0_ptr;
    cudaGetSymbolAddress(&yo_ptr,  g_yo);
    cudaGetSymbolAddress(&cnt_ptr, g_cnt);
    cudaGetSymbolAddress(&s1_ptr,  g_s1);
    cudaGetSymbolAddress(&s0_ptr,  g_s0);
    cudaMemsetAsync(yo_ptr,  0, sizeof(float) * (size_t)TBNc * Hh, 0);
    cudaMemsetAsync(cnt_ptr, 0, sizeof(int) * Nn, 0);
    cudaMemsetAsync(s1_ptr,  0, sizeof(float) * 64 * 64, 0);
    cudaMemsetAsync(s0_ptr,  0, sizeof(float) * 64, 0);

    cudaMemcpyAsync(out_hg, h_global, 1024 * sizeof(float), cudaMemcpyDeviceToDevice, 0);

    int smem_gru  = GRU_SM_TOT * 4;                                // 140032 B
    cudaFuncSetAttribute(k_gru_qkv, cudaFuncAttributeMaxDynamicSharedMemorySize, smem_gru);
    int smem_post = (256*17*4 + 4096 + 64 + 64 + 64 + 256 + 8) * 4; // 88112 B
    cudaFuncSetAttribute(k_post, cudaFuncAttributeMaxDynamicSharedMemorySize, smem_post);

    k_count<<<(Ff * ORD + 255) / 256, 256>>>(indices);
    k_prep<<<32, 256>>>(Wo, bo, W1, b1, Wv1, extra);
    k_gru_qkv<<<148, 512, smem_gru>>>(h0, x, dones, Wi, bi, Wh, bhn,
                                      Wq, bq, Wk, bk, Wv, bv, out_hfin);
    k_attn<<<TBc * Ff / 16, 256>>>(indices);
    k_post<<<TBNc / 256, 256, smem_post>>>(nnz, W2, b2, out_logit);
    k_value<<<1, 64>>>(extra, Wv1, bv1, out_val);
}

// round 14
// speedup vs baseline: 1.8373x; 1.0059x over previous
#include <cuda_runtime.h>
#include <math.h>
#include <stdint.h>

// Problem constants
#define Tt   4
#define Bb   4
#define Nn   16384
#define KALLc 4
#define Ff   16384
#define ORD  3
#define Hh   64
#define N0c  4096

#define TBc  (Tt*Bb)        // 16
#define BNc  (Bb*Nn)        // 65536
#define TBNc (TBc*Nn)       // 262144
#define H3c  (3*Hh)         // 192

// Output layout: h_fin [B,N,H] | h_global [B,K,64] | logit [T,B,N] | value [T,B]
#define OFF_HG    4194304
#define OFF_LOGIT (OFF_HG + 1024)
#define OFF_VAL   (OFF_LOGIT + 262144)

// Scratch
__device__ float g_qkv[TBNc * H3c];   // [T,B,N,192]
__device__ float g_yo [TBNc * Hh];    // [T,B,N,64]
__device__ int   g_cnt[Nn];
__device__ float g_M  [64*64];        // Wo @ W1[:64]
__device__ float g_c1 [64];           // bo @ W1[:64]
__device__ float g_E  [64*64];        // per (tb,kall): b1 + extra@W1[64:]
__device__ float g_wv [64];           // Wo @ Wv1[:64]
__device__ float g_bv [1];            // bo @ Wv1[:64]
__device__ float g_s1 [64*64];        // per (tb,kall): sum_n yo*invnnz
__device__ float g_s0 [64];           // per (tb,kall): sum_n cnt*invnnz

__device__ __forceinline__ float sigmoidf_(float v) { return 1.f / (1.f + expf(-v)); }

// ---- packed fp32 helpers (fma.rn.f32x2) ----
__device__ __forceinline__ unsigned long long packdup(float v) {
    unsigned long long r;
    asm("mov.b64 %0, {%1, %1};" : "=l"(r) : "f"(v));
    return r;
}
__device__ __forceinline__ unsigned long long pack2(float a, float b) {
    unsigned long long r;
    asm("mov.b64 %0, {%1, %2};" : "=l"(r) : "f"(a), "f"(b));
    return r;
}
__device__ __forceinline__ void ffma2(unsigned long long& acc,
                                      unsigned long long a, unsigned long long b) {
    asm("fma.rn.f32x2 %0, %1, %2, %0;" : "+l"(acc) : "l"(a), "l"(b));
}
__device__ __forceinline__ float2 unpack2(unsigned long long v) {
    float lo, hi;
    asm("mov.b64 {%0, %1}, %2;" : "=f"(lo), "=f"(hi) : "l"(v));
    return make_float2(lo, hi);
}

// ---------------------------------------------------------------------------
__global__ void k_count(const int* __restrict__ indices) {
    int i = blockIdx.x * 256 + threadIdx.x;
    if (i < Ff * ORD) atomicAdd(&g_cnt[indices[i]], 1);
}

// ---------------------------------------------------------------------------
__global__ void k_prep(const float* __restrict__ Wo, const float* __restrict__ bo,
                       const float* __restrict__ W1, const float* __restrict__ b1,
                       const float* __restrict__ Wv1,
                       const float* __restrict__ extra)
{
    int o = blockIdx.x * 256 + threadIdx.x;   // grid 32 x 256 = 8192
    if (o < 4096) {
        int j = o >> 6, c = o & 63;
        float s = 0.f;
        #pragma unroll
        for (int h = 0; h < 64; h++) s += Wo[j*64 + h] * W1[h*64 + c];
        g_M[o] = s;
    } else {
        int e = o - 4096;
        int g = e >> 6, c = e & 63;
        float s = b1[c];
        #pragma unroll
        for (int d = 0; d < 4; d++) s += extra[g*4 + d] * W1[(64 + d)*64 + c];
        g_E[e] = s;
    }
    if (blockIdx.x == 0 && threadIdx.x < 64) {
        int tid = threadIdx.x;
        float s = 0.f, w = 0.f;
        #pragma unroll
        for (int h = 0; h < 64; h++) {
            s += bo[h] * W1[h*64 + tid];
            w += Wo[tid*64 + h] * Wv1[h];
        }
        g_c1[tid] = s;
        g_wv[tid] = w;
        if (tid == 0) {
            float bvv = 0.f;
            #pragma unroll
            for (int h = 0; h < 64; h++) bvv += bo[h] * Wv1[h];
            g_bv[0] = bvv;
        }
    }
}

// ---------------------------------------------------------------------------
// Fused GRU scan + QKV projection, PERSISTENT (unchanged from R13, passing).
// ---------------------------------------------------------------------------
#define GRU_HSTR     68
#define GRU_OFF_WI   12288
#define GRU_OFF_BI   (GRU_OFF_WI + 768)       // 13056
#define GRU_OFF_BHN  (GRU_OFF_BI + 192)       // 13248
#define GRU_OFF_WQ   (GRU_OFF_BHN + 64)       // 13312
#define GRU_OFF_BQ   (GRU_OFF_WQ + 12288)     // 25600
#define GRU_OFF_X    (GRU_OFF_BQ + 192)       // 25792
#define GRU_OFF_H    (GRU_OFF_X + 512)        // 26304
#define GRU_SM_TOT   (GRU_OFF_H + 128*GRU_HSTR) // 35008 floats = 140032 B
#define GRU_NT       512                       // 65536/128 tiles

__global__ __launch_bounds__(512)
void k_gru_qkv(const float* __restrict__ h0, const float* __restrict__ x,
               const uint32_t* __restrict__ dones,
               const float* __restrict__ Wi, const float* __restrict__ bi,
               const float* __restrict__ Wh, const float* __restrict__ bhn,
               const float* __restrict__ Wq, const float* __restrict__ bq,
               const float* __restrict__ Wk, const float* __restrict__ bk,
               const float* __restrict__ Wv, const float* __restrict__ bv,
               float* __restrict__ hfin_out)
{
    extern __shared__ float gs[];
    float* sWh   = gs;                    // reordered: [k][3c+g]
    float* sWi   = gs + GRU_OFF_WI;       // reordered
    float* sbi   = gs + GRU_OFF_BI;       // reordered
    float* sbhn  = gs + GRU_OFF_BHN;      // natural unit order
    float* sWq   = gs + GRU_OFF_WQ;       // [k][q|k|v 192]
    float* sbq   = gs + GRU_OFF_BQ;
    float* sX    = gs + GRU_OFF_X;
    float* sH    = gs + GRU_OFF_H;

    int tid = threadIdx.x;

    // Stage weights ONCE per block
    for (int i = tid; i < 12288; i += 512) {
        int k = i / 192, e = i % 192;
        int c = e / 3, g = e % 3;
        sWh[i] = Wh[k*192 + g*64 + c];
    }
    for (int i = tid; i < 768; i += 512) {
        int k = i / 192, e = i % 192;
        int c = e / 3, g = e % 3;
        sWi[i] = Wi[k*192 + g*64 + c];
    }
    if (tid < 192) {
        int c = tid / 3, g = tid % 3;
        sbi[tid] = bi[g*64 + c];
    }
    if (tid < 64) sbhn[tid] = bhn[tid];
    for (int i = tid; i < 12288; i += 512) {
        int k = i / 192, e = i % 192;
        sWq[i] = (e < 64) ? Wq[k*64 + e] : (e < 128) ? Wk[k*64 + e - 64] : Wv[k*64 + e - 128];
    }
    if (tid < 192)
        sbq[tid] = (tid < 64) ? bq[tid] : (tid < 128) ? bk[tid - 64] : bv[tid - 128];

    int rg = tid >> 5;
    int cg = tid & 31;
    int c0 = cg * 6;
    int u0 = cg * 2;

    #pragma unroll 1
    for (int tile = blockIdx.x; tile < GRU_NT; tile += gridDim.x) {
        size_t rowbase = (size_t)tile * 128;
        int b = (int)(rowbase >> 14);

        __syncthreads();
        for (int i = tid; i < 8192; i += 512) {
            int r = i >> 6, c = i & 63;
            sH[r*GRU_HSTR + c] = h0[rowbase*64 + i];
        }

        #pragma unroll 1
        for (int t = 0; t < Tt; t++) {
            __syncthreads();

            sX[tid] = x[((size_t)t * BNc + rowbase) * 4 + tid];
            if (dones[t * Bb + b] != 0u) {
                for (int i = tid; i < 8192; i += 512) {
                    int r = i >> 6, c = i & 63;
                    sH[r*GRU_HSTR + c] = 0.f;
                }
            }
            __syncthreads();

            unsigned long long acc[8][3];
            #pragma unroll
            for (int i = 0; i < 8; i++) { acc[i][0] = 0ULL; acc[i][1] = 0ULL; acc[i][2] = 0ULL; }

            const float* sWrow = sWh + c0;
            #pragma unroll 1
            for (int k4 = 0; k4 < 16; k4++) {
                unsigned long long w[4][3];
                #pragma unroll
                for (int kk = 0; kk < 4; kk++) {
                    const float* wr = sWrow + (k4*4 + kk) * 192;
                    w[kk][0] = *(const unsigned long long*)(wr);
                    w[kk][1] = *(const unsigned long long*)(wr + 2);
                    w[kk][2] = *(const unsigned long long*)(wr + 4);
                }
                #pragma unroll
                for (int i = 0; i < 8; i++) {
                    float4 hv = *(const float4*)&sH[(rg + 16*i) * GRU_HSTR + k4*4];
                    unsigned long long hh0 = packdup(hv.x);
                    ffma2(acc[i][0], hh0, w[0][0]); ffma2(acc[i][1], hh0, w[0][1]); ffma2(acc[i][2], hh0, w[0][2]);
                    unsigned long long hh1 = packdup(hv.y);
                    ffma2(acc[i][0], hh1, w[1][0]); ffma2(acc[i][1], hh1, w[1][1]); ffma2(acc[i][2], hh1, w[1][2]);
                    unsigned long long hh2 = packdup(hv.z);
                    ffma2(acc[i][0], hh2, w[2][0]); ffma2(acc[i][1], hh2, w[2][1]); ffma2(acc[i][2], hh2, w[2][2]);
                    unsigned long long hh3 = packdup(hv.w);
                    ffma2(acc[i][0], hh3, w[3][0]); ffma2(acc[i][1], hh3, w[3][1]); ffma2(acc[i][2], hh3, w[3][2]);
                }
            }
            __syncthreads();

            float2 bh2 = *(const float2*)&sbhn[u0];
            #pragma unroll
            for (int i = 0; i < 8; i++) {
                int row = rg + 16*i;
                unsigned long long g0 = *(const unsigned long long*)(sbi + c0);
                unsigned long long g1 = *(const unsigned long long*)(sbi + c0 + 2);
                unsigned long long g2 = *(const unsigned long long*)(sbi + c0 + 4);
                #pragma unroll
                for (int d = 0; d < 4; d++) {
                    unsigned long long xv = packdup(sX[row*4 + d]);
                    const float* wr = sWi + d*192 + c0;
                    ffma2(g0, xv, *(const unsigned long long*)(wr));
                    ffma2(g1, xv, *(const unsigned long long*)(wr + 2));
                    ffma2(g2, xv, *(const unsigned long long*)(wr + 4));
                }
                float2 a0 = unpack2(acc[i][0]);
                float2 a1 = unpack2(acc[i][1]);
                float2 a2 = unpack2(acc[i][2]);
                float2 i0 = unpack2(g0);
                float2 i1 = unpack2(g1);
                float2 i2 = unpack2(g2);

                float2 hold = *(const float2*)&sH[row*GRU_HSTR + u0];
                float r0 = sigmoidf_(i0.x + a0.x);
                float z0 = sigmoidf_(i0.y + a0.y);
                float n0 = tanhf(i1.x + r0 * (a1.x + bh2.x));
                float h0n = (1.f - z0) * n0 + z0 * hold.x;
                float r1 = sigmoidf_(i1.y + a1.y);
                float z1 = sigmoidf_(i2.x + a2.x);
                float n1 = tanhf(i2.y + r1 * (a2.y + bh2.y));
                float h1n = (1.f - z1) * n1 + z1 * hold.y;
                *(float2*)&sH[row*GRU_HSTR + u0] = make_float2(h0n, h1n);
            }
            __syncthreads();

            {
                unsigned long long qa[8][3];
                float2 b01 = *(const float2*)&sbq[c0];
                float2 b23 = *(const float2*)&sbq[c0 + 2];
                float2 b45 = *(const float2*)&sbq[c0 + 4];
                #pragma unroll
                for (int i = 0; i < 8; i++) {
                    qa[i][0] = pack2(b01.x, b01.y);
                    qa[i][1] = pack2(b23.x, b23.y);
                    qa[i][2] = pack2(b45.x, b45.y);
                }
                const float* sQrow = sWq + c0;
                #pragma unroll 1
                for (int k4 = 0; k4 < 16; k4++) {
                    unsigned long long w[4][3];
                    #pragma unroll
                    for (int kk = 0; kk < 4; kk++) {
                        const float* wr = sQrow + (k4*4 + kk) * 192;
                        w[kk][0] = *(const unsigned long long*)(wr);
                        w[kk][1] = *(const unsigned long long*)(wr + 2);
                        w[kk][2] = *(const unsigned long long*)(wr + 4);
                    }
                    #pragma unroll
                    for (int i = 0; i < 8; i++) {
                        float4 hv = *(const float4*)&sH[(rg + 16*i) * GRU_HSTR + k4*4];
                        unsigned long long hh0 = packdup(hv.x);
                        ffma2(qa[i][0], hh0, w[0][0]); ffma2(qa[i][1], hh0, w[0][1]); ffma2(qa[i][2], hh0, w[0][2]);
                        unsigned long long hh1 = packdup(hv.y);
                        ffma2(qa[i][0], hh1, w[1][0]); ffma2(qa[i][1], hh1, w[1][1]); ffma2(qa[i][2], hh1, w[1][2]);
                        unsigned long long hh2 = packdup(hv.z);
                        ffma2(qa[i][0], hh2, w[2][0]); ffma2(qa[i][1], hh2, w[2][1]); ffma2(qa[i][2], hh2, w[2][2]);
                        unsigned long long hh3 = packdup(hv.w);
                        ffma2(qa[i][0], hh3, w[3][0]); ffma2(qa[i][1], hh3, w[3][1]); ffma2(qa[i][2], hh3, w[3][2]);
                    }
                }
                size_t orow0 = (size_t)t * BNc + rowbase;
                #pragma unroll
                for (int i = 0; i < 8; i++) {
                    unsigned long long* dst =
                        (unsigned long long*)(g_qkv + (orow0 + rg + 16*i) * H3c + c0);
                    dst[0] = qa[i][0];
                    dst[1] = qa[i][1];
                    dst[2] = qa[i][2];
                }
            }
        }

        __syncthreads();
        for (int i = tid; i < 8192; i += 512) {
            int r = i >> 6, c = i & 63;
            hfin_out[rowbase*64 + i] = sH[r*GRU_HSTR + c];
        }
    }
}

// ---------------------------------------------------------------------------
// Attention v3: 4 instances per warp (12 rows), vectorized compute.
// Compute lanes = (head hh, instance i), lane = hh*4+i: conflict-free LDS.128
// (offsets mod 32 = {0,12,24,4} + {0,16}). k in registers, q/v streamed as
// float4. o overwrites dead q slices. Scatter full-warp float4 atomics.
// ---------------------------------------------------------------------------
#define ATT_RSTR 196    // floats per row (196*4B=784B, 16B-aligned)
#define ATT_SM   (8 * 12 * ATT_RSTR * 4)    // 75264 B dynamic

__global__ __launch_bounds__(256)
void k_attn(const int* __restrict__ indices)
{
    extern __shared__ __align__(16) float as_[];
    __shared__ int sIdx[8][12];

    int warp = threadIdx.x >> 5, lane = threadIdx.x & 31;
    float* R0 = as_ + warp * 12 * ATT_RSTR;

    int ip = blockIdx.x * 32 + warp * 4;      // 4 consecutive instances
    int tb = ip >> 14;                        // never crosses tb within warp
    int f0 = ip & 16383;

    if (lane < 12) sIdx[warp][lane] = __ldg(&indices[f0*3 + lane]);
    __syncwarp();

    // Gather 12 rows x 192 floats (48 float4): lane + predicated lane+32
    const float* base = g_qkv + (size_t)tb * Nn * H3c;
    #pragma unroll
    for (int r = 0; r < 12; r++) {
        const float4* src = (const float4*)(base + (size_t)sIdx[warp][r] * H3c);
        float4* dst = (float4*)(R0 + r * ATT_RSTR);
        dst[lane] = src[lane];
        if (lane < 16) dst[32 + lane] = src[32 + lane];
    }
    __syncwarp();

    // Compute: 16 lanes, lane = hh*4 + i
    if (lane < 16) {
        int i = lane & 3, hh = lane >> 2;
        float* R = R0 + i * 3 * ATT_RSTR;
        int ho = hh * 16;

        float kreg[3][16];
        #pragma unroll
        for (int kr = 0; kr < 3; kr++) {
            #pragma unroll
            for (int d4 = 0; d4 < 4; d4++) {
                float4 v = *(const float4*)(R + kr*ATT_RSTR + 64 + ho + d4*4);
                kreg[kr][d4*4+0] = v.x; kreg[kr][d4*4+1] = v.y;
                kreg[kr][d4*4+2] = v.z; kreg[kr][d4*4+3] = v.w;
            }
        }

        #pragma unroll
        for (int qr = 0; qr < 3; qr++) {
            float q[16];
            #pragma unroll
            for (int d4 = 0; d4 < 4; d4++) {
                float4 v = *(const float4*)(R + qr*ATT_RSTR + ho + d4*4);
                q[d4*4+0] = v.x; q[d4*4+1] = v.y; q[d4*4+2] = v.z; q[d4*4+3] = v.w;
            }
            float l[3];
            #pragma unroll
            for (int kr = 0; kr < 3; kr++) {
                float s = 0.f;
                #pragma unroll
                for (int d = 0; d < 16; d++) s += q[d] * kreg[kr][d];
                l[kr] = s * 0.25f;
            }
            float m = fmaxf(l[0], fmaxf(l[1], l[2]));
            float e0 = __expf(l[0] - m), e1 = __expf(l[1] - m), e2 = __expf(l[2] - m);
            float inv = 1.f / (e0 + e1 + e2);
            e0 *= inv; e1 *= inv; e2 *= inv;

            float o[16];
            #pragma unroll
            for (int d4 = 0; d4 < 4; d4++) {
                float4 v0 = *(const float4*)(R + 0*ATT_RSTR + 128 + ho + d4*4);
                float4 v1 = *(const float4*)(R + 1*ATT_RSTR + 128 + ho + d4*4);
                float4 v2 = *(const float4*)(R + 2*ATT_RSTR + 128 + ho + d4*4);
                o[d4*4+0] = e0*v0.x + e1*v1.x + e2*v2.x;
                o[d4*4+1] = e0*v0.y + e1*v1.y + e2*v2.y;
                o[d4*4+2] = e0*v0.z + e1*v1.z + e2*v2.z;
                o[d4*4+3] = e0*v0.w + e1*v1.w + e2*v2.w;
            }
            // overwrite dead q slice with o
            #pragma unroll
            for (int d4 = 0; d4 < 4; d4++)
                *(float4*)(R + qr*ATT_RSTR + ho + d4*4) =
                    make_float4(o[d4*4+0], o[d4*4+1], o[d4*4+2], o[d4*4+3]);
        }
    }
    __syncwarp();

    // Scatter: 12 rows x 16 float4 cols; lane = (rowhalf, col)
    {
        int rhalf = lane >> 4, col = lane & 15;
        float4* yo = (float4*)g_yo + (size_t)tb * Nn * 16;
        #pragma unroll
        for (int it = 0; it < 6; it++) {
            int r = it*2 + rhalf;
            float4 v = *(const float4*)(R0 + r*ATT_RSTR + col*4);
            atomicAdd(&yo[(size_t)sIdx[warp][r] * 16 + col], v);
        }
    }
}

// ---------------------------------------------------------------------------
// Logit head + fused value-head segment sums (unchanged, passing).
// ---------------------------------------------------------------------------
__global__ __launch_bounds__(256, 2)
void k_post(const float* __restrict__ nnz,
            const float* __restrict__ W2, const float* __restrict__ b2,
            float* __restrict__ logit_out)
{
    extern __shared__ float ps[];
    float4* sT4 = (float4*)ps;                 // 256 rows x 17 float4 (pad)
    float*  sM  = ps + 256*17*4;               // 4096
    float*  sc1 = sM + 4096;                   // 64
    float*  sE  = sc1 + 64;                    // 64
    float*  sW2 = sE + 64;                     // 64
    float*  sRed = sW2 + 64;                   // 4*64 = 256
    float*  sR0  = sRed + 256;                 // 8

    int tid = threadIdx.x;
    int rowbase = blockIdx.x * 256;
    int g = rowbase >> 12;

    const float4* yo4 = (const float4*)g_yo + (size_t)rowbase * 16;
    for (int i = tid; i < 4096; i += 256)
        sT4[(i >> 4) * 17 + (i & 15)] = yo4[i];
    for (int i = tid; i < 4096; i += 256) sM[i] = g_M[i];
    if (tid < 64) { sc1[tid] = g_c1[tid]; sE[tid] = g_E[g*64 + tid]; sW2[tid] = W2[tid]; }
    __syncthreads();

    int row = rowbase + tid;
    int n = row & 16383;
    float inv = 1.f / nnz[n];
    float cninv = (float)g_cnt[n] * inv;

    float yo[64];
    #pragma unroll
    for (int jj = 0; jj < 16; jj++) {
        float4 v = sT4[tid * 17 + jj];
        yo[4*jj] = v.x; yo[4*jj+1] = v.y; yo[4*jj+2] = v.z; yo[4*jj+3] = v.w;
    }

    const ulonglong2* sM2 = (const ulonglong2*)sM;
    float logit = 0.f;
    #pragma unroll 1
    for (int p = 0; p < 8; p++) {
        unsigned long long acc[4] = {0ULL, 0ULL, 0ULL, 0ULL};
        #pragma unroll
        for (int j = 0; j < 64; j++) {
            unsigned long long y2 = packdup(yo[j]);
            ulonglong2 w0 = sM2[j*16 + p*2];
            ulonglong2 w1 = sM2[j*16 + p*2 + 1];
            ffma2(acc[0], y2, w0.x);
            ffma2(acc[1], y2, w0.y);
            ffma2(acc[2], y2, w1.x);
            ffma2(acc[3], y2, w1.y);
        }
        #pragma unroll
        for (int q = 0; q < 4; q++) {
            float2 v = unpack2(acc[q]);
            int c = p*8 + q*2;
            float pre, rr;
            pre = inv*v.x + cninv*sc1[c]   + sE[c];   rr = fmaxf(pre, 0.f); logit += rr*sW2[c];
            pre = inv*v.y + cninv*sc1[c+1] + sE[c+1]; rr = fmaxf(pre, 0.f); logit += rr*sW2[c+1];
        }
    }
    logit_out[row] = logit + b2[0];

    // ---- fused value-head partial sums ----
    __syncthreads();
    #pragma unroll
    for (int jj = 0; jj < 16; jj++) {
        sT4[tid * 17 + jj] = make_float4(yo[4*jj]*inv, yo[4*jj+1]*inv,
                                         yo[4*jj+2]*inv, yo[4*jj+3]*inv);
    }
    __syncthreads();
    {
        int col = tid & 63, part = tid >> 6;
        const float* sS = ps;
        float s = 0.f;
        #pragma unroll 4
        for (int r = part*64; r < part*64 + 64; r++)
            s += sS[r*68 + col];
        sRed[part*64 + col] = s;
    }
    {
        float v = cninv;
        #pragma unroll
        for (int off = 16; off; off >>= 1) v += __shfl_xor_sync(0xffffffffu, v, off);
        if ((tid & 31) == 0) sR0[tid >> 5] = v;
    }
    __syncthreads();
    if (tid < 64)
        atomicAdd(&g_s1[g*64 + tid], sRed[tid] + sRed[64 + tid] + sRed[128 + tid] + sRed[192 + tid]);
    if (tid == 0) {
        float s0 = 0.f;
        #pragma unroll
        for (int w = 0; w < 8; w++) s0 += sR0[w];
        atomicAdd(&g_s0[g], s0);
    }
}

// ---------------------------------------------------------------------------
__global__ void k_value(const float* __restrict__ extra,
                        const float* __restrict__ Wv1, const float* __restrict__ bv1,
                        float* __restrict__ val_out)
{
    __shared__ float sv[64];
    int tid = threadIdx.x;                  // 64 = (tb,kall)
    float acc = 0.f;
    #pragma unroll
    for (int j = 0; j < 64; j++) acc += g_s1[tid*64 + j] * g_wv[j];
    acc += g_s0[tid] * g_bv[0];
    acc *= (1.f / (float)N0c);
    #pragma unroll
    for (int d = 0; d < 4; d++) acc += extra[tid*4 + d] * Wv1[64 + d];
    acc += bv1[0];
    sv[tid] = acc;
    __syncthreads();
    if (tid < 16)
        val_out[tid] = sv[tid*4] + sv[tid*4+1] + sv[tid*4+2] + sv[tid*4+3];
}

// ---------------------------------------------------------------------------
extern "C" void kernel_launch(void* const* d_in, const int* in_sizes, int n_in,
                              void* d_out, int out_size)
{
    const float* h0       = (const float*)d_in[0];
    const float* h_global = (const float*)d_in[1];
    const float* x        = (const float*)d_in[2];
    const float* extra    = (const float*)d_in[3];
    const uint32_t* dones = (const uint32_t*)d_in[4];
    const int*   indices  = (const int*)d_in[5];
    const float* nnz      = (const float*)d_in[6];
    const float* Wi  = (const float*)d_in[7];
    const float* bi  = (const float*)d_in[8];
    const float* Wh  = (const float*)d_in[9];
    const float* bhn = (const float*)d_in[10];
    const float* Wq  = (const float*)d_in[11];
    const float* bq  = (const float*)d_in[12];
    const float* Wk  = (const float*)d_in[13];
    const float* bk  = (const float*)d_in[14];
    const float* Wv  = (const float*)d_in[15];
    const float* bv  = (const float*)d_in[16];
    const float* Wo  = (const float*)d_in[17];
    const float* bo  = (const float*)d_in[18];
    const float* W1  = (const float*)d_in[19];
    const float* b1  = (const float*)d_in[20];
    const float* W2  = (const float*)d_in[21];
    const float* b2  = (const float*)d_in[22];
    const float* Wv1 = (const float*)d_in[23];
    const float* bv1 = (const float*)d_in[24];

    float* out       = (float*)d_out;
    float* out_hfin  = out;
    float* out_hg    = out + OFF_HG;
    float* out_logit = out + OFF_LOGIT;
    float* out_val   = out + OFF_VAL;

    void *yo_ptr, *cnt_ptr, *s1_ptr, *s0_ptr;
    cudaGetSymbolAddress(&yo_ptr,  g_yo);
    cudaGetSymbolAddress(&cnt_ptr, g_cnt);
    cudaGetSymbolAddress(&s1_ptr,  g_s1);
    cudaGetSymbolAddress(&s0_ptr,  g_s0);
    cudaMemsetAsync(yo_ptr,  0, sizeof(float) * (size_t)TBNc * Hh, 0);
    cudaMemsetAsync(cnt_ptr, 0, sizeof(int) * Nn, 0);
    cudaMemsetAsync(s1_ptr,  0, sizeof(float) * 64 * 64, 0);
    cudaMemsetAsync(s0_ptr,  0, sizeof(float) * 64, 0);

    cudaMemcpyAsync(out_hg, h_global, 1024 * sizeof(float), cudaMemcpyDeviceToDevice, 0);

    int smem_gru  = GRU_SM_TOT * 4;                                // 140032 B
    cudaFuncSetAttribute(k_gru_qkv, cudaFuncAttributeMaxDynamicSharedMemorySize, smem_gru);
    cudaFuncSetAttribute(k_attn, cudaFuncAttributeMaxDynamicSharedMemorySize, ATT_SM);
    int smem_post = (256*17*4 + 4096 + 64 + 64 + 64 + 256 + 8) * 4; // 88112 B
    cudaFuncSetAttribute(k_post, cudaFuncAttributeMaxDynamicSharedMemorySize, smem_post);

    k_count<<<(Ff * ORD + 255) / 256, 256>>>(indices);
    k_prep<<<32, 256>>>(Wo, bo, W1, b1, Wv1, extra);
    k_gru_qkv<<<148, 512, smem_gru>>>(h0, x, dones, Wi, bi, Wh, bhn,
                                      Wq, bq, Wk, bk, Wv, bv, out_hfin);
    k_attn<<<TBc * Ff / 32, 256, ATT_SM>>>(indices);
    k_post<<<TBNc / 256, 256, smem_post>>>(nnz, W2, b2, out_logit);
    k_value<<<1, 64>>>(extra, Wv1, bv1, out_val);
}

// round 15
// speedup vs baseline: 2.0764x; 1.1301x over previous
#include <cuda_runtime.h>
#include <cuda_fp16.h>
#include <math.h>
#include <stdint.h>

// Problem constants
#define Tt   4
#define Bb   4
#define Nn   16384
#define KALLc 4
#define Ff   16384
#define ORD  3
#define Hh   64
#define N0c  4096

#define TBc  (Tt*Bb)        // 16
#define BNc  (Bb*Nn)        // 65536
#define TBNc (TBc*Nn)       // 262144
#define H3c  (3*Hh)         // 192

// Output layout: h_fin [B,N,H] | h_global [B,K,64] | logit [T,B,N] | value [T,B]
#define OFF_HG    4194304
#define OFF_LOGIT (OFF_HG + 1024)
#define OFF_VAL   (OFF_LOGIT + 262144)

// Scratch
__device__ __half g_qkvh[TBNc * H3c]; // [T,B,N,192] fp16 (intermediate only)
__device__ float g_yo [TBNc * Hh];    // [T,B,N,64]
__device__ int   g_cnt[Nn];
__device__ float g_M  [64*64];        // Wo @ W1[:64]
__device__ float g_c1 [64];           // bo @ W1[:64]
__device__ float g_E  [64*64];        // per (tb,kall): b1 + extra@W1[64:]
__device__ float g_wv [64];           // Wo @ Wv1[:64]
__device__ float g_bv [1];            // bo @ Wv1[:64]
__device__ float g_s1 [64*64];        // per (tb,kall): sum_n yo*invnnz
__device__ float g_s0 [64];           // per (tb,kall): sum_n cnt*invnnz

__device__ __forceinline__ float sigmoidf_(float v) { return 1.f / (1.f + expf(-v)); }

// ---- packed fp32 helpers (fma.rn.f32x2) ----
__device__ __forceinline__ unsigned long long packdup(float v) {
    unsigned long long r;
    asm("mov.b64 %0, {%1, %1};" : "=l"(r) : "f"(v));
    return r;
}
__device__ __forceinline__ unsigned long long pack2(float a, float b) {
    unsigned long long r;
    asm("mov.b64 %0, {%1, %2};" : "=l"(r) : "f"(a), "f"(b));
    return r;
}
__device__ __forceinline__ void ffma2(unsigned long long& acc,
                                      unsigned long long a, unsigned long long b) {
    asm("fma.rn.f32x2 %0, %1, %2, %0;" : "+l"(acc) : "l"(a), "l"(b));
}
__device__ __forceinline__ float2 unpack2(unsigned long long v) {
    float lo, hi;
    asm("mov.b64 {%0, %1}, %2;" : "=f"(lo), "=f"(hi) : "l"(v));
    return make_float2(lo, hi);
}

// load 16 halfs -> 16 floats
__device__ __forceinline__ void ld16h(const __half* p, float* f) {
    uint4 a = *(const uint4*)p;
    uint4 b = *(const uint4*)(p + 8);
    float2 t;
    t = __half22float2(*(__half2*)&a.x); f[0]=t.x;  f[1]=t.y;
    t = __half22float2(*(__half2*)&a.y); f[2]=t.x;  f[3]=t.y;
    t = __half22float2(*(__half2*)&a.z); f[4]=t.x;  f[5]=t.y;
    t = __half22float2(*(__half2*)&a.w); f[6]=t.x;  f[7]=t.y;
    t = __half22float2(*(__half2*)&b.x); f[8]=t.x;  f[9]=t.y;
    t = __half22float2(*(__half2*)&b.y); f[10]=t.x; f[11]=t.y;
    t = __half22float2(*(__half2*)&b.z); f[12]=t.x; f[13]=t.y;
    t = __half22float2(*(__half2*)&b.w); f[14]=t.x; f[15]=t.y;
}

// ---------------------------------------------------------------------------
__global__ void k_count(const int* __restrict__ indices) {
    int i = blockIdx.x * 256 + threadIdx.x;
    if (i < Ff * ORD) atomicAdd(&g_cnt[indices[i]], 1);
}

// ---------------------------------------------------------------------------
__global__ void k_prep(const float* __restrict__ Wo, const float* __restrict__ bo,
                       const float* __restrict__ W1, const float* __restrict__ b1,
                       const float* __restrict__ Wv1,
                       const float* __restrict__ extra)
{
    int o = blockIdx.x * 256 + threadIdx.x;
    if (o < 4096) {
        int j = o >> 6, c = o & 63;
        float s = 0.f;
        #pragma unroll
        for (int h = 0; h < 64; h++) s += Wo[j*64 + h] * W1[h*64 + c];
        g_M[o] = s;
    } else {
        int e = o - 4096;
        int g = e >> 6, c = e & 63;
        float s = b1[c];
        #pragma unroll
        for (int d = 0; d < 4; d++) s += extra[g*4 + d] * W1[(64 + d)*64 + c];
        g_E[e] = s;
    }
    if (blockIdx.x == 0 && threadIdx.x < 64) {
        int tid = threadIdx.x;
        float s = 0.f, w = 0.f;
        #pragma unroll
        for (int h = 0; h < 64; h++) {
            s += bo[h] * W1[h*64 + tid];
            w += Wo[tid*64 + h] * Wv1[h];
        }
        g_c1[tid] = s;
        g_wv[tid] = w;
        if (tid == 0) {
            float bvv = 0.f;
            #pragma unroll
            for (int h = 0; h < 64; h++) bvv += bo[h] * Wv1[h];
            g_bv[0] = bvv;
        }
    }
}

// ---------------------------------------------------------------------------
// Fused GRU scan + QKV projection, persistent; qkv stored as fp16.
// ---------------------------------------------------------------------------
#define GRU_HSTR     68
#define GRU_OFF_WI   12288
#define GRU_OFF_BI   (GRU_OFF_WI + 768)
#define GRU_OFF_BHN  (GRU_OFF_BI + 192)
#define GRU_OFF_WQ   (GRU_OFF_BHN + 64)
#define GRU_OFF_BQ   (GRU_OFF_WQ + 12288)
#define GRU_OFF_X    (GRU_OFF_BQ + 192)
#define GRU_OFF_H    (GRU_OFF_X + 512)
#define GRU_SM_TOT   (GRU_OFF_H + 128*GRU_HSTR)
#define GRU_NT       512

__global__ __launch_bounds__(512)
void k_gru_qkv(const float* __restrict__ h0, const float* __restrict__ x,
               const uint32_t* __restrict__ dones,
               const float* __restrict__ Wi, const float* __restrict__ bi,
               const float* __restrict__ Wh, const float* __restrict__ bhn,
               const float* __restrict__ Wq, const float* __restrict__ bq,
               const float* __restrict__ Wk, const float* __restrict__ bk,
               const float* __restrict__ Wv, const float* __restrict__ bv,
               float* __restrict__ hfin_out)
{
    extern __shared__ float gs[];
    float* sWh   = gs;
    float* sWi   = gs + GRU_OFF_WI;
    float* sbi   = gs + GRU_OFF_BI;
    float* sbhn  = gs + GRU_OFF_BHN;
    float* sWq   = gs + GRU_OFF_WQ;
    float* sbq   = gs + GRU_OFF_BQ;
    float* sX    = gs + GRU_OFF_X;
    float* sH    = gs + GRU_OFF_H;

    int tid = threadIdx.x;

    for (int i = tid; i < 12288; i += 512) {
        int k = i / 192, e = i % 192;
        int c = e / 3, g = e % 3;
        sWh[i] = Wh[k*192 + g*64 + c];
    }
    for (int i = tid; i < 768; i += 512) {
        int k = i / 192, e = i % 192;
        int c = e / 3, g = e % 3;
        sWi[i] = Wi[k*192 + g*64 + c];
    }
    if (tid < 192) {
        int c = tid / 3, g = tid % 3;
        sbi[tid] = bi[g*64 + c];
    }
    if (tid < 64) sbhn[tid] = bhn[tid];
    for (int i = tid; i < 12288; i += 512) {
        int k = i / 192, e = i % 192;
        sWq[i] = (e < 64) ? Wq[k*64 + e] : (e < 128) ? Wk[k*64 + e - 64] : Wv[k*64 + e - 128];
    }
    if (tid < 192)
        sbq[tid] = (tid < 64) ? bq[tid] : (tid < 128) ? bk[tid - 64] : bv[tid - 128];

    int rg = tid >> 5;
    int cg = tid & 31;
    int c0 = cg * 6;
    int u0 = cg * 2;

    #pragma unroll 1
    for (int tile = blockIdx.x; tile < GRU_NT; tile += gridDim.x) {
        size_t rowbase = (size_t)tile * 128;
        int b = (int)(rowbase >> 14);

        __syncthreads();
        for (int i = tid; i < 8192; i += 512) {
            int r = i >> 6, c = i & 63;
            sH[r*GRU_HSTR + c] = h0[rowbase*64 + i];
        }

        #pragma unroll 1
        for (int t = 0; t < Tt; t++) {
            __syncthreads();

            sX[tid] = x[((size_t)t * BNc + rowbase) * 4 + tid];
            if (dones[t * Bb + b] != 0u) {
                for (int i = tid; i < 8192; i += 512) {
                    int r = i >> 6, c = i & 63;
                    sH[r*GRU_HSTR + c] = 0.f;
                }
            }
            __syncthreads();

            unsigned long long acc[8][3];
            #pragma unroll
            for (int i = 0; i < 8; i++) { acc[i][0] = 0ULL; acc[i][1] = 0ULL; acc[i][2] = 0ULL; }

            const float* sWrow = sWh + c0;
            #pragma unroll 1
            for (int k4 = 0; k4 < 16; k4++) {
                unsigned long long w[4][3];
                #pragma unroll
                for (int kk = 0; kk < 4; kk++) {
                    const float* wr = sWrow + (k4*4 + kk) * 192;
                    w[kk][0] = *(const unsigned long long*)(wr);
                    w[kk][1] = *(const unsigned long long*)(wr + 2);
                    w[kk][2] = *(const unsigned long long*)(wr + 4);
                }
                #pragma unroll
                for (int i = 0; i < 8; i++) {
                    float4 hv = *(const float4*)&sH[(rg + 16*i) * GRU_HSTR + k4*4];
                    unsigned long long hh0 = packdup(hv.x);
                    ffma2(acc[i][0], hh0, w[0][0]); ffma2(acc[i][1], hh0, w[0][1]); ffma2(acc[i][2], hh0, w[0][2]);
                    unsigned long long hh1 = packdup(hv.y);
                    ffma2(acc[i][0], hh1, w[1][0]); ffma2(acc[i][1], hh1, w[1][1]); ffma2(acc[i][2], hh1, w[1][2]);
                    unsigned long long hh2 = packdup(hv.z);
                    ffma2(acc[i][0], hh2, w[2][0]); ffma2(acc[i][1], hh2, w[2][1]); ffma2(acc[i][2], hh2, w[2][2]);
                    unsigned long long hh3 = packdup(hv.w);
                    ffma2(acc[i][0], hh3, w[3][0]); ffma2(acc[i][1], hh3, w[3][1]); ffma2(acc[i][2], hh3, w[3][2]);
                }
            }
            __syncthreads();

            float2 bh2 = *(const float2*)&sbhn[u0];
            #pragma unroll
            for (int i = 0; i < 8; i++) {
                int row = rg + 16*i;
                unsigned long long g0 = *(const unsigned long long*)(sbi + c0);
                unsigned long long g1 = *(const unsigned long long*)(sbi + c0 + 2);
                unsigned long long g2 = *(const unsigned long long*)(sbi + c0 + 4);
                #pragma unroll
                for (int d = 0; d < 4; d++) {
                    unsigned long long xv = packdup(sX[row*4 + d]);
                    const float* wr = sWi + d*192 + c0;
                    ffma2(g0, xv, *(const unsigned long long*)(wr));
                    ffma2(g1, xv, *(const unsigned long long*)(wr + 2));
                    ffma2(g2, xv, *(const unsigned long long*)(wr + 4));
                }
                float2 a0 = unpack2(acc[i][0]);
                float2 a1 = unpack2(acc[i][1]);
                float2 a2 = unpack2(acc[i][2]);
                float2 i0 = unpack2(g0);
                float2 i1 = unpack2(g1);
                float2 i2 = unpack2(g2);

                float2 hold = *(const float2*)&sH[row*GRU_HSTR + u0];
                float r0 = sigmoidf_(i0.x + a0.x);
                float z0 = sigmoidf_(i0.y + a0.y);
                float n0 = tanhf(i1.x + r0 * (a1.x + bh2.x));
                float h0n = (1.f - z0) * n0 + z0 * hold.x;
                float r1 = sigmoidf_(i1.y + a1.y);
                float z1 = sigmoidf_(i2.x + a2.x);
                float n1 = tanhf(i2.y + r1 * (a2.y + bh2.y));
                float h1n = (1.f - z1) * n1 + z1 * hold.y;
                *(float2*)&sH[row*GRU_HSTR + u0] = make_float2(h0n, h1n);
            }
            __syncthreads();

            {
                unsigned long long qa[8][3];
                float2 b01 = *(const float2*)&sbq[c0];
                float2 b23 = *(const float2*)&sbq[c0 + 2];
                float2 b45 = *(const float2*)&sbq[c0 + 4];
                #pragma unroll
                for (int i = 0; i < 8; i++) {
                    qa[i][0] = pack2(b01.x, b01.y);
                    qa[i][1] = pack2(b23.x, b23.y);
                    qa[i][2] = pack2(b45.x, b45.y);
                }
                const float* sQrow = sWq + c0;
                #pragma unroll 1
                for (int k4 = 0; k4 < 16; k4++) {
                    unsigned long long w[4][3];
                    #pragma unroll
                    for (int kk = 0; kk < 4; kk++) {
                        const float* wr = sQrow + (k4*4 + kk) * 192;
                        w[kk][0] = *(const unsigned long long*)(wr);
                        w[kk][1] = *(const unsigned long long*)(wr + 2);
                        w[kk][2] = *(const unsigned long long*)(wr + 4);
                    }
                    #pragma unroll
                    for (int i = 0; i < 8; i++) {
                        float4 hv = *(const float4*)&sH[(rg + 16*i) * GRU_HSTR + k4*4];
                        unsigned long long hh0 = packdup(hv.x);
                        ffma2(qa[i][0], hh0, w[0][0]); ffma2(qa[i][1], hh0, w[0][1]); ffma2(qa[i][2], hh0, w[0][2]);
                        unsigned long long hh1 = packdup(hv.y);
                        ffma2(qa[i][0], hh1, w[1][0]); ffma2(qa[i][1], hh1, w[1][1]); ffma2(qa[i][2], hh1, w[1][2]);
                        unsigned long long hh2 = packdup(hv.z);
                        ffma2(qa[i][0], hh2, w[2][0]); ffma2(qa[i][1], hh2, w[2][1]); ffma2(qa[i][2], hh2, w[2][2]);
                        unsigned long long hh3 = packdup(hv.w);
                        ffma2(qa[i][0], hh3, w[3][0]); ffma2(qa[i][1], hh3, w[3][1]); ffma2(qa[i][2], hh3, w[3][2]);
                    }
                }
                size_t orow0 = (size_t)t * BNc + rowbase;
                #pragma unroll
                for (int i = 0; i < 8; i++) {
                    float2 p0 = unpack2(qa[i][0]);
                    float2 p1 = unpack2(qa[i][1]);
                    float2 p2 = unpack2(qa[i][2]);
                    __half2* dst = (__half2*)(g_qkvh + (orow0 + rg + 16*i) * H3c + c0);
                    dst[0] = __floats2half2_rn(p0.x, p0.y);
                    dst[1] = __floats2half2_rn(p1.x, p1.y);
                    dst[2] = __floats2half2_rn(p2.x, p2.y);
                }
            }
        }

        __syncthreads();
        for (int i = tid; i < 8192; i += 512) {
            int r = i >> 6, c = i & 63;
            hfin_out[rowbase*64 + i] = sH[r*GRU_HSTR + c];
        }
    }
}

// ---------------------------------------------------------------------------
// Attention v4: fp16 rows, 4 instances/warp, low-reg compute.
// Phase A: all 9 logits (k alive). Phase B: o streamed to dead q+k front
// (256B = 64 fp32) per row. Scatter fp32 atomics from smem.
// ---------------------------------------------------------------------------
#define ATT_HSTR 200    // halfs per row (400B, 16B aligned)
#define ATT_SM   (8 * 12 * ATT_HSTR * 2)   // 38400 B

__global__ __launch_bounds__(256, 3)
void k_attn(const int* __restrict__ indices)
{
    extern __shared__ __align__(16) __half ah_[];
    __shared__ int sIdx[8][12];

    int warp = threadIdx.x >> 5, lane = threadIdx.x & 31;
    __half* R0 = ah_ + warp * 12 * ATT_HSTR;

    int ip = blockIdx.x * 32 + warp * 4;
    int tb = ip >> 14;
    int f0 = ip & 16383;

    if (lane < 12) sIdx[warp][lane] = __ldg(&indices[f0*3 + lane]);
    __syncwarp();

    // Gather 12 rows x 192 halfs (24 uint4 each); lanes 0..23 active
    const __half* base = g_qkvh + (size_t)tb * Nn * H3c;
    #pragma unroll
    for (int r = 0; r < 12; r++) {
        if (lane < 24) {
            const uint4* src = (const uint4*)(base + (size_t)sIdx[warp][r] * H3c);
            ((uint4*)(R0 + r * ATT_HSTR))[lane] = src[lane];
        }
    }
    __syncwarp();

    // Compute: 16 lanes, lane = hh*4 + i
    if (lane < 16) {
        int i = lane & 3, hh = lane >> 2;
        __half* R = R0 + i * 3 * ATT_HSTR;
        int ho = hh * 16;

        // Phase A: all 9 logits
        float l[3][3];
        #pragma unroll
        for (int qr = 0; qr < 3; qr++) {
            float q[16];
            ld16h(R + qr*ATT_HSTR + ho, q);
            #pragma unroll
            for (int kr = 0; kr < 3; kr++) {
                float kv[16];
                ld16h(R + kr*ATT_HSTR + 64 + ho, kv);
                float s = 0.f;
                #pragma unroll
                for (int d = 0; d < 16; d++) s += q[d] * kv[d];
                l[qr][kr] = s * 0.25f;
            }
        }
        // Phase B: softmax + o -> overwrite q+k front (as fp32)
        #pragma unroll
        for (int qr = 0; qr < 3; qr++) {
            float m = fmaxf(l[qr][0], fmaxf(l[qr][1], l[qr][2]));
            float e0 = __expf(l[qr][0] - m), e1 = __expf(l[qr][1] - m), e2 = __expf(l[qr][2] - m);
            float inv = 1.f / (e0 + e1 + e2);
            e0 *= inv; e1 *= inv; e2 *= inv;
            float v0[16], v1[16], v2[16];
            ld16h(R + 0*ATT_HSTR + 128 + ho, v0);
            ld16h(R + 1*ATT_HSTR + 128 + ho, v1);
            ld16h(R + 2*ATT_HSTR + 128 + ho, v2);
            float* of = (float*)(R + qr*ATT_HSTR) + ho;   // front 64 floats
            #pragma unroll
            for (int d4 = 0; d4 < 4; d4++) {
                float4 v;
                v.x = e0*v0[d4*4+0] + e1*v1[d4*4+0] + e2*v2[d4*4+0];
                v.y = e0*v0[d4*4+1] + e1*v1[d4*4+1] + e2*v2[d4*4+1];
                v.z = e0*v0[d4*4+2] + e1*v1[d4*4+2] + e2*v2[d4*4+2];
                v.w = e0*v0[d4*4+3] + e1*v1[d4*4+3] + e2*v2[d4*4+3];
                *(float4*)(of + d4*4) = v;
            }
        }
    }
    __syncwarp();

    // Scatter: 12 rows x 16 float4 cols
    {
        int rhalf = lane >> 4, col = lane & 15;
        float4* yo = (float4*)g_yo + (size_t)tb * Nn * 16;
        #pragma unroll
        for (int it = 0; it < 6; it++) {
            int r = it*2 + rhalf;
            float4 v = *(const float4*)((const float*)(R0 + r*ATT_HSTR) + col*4);
            atomicAdd(&yo[(size_t)sIdx[warp][r] * 16 + col], v);
        }
    }
}

// ---------------------------------------------------------------------------
// Logit head + fused value-head segment sums (unchanged, passing).
// ---------------------------------------------------------------------------
__global__ __launch_bounds__(256, 2)
void k_post(const float* __restrict__ nnz,
            const float* __restrict__ W2, const float* __restrict__ b2,
            float* __restrict__ logit_out)
{
    extern __shared__ float ps[];
    float4* sT4 = (float4*)ps;
    float*  sM  = ps + 256*17*4;
    float*  sc1 = sM + 4096;
    float*  sE  = sc1 + 64;
    float*  sW2 = sE + 64;
    float*  sRed = sW2 + 64;
    float*  sR0  = sRed + 256;

    int tid = threadIdx.x;
    int rowbase = blockIdx.x * 256;
    int g = rowbase >> 12;

    const float4* yo4 = (const float4*)g_yo + (size_t)rowbase * 16;
    for (int i = tid; i < 4096; i += 256)
        sT4[(i >> 4) * 17 + (i & 15)] = yo4[i];
    for (int i = tid; i < 4096; i += 256) sM[i] = g_M[i];
    if (tid < 64) { sc1[tid] = g_c1[tid]; sE[tid] = g_E[g*64 + tid]; sW2[tid] = W2[tid]; }
    __syncthreads();

    int row = rowbase + tid;
    int n = row & 16383;
    float inv = 1.f / nnz[n];
    float cninv = (float)g_cnt[n] * inv;

    float yo[64];
    #pragma unroll
    for (int jj = 0; jj < 16; jj++) {
        float4 v = sT4[tid * 17 + jj];
        yo[4*jj] = v.x; yo[4*jj+1] = v.y; yo[4*jj+2] = v.z; yo[4*jj+3] = v.w;
    }

    const ulonglong2* sM2 = (const ulonglong2*)sM;
    float logit = 0.f;
    #pragma unroll 1
    for (int p = 0; p < 8; p++) {
        unsigned long long acc[4] = {0ULL, 0ULL, 0ULL, 0ULL};
        #pragma unroll
        for (int j = 0; j < 64; j++) {
            unsigned long long y2 = packdup(yo[j]);
            ulonglong2 w0 = sM2[j*16 + p*2];
            ulonglong2 w1 = sM2[j*16 + p*2 + 1];
            ffma2(acc[0], y2, w0.x);
            ffma2(acc[1], y2, w0.y);
            ffma2(acc[2], y2, w1.x);
            ffma2(acc[3], y2, w1.y);
        }
        #pragma unroll
        for (int q = 0; q < 4; q++) {
            float2 v = unpack2(acc[q]);
            int c = p*8 + q*2;
            float pre, rr;
            pre = inv*v.x + cninv*sc1[c]   + sE[c];   rr = fmaxf(pre, 0.f); logit += rr*sW2[c];
            pre = inv*v.y + cninv*sc1[c+1] + sE[c+1]; rr = fmaxf(pre, 0.f); logit += rr*sW2[c+1];
        }
    }
    logit_out[row] = logit + b2[0];

    __syncthreads();
    #pragma unroll
    for (int jj = 0; jj < 16; jj++) {
        sT4[tid * 17 + jj] = make_float4(yo[4*jj]*inv, yo[4*jj+1]*inv,
                                         yo[4*jj+2]*inv, yo[4*jj+3]*inv);
    }
    __syncthreads();
    {
        int col = tid & 63, part = tid >> 6;
        const float* sS = ps;
        float s = 0.f;
        #pragma unroll 4
        for (int r = part*64; r < part*64 + 64; r++)
            s += sS[r*68 + col];
        sRed[part*64 + col] = s;
    }
    {
        float v = cninv;
        #pragma unroll
        for (int off = 16; off; off >>= 1) v += __shfl_xor_sync(0xffffffffu, v, off);
        if ((tid & 31) == 0) sR0[tid >> 5] = v;
    }
    __syncthreads();
    if (tid < 64)
        atomicAdd(&g_s1[g*64 + tid], sRed[tid] + sRed[64 + tid] + sRed[128 + tid] + sRed[192 + tid]);
    if (tid == 0) {
        float s0 = 0.f;
        #pragma unroll
        for (int w = 0; w < 8; w++) s0 += sR0[w];
        atomicAdd(&g_s0[g], s0);
    }
}

// ---------------------------------------------------------------------------
__global__ void k_value(const float* __restrict__ extra,
                        const float* __restrict__ Wv1, const float* __restrict__ bv1,
                        float* __restrict__ val_out)
{
    __shared__ float sv[64];
    int tid = threadIdx.x;
    float acc = 0.f;
    #pragma unroll
    for (int j = 0; j < 64; j++) acc += g_s1[tid*64 + j] * g_wv[j];
    acc += g_s0[tid] * g_bv[0];
    acc *= (1.f / (float)N0c);
    #pragma unroll
    for (int d = 0; d < 4; d++) acc += extra[tid*4 + d] * Wv1[64 + d];
    acc += bv1[0];
    sv[tid] = acc;
    __syncthreads();
    if (tid < 16)
        val_out[tid] = sv[tid*4] + sv[tid*4+1] + sv[tid*4+2] + sv[tid*4+3];
}

// ---------------------------------------------------------------------------
extern "C" void kernel_launch(void* const* d_in, const int* in_sizes, int n_in,
                              void* d_out, int out_size)
{
    const float* h0       = (const float*)d_in[0];
    const float* h_global = (const float*)d_in[1];
    const float* x        = (const float*)d_in[2];
    const float* extra    = (const float*)d_in[3];
    const uint32_t* dones = (const uint32_t*)d_in[4];
    const int*   indices  = (const int*)d_in[5];
    const float* nnz      = (const float*)d_in[6];
    const float* Wi  = (const float*)d_in[7];
    const float* bi  = (const float*)d_in[8];
    const float* Wh  = (const float*)d_in[9];
    const float* bhn = (const float*)d_in[10];
    const float* Wq  = (const float*)d_in[11];
    const float* bq  = (const float*)d_in[12];
    const float* Wk  = (const float*)d_in[13];
    const float* bk  = (const float*)d_in[14];
    const float* Wv  = (const float*)d_in[15];
    const float* bv  = (const float*)d_in[16];
    const float* Wo  = (const float*)d_in[17];
    const float* bo  = (const float*)d_in[18];
    const float* W1  = (const float*)d_in[19];
    const float* b1  = (const float*)d_in[20];
    const float* W2  = (const float*)d_in[21];
    const float* b2  = (const float*)d_in[22];
    const float* Wv1 = (const float*)d_in[23];
    const float* bv1 = (const float*)d_in[24];

    float* out       = (float*)d_out;
    float* out_hfin  = out;
    float* out_hg    = out + OFF_HG;
    float* out_logit = out + OFF_LOGIT;
    float* out_val   = out + OFF_VAL;

    void *yo_ptr, *cnt_ptr, *s1_ptr, *s0_ptr;
    cudaGetSymbolAddress(&yo_ptr,  g_yo);
    cudaGetSymbolAddress(&cnt_ptr, g_cnt);
    cudaGetSymbolAddress(&s1_ptr,  g_s1);
    cudaGetSymbolAddress(&s0_ptr,  g_s0);
    cudaMemsetAsync(yo_ptr,  0, sizeof(float) * (size_t)TBNc * Hh, 0);
    cudaMemsetAsync(cnt_ptr, 0, sizeof(int) * Nn, 0);
    cudaMemsetAsync(s1_ptr,  0, sizeof(float) * 64 * 64, 0);
    cudaMemsetAsync(s0_ptr,  0, sizeof(float) * 64, 0);

    cudaMemcpyAsync(out_hg, h_global, 1024 * sizeof(float), cudaMemcpyDeviceToDevice, 0);

    int smem_gru  = GRU_SM_TOT * 4;                                // 140032 B
    cudaFuncSetAttribute(k_gru_qkv, cudaFuncAttributeMaxDynamicSharedMemorySize, smem_gru);
    cudaFuncSetAttribute(k_attn, cudaFuncAttributeMaxDynamicSharedMemorySize, ATT_SM);
    int smem_post = (256*17*4 + 4096 + 64 + 64 + 64 + 256 + 8) * 4; // 88112 B
    cudaFuncSetAttribute(k_post, cudaFuncAttributeMaxDynamicSharedMemorySize, smem_post);

    k_count<<<(Ff * ORD + 255) / 256, 256>>>(indices);
    k_prep<<<32, 256>>>(Wo, bo, W1, b1, Wv1, extra);
    k_gru_qkv<<<148, 512, smem_gru>>>(h0, x, dones, Wi, bi, Wh, bhn,
                                      Wq, bq, Wk, bk, Wv, bv, out_hfin);
    k_attn<<<TBc * Ff / 32, 256, ATT_SM>>>(indices);
    k_post<<<TBNc / 256, 256, smem_post>>>(nnz, W2, b2, out_logit);
    k_value<<<1, 64>>>(extra, Wv1, bv1, out_val);
}

// round 16
// speedup vs baseline: 2.1498x; 1.0354x over previous
#include <cuda_runtime.h>
#include <cuda_fp16.h>
#include <math.h>
#include <stdint.h>

// Problem constants
#define Tt   4
#define Bb   4
#define Nn   16384
#define KALLc 4
#define Ff   16384
#define ORD  3
#define Hh   64
#define N0c  4096

#define TBc  (Tt*Bb)        // 16
#define BNc  (Bb*Nn)        // 65536
#define TBNc (TBc*Nn)       // 262144
#define H3c  (3*Hh)         // 192

// Output layout: h_fin [B,N,H] | h_global [B,K,64] | logit [T,B,N] | value [T,B]
#define OFF_HG    4194304
#define OFF_LOGIT (OFF_HG + 1024)
#define OFF_VAL   (OFF_LOGIT + 262144)

// Scratch
__device__ __half g_qkvh[TBNc * H3c]; // [T,B,N,192] fp16 (intermediate only)
__device__ float g_yo [TBNc * Hh];    // [T,B,N,64]
__device__ int   g_cnt[Nn];
__device__ float g_M  [64*64];        // Wo @ W1[:64]
__device__ float g_c1 [64];           // bo @ W1[:64]
__device__ float g_E  [64*64];        // per (tb,kall): b1 + extra@W1[64:]
__device__ float g_wv [64];           // Wo @ Wv1[:64]
__device__ float g_bv [1];            // bo @ Wv1[:64]
__device__ float g_s1 [64*64];        // per (tb,kall): sum_n yo*invnnz
__device__ float g_s0 [64];           // per (tb,kall): sum_n cnt*invnnz

__device__ __forceinline__ float sigmoidf_(float v) { return 1.f / (1.f + expf(-v)); }

// ---- packed fp32 helpers (fma.rn.f32x2) ----
__device__ __forceinline__ unsigned long long packdup(float v) {
    unsigned long long r;
    asm("mov.b64 %0, {%1, %1};" : "=l"(r) : "f"(v));
    return r;
}
__device__ __forceinline__ unsigned long long pack2(float a, float b) {
    unsigned long long r;
    asm("mov.b64 %0, {%1, %2};" : "=l"(r) : "f"(a), "f"(b));
    return r;
}
__device__ __forceinline__ void ffma2(unsigned long long& acc,
                                      unsigned long long a, unsigned long long b) {
    asm("fma.rn.f32x2 %0, %1, %2, %0;" : "+l"(acc) : "l"(a), "l"(b));
}
__device__ __forceinline__ float2 unpack2(unsigned long long v) {
    float lo, hi;
    asm("mov.b64 {%0, %1}, %2;" : "=f"(lo), "=f"(hi) : "l"(v));
    return make_float2(lo, hi);
}

// load 4 halfs -> float4
__device__ __forceinline__ float4 ld4h(const __half* p) {
    uint2 a = *(const uint2*)p;
    float2 lo = __half22float2(*(__half2*)&a.x);
    float2 hi = __half22float2(*(__half2*)&a.y);
    return make_float4(lo.x, lo.y, hi.x, hi.y);
}

// ---------------------------------------------------------------------------
__global__ void k_count(const int* __restrict__ indices) {
    int i = blockIdx.x * 256 + threadIdx.x;
    if (i < Ff * ORD) atomicAdd(&g_cnt[indices[i]], 1);
}

// ---------------------------------------------------------------------------
__global__ void k_prep(const float* __restrict__ Wo, const float* __restrict__ bo,
                       const float* __restrict__ W1, const float* __restrict__ b1,
                       const float* __restrict__ Wv1,
                       const float* __restrict__ extra)
{
    int o = blockIdx.x * 256 + threadIdx.x;
    if (o < 4096) {
        int j = o >> 6, c = o & 63;
        float s = 0.f;
        #pragma unroll
        for (int h = 0; h < 64; h++) s += Wo[j*64 + h] * W1[h*64 + c];
        g_M[o] = s;
    } else {
        int e = o - 4096;
        int g = e >> 6, c = e & 63;
        float s = b1[c];
        #pragma unroll
        for (int d = 0; d < 4; d++) s += extra[g*4 + d] * W1[(64 + d)*64 + c];
        g_E[e] = s;
    }
    if (blockIdx.x == 0 && threadIdx.x < 64) {
        int tid = threadIdx.x;
        float s = 0.f, w = 0.f;
        #pragma unroll
        for (int h = 0; h < 64; h++) {
            s += bo[h] * W1[h*64 + tid];
            w += Wo[tid*64 + h] * Wv1[h];
        }
        g_c1[tid] = s;
        g_wv[tid] = w;
        if (tid == 0) {
            float bvv = 0.f;
            #pragma unroll
            for (int h = 0; h < 64; h++) bvv += bo[h] * Wv1[h];
            g_bv[0] = bvv;
        }
    }
}

// ---------------------------------------------------------------------------
// Fused GRU scan + QKV projection, persistent; qkv stored as fp16.
// (unchanged from R15, passing)
// ---------------------------------------------------------------------------
#define GRU_HSTR     68
#define GRU_OFF_WI   12288
#define GRU_OFF_BI   (GRU_OFF_WI + 768)
#define GRU_OFF_BHN  (GRU_OFF_BI + 192)
#define GRU_OFF_WQ   (GRU_OFF_BHN + 64)
#define GRU_OFF_BQ   (GRU_OFF_WQ + 12288)
#define GRU_OFF_X    (GRU_OFF_BQ + 192)
#define GRU_OFF_H    (GRU_OFF_X + 512)
#define GRU_SM_TOT   (GRU_OFF_H + 128*GRU_HSTR)
#define GRU_NT       512

__global__ __launch_bounds__(512)
void k_gru_qkv(const float* __restrict__ h0, const float* __restrict__ x,
               const uint32_t* __restrict__ dones,
               const float* __restrict__ Wi, const float* __restrict__ bi,
               const float* __restrict__ Wh, const float* __restrict__ bhn,
               const float* __restrict__ Wq, const float* __restrict__ bq,
               const float* __restrict__ Wk, const float* __restrict__ bk,
               const float* __restrict__ Wv, const float* __restrict__ bv,
               float* __restrict__ hfin_out)
{
    extern __shared__ float gs[];
    float* sWh   = gs;
    float* sWi   = gs + GRU_OFF_WI;
    float* sbi   = gs + GRU_OFF_BI;
    float* sbhn  = gs + GRU_OFF_BHN;
    float* sWq   = gs + GRU_OFF_WQ;
    float* sbq   = gs + GRU_OFF_BQ;
    float* sX    = gs + GRU_OFF_X;
    float* sH    = gs + GRU_OFF_H;

    int tid = threadIdx.x;

    for (int i = tid; i < 12288; i += 512) {
        int k = i / 192, e = i % 192;
        int c = e / 3, g = e % 3;
        sWh[i] = Wh[k*192 + g*64 + c];
    }
    for (int i = tid; i < 768; i += 512) {
        int k = i / 192, e = i % 192;
        int c = e / 3, g = e % 3;
        sWi[i] = Wi[k*192 + g*64 + c];
    }
    if (tid < 192) {
        int c = tid / 3, g = tid % 3;
        sbi[tid] = bi[g*64 + c];
    }
    if (tid < 64) sbhn[tid] = bhn[tid];
    for (int i = tid; i < 12288; i += 512) {
        int k = i / 192, e = i % 192;
        sWq[i] = (e < 64) ? Wq[k*64 + e] : (e < 128) ? Wk[k*64 + e - 64] : Wv[k*64 + e - 128];
    }
    if (tid < 192)
        sbq[tid] = (tid < 64) ? bq[tid] : (tid < 128) ? bk[tid - 64] : bv[tid - 128];

    int rg = tid >> 5;
    int cg = tid & 31;
    int c0 = cg * 6;
    int u0 = cg * 2;

    #pragma unroll 1
    for (int tile = blockIdx.x; tile < GRU_NT; tile += gridDim.x) {
        size_t rowbase = (size_t)tile * 128;
        int b = (int)(rowbase >> 14);

        __syncthreads();
        for (int i = tid; i < 8192; i += 512) {
            int r = i >> 6, c = i & 63;
            sH[r*GRU_HSTR + c] = h0[rowbase*64 + i];
        }

        #pragma unroll 1
        for (int t = 0; t < Tt; t++) {
            __syncthreads();

            sX[tid] = x[((size_t)t * BNc + rowbase) * 4 + tid];
            if (dones[t * Bb + b] != 0u) {
                for (int i = tid; i < 8192; i += 512) {
                    int r = i >> 6, c = i & 63;
                    sH[r*GRU_HSTR + c] = 0.f;
                }
            }
            __syncthreads();

            unsigned long long acc[8][3];
            #pragma unroll
            for (int i = 0; i < 8; i++) { acc[i][0] = 0ULL; acc[i][1] = 0ULL; acc[i][2] = 0ULL; }

            const float* sWrow = sWh + c0;
            #pragma unroll 1
            for (int k4 = 0; k4 < 16; k4++) {
                unsigned long long w[4][3];
                #pragma unroll
                for (int kk = 0; kk < 4; kk++) {
                    const float* wr = sWrow + (k4*4 + kk) * 192;
                    w[kk][0] = *(const unsigned long long*)(wr);
                    w[kk][1] = *(const unsigned long long*)(wr + 2);
                    w[kk][2] = *(const unsigned long long*)(wr + 4);
                }
                #pragma unroll
                for (int i = 0; i < 8; i++) {
                    float4 hv = *(const float4*)&sH[(rg + 16*i) * GRU_HSTR + k4*4];
                    unsigned long long hh0 = packdup(hv.x);
                    ffma2(acc[i][0], hh0, w[0][0]); ffma2(acc[i][1], hh0, w[0][1]); ffma2(acc[i][2], hh0, w[0][2]);
                    unsigned long long hh1 = packdup(hv.y);
                    ffma2(acc[i][0], hh1, w[1][0]); ffma2(acc[i][1], hh1, w[1][1]); ffma2(acc[i][2], hh1, w[1][2]);
                    unsigned long long hh2 = packdup(hv.z);
                    ffma2(acc[i][0], hh2, w[2][0]); ffma2(acc[i][1], hh2, w[2][1]); ffma2(acc[i][2], hh2, w[2][2]);
                    unsigned long long hh3 = packdup(hv.w);
                    ffma2(acc[i][0], hh3, w[3][0]); ffma2(acc[i][1], hh3, w[3][1]); ffma2(acc[i][2], hh3, w[3][2]);
                }
            }
            __syncthreads();

            float2 bh2 = *(const float2*)&sbhn[u0];
            #pragma unroll
            for (int i = 0; i < 8; i++) {
                int row = rg + 16*i;
                unsigned long long g0 = *(const unsigned long long*)(sbi + c0);
                unsigned long long g1 = *(const unsigned long long*)(sbi + c0 + 2);
                unsigned long long g2 = *(const unsigned long long*)(sbi + c0 + 4);
                #pragma unroll
                for (int d = 0; d < 4; d++) {
                    unsigned long long xv = packdup(sX[row*4 + d]);
                    const float* wr = sWi + d*192 + c0;
                    ffma2(g0, xv, *(const unsigned long long*)(wr));
                    ffma2(g1, xv, *(const unsigned long long*)(wr + 2));
                    ffma2(g2, xv, *(const unsigned long long*)(wr + 4));
                }
                float2 a0 = unpack2(acc[i][0]);
                float2 a1 = unpack2(acc[i][1]);
                float2 a2 = unpack2(acc[i][2]);
                float2 i0 = unpack2(g0);
                float2 i1 = unpack2(g1);
                float2 i2 = unpack2(g2);

                float2 hold = *(const float2*)&sH[row*GRU_HSTR + u0];
                float r0 = sigmoidf_(i0.x + a0.x);
                float z0 = sigmoidf_(i0.y + a0.y);
                float n0 = tanhf(i1.x + r0 * (a1.x + bh2.x));
                float h0n = (1.f - z0) * n0 + z0 * hold.x;
                float r1 = sigmoidf_(i1.y + a1.y);
                float z1 = sigmoidf_(i2.x + a2.x);
                float n1 = tanhf(i2.y + r1 * (a2.y + bh2.y));
                float h1n = (1.f - z1) * n1 + z1 * hold.y;
                *(float2*)&sH[row*GRU_HSTR + u0] = make_float2(h0n, h1n);
            }
            __syncthreads();

            {
                unsigned long long qa[8][3];
                float2 b01 = *(const float2*)&sbq[c0];
                float2 b23 = *(const float2*)&sbq[c0 + 2];
                float2 b45 = *(const float2*)&sbq[c0 + 4];
                #pragma unroll
                for (int i = 0; i < 8; i++) {
                    qa[i][0] = pack2(b01.x, b01.y);
                    qa[i][1] = pack2(b23.x, b23.y);
                    qa[i][2] = pack2(b45.x, b45.y);
                }
                const float* sQrow = sWq + c0;
                #pragma unroll 1
                for (int k4 = 0; k4 < 16; k4++) {
                    unsigned long long w[4][3];
                    #pragma unroll
                    for (int kk = 0; kk < 4; kk++) {
                        const float* wr = sQrow + (k4*4 + kk) * 192;
                        w[kk][0] = *(const unsigned long long*)(wr);
                        w[kk][1] = *(const unsigned long long*)(wr + 2);
                        w[kk][2] = *(const unsigned long long*)(wr + 4);
                    }
                    #pragma unroll
                    for (int i = 0; i < 8; i++) {
                        float4 hv = *(const float4*)&sH[(rg + 16*i) * GRU_HSTR + k4*4];
                        unsigned long long hh0 = packdup(hv.x);
                        ffma2(qa[i][0], hh0, w[0][0]); ffma2(qa[i][1], hh0, w[0][1]); ffma2(qa[i][2], hh0, w[0][2]);
                        unsigned long long hh1 = packdup(hv.y);
                        ffma2(qa[i][0], hh1, w[1][0]); ffma2(qa[i][1], hh1, w[1][1]); ffma2(qa[i][2], hh1, w[1][2]);
                        unsigned long long hh2 = packdup(hv.z);
                        ffma2(qa[i][0], hh2, w[2][0]); ffma2(qa[i][1], hh2, w[2][1]); ffma2(qa[i][2], hh2, w[2][2]);
                        unsigned long long hh3 = packdup(hv.w);
                        ffma2(qa[i][0], hh3, w[3][0]); ffma2(qa[i][1], hh3, w[3][1]); ffma2(qa[i][2], hh3, w[3][2]);
                    }
                }
                size_t orow0 = (size_t)t * BNc + rowbase;
                #pragma unroll
                for (int i = 0; i < 8; i++) {
                    float2 p0 = unpack2(qa[i][0]);
                    float2 p1 = unpack2(qa[i][1]);
                    float2 p2 = unpack2(qa[i][2]);
                    __half2* dst = (__half2*)(g_qkvh + (orow0 + rg + 16*i) * H3c + c0);
                    dst[0] = __floats2half2_rn(p0.x, p0.y);
                    dst[1] = __floats2half2_rn(p1.x, p1.y);
                    dst[2] = __floats2half2_rn(p2.x, p2.y);
                }
            }
        }

        __syncthreads();
        for (int i = tid; i < 8192; i += 512) {
            int r = i >> 6, c = i & 63;
            hfin_out[rowbase*64 + i] = sH[r*GRU_HSTR + c];
        }
    }
}

// ---------------------------------------------------------------------------
// Attention v5: fp16 rows, 4 inst/warp, chunked loads (<=64 regs, 4 blocks/SM),
// full-lane gather. Phase A: all 9 logits. Phase B: o -> dead q+k front.
// ---------------------------------------------------------------------------
#define ATT_HSTR 200    // halfs per row (400B, 16B aligned)
#define ATT_SM   (8 * 12 * ATT_HSTR * 2)   // 38400 B

__global__ __launch_bounds__(256, 4)
void k_attn(const int* __restrict__ indices)
{
    extern __shared__ __align__(16) __half ah_[];
    __shared__ int sIdx[8][12];

    int warp = threadIdx.x >> 5, lane = threadIdx.x & 31;
    __half* R0 = ah_ + warp * 12 * ATT_HSTR;

    int ip = blockIdx.x * 32 + warp * 4;
    int tb = ip >> 14;
    int f0 = ip & 16383;

    if (lane < 12) sIdx[warp][lane] = __ldg(&indices[f0*3 + lane]);
    __syncwarp();

    // Gather: 12 rows x 24 uint4 = 288 chunks, all 32 lanes, 9 iters
    const __half* base = g_qkvh + (size_t)tb * Nn * H3c;
    #pragma unroll
    for (int it = 0; it < 9; it++) {
        int idx = it * 32 + lane;            // 0..287
        int r = idx / 24, e = idx - r * 24;  // const-div, strength-reduced
        const uint4* src = (const uint4*)(base + (size_t)sIdx[warp][r] * H3c);
        ((uint4*)(R0 + r * ATT_HSTR))[e] = src[e];
    }
    __syncwarp();

    // Compute: 16 lanes, lane = hh*4 + i; chunked loads keep regs < 64
    if (lane < 16) {
        int i = lane & 3, hh = lane >> 2;
        __half* R = R0 + i * 3 * ATT_HSTR;
        int ho = hh * 16;

        // Phase A: all 9 logits, k streamed in 4-float chunks
        float l[3][3];
        #pragma unroll
        for (int qr = 0; qr < 3; qr++) {
            float q[16];
            #pragma unroll
            for (int d4 = 0; d4 < 4; d4++) {
                float4 v = ld4h(R + qr*ATT_HSTR + ho + d4*4);
                q[d4*4+0] = v.x; q[d4*4+1] = v.y; q[d4*4+2] = v.z; q[d4*4+3] = v.w;
            }
            #pragma unroll
            for (int kr = 0; kr < 3; kr++) {
                float s = 0.f;
                #pragma unroll
                for (int d4 = 0; d4 < 4; d4++) {
                    float4 kv = ld4h(R + kr*ATT_HSTR + 64 + ho + d4*4);
                    s += q[d4*4+0]*kv.x + q[d4*4+1]*kv.y + q[d4*4+2]*kv.z + q[d4*4+3]*kv.w;
                }
                l[qr][kr] = s * 0.25f;
            }
        }
        // Phase B: softmax + o streamed per-chunk into dead q+k front (fp32)
        #pragma unroll
        for (int qr = 0; qr < 3; qr++) {
            float m = fmaxf(l[qr][0], fmaxf(l[qr][1], l[qr][2]));
            float e0 = __expf(l[qr][0] - m), e1 = __expf(l[qr][1] - m), e2 = __expf(l[qr][2] - m);
            float inv = 1.f / (e0 + e1 + e2);
            e0 *= inv; e1 *= inv; e2 *= inv;
            float* of = (float*)(R + qr*ATT_HSTR) + ho;
            #pragma unroll
            for (int d4 = 0; d4 < 4; d4++) {
                float4 v0 = ld4h(R + 0*ATT_HSTR + 128 + ho + d4*4);
                float4 v1 = ld4h(R + 1*ATT_HSTR + 128 + ho + d4*4);
                float4 v2 = ld4h(R + 2*ATT_HSTR + 128 + ho + d4*4);
                float4 v;
                v.x = e0*v0.x + e1*v1.x + e2*v2.x;
                v.y = e0*v0.y + e1*v1.y + e2*v2.y;
                v.z = e0*v0.z + e1*v1.z + e2*v2.z;
                v.w = e0*v0.w + e1*v1.w + e2*v2.w;
                *(float4*)(of + d4*4) = v;
            }
        }
    }
    __syncwarp();

    // Scatter: 12 rows x 16 float4 cols
    {
        int rhalf = lane >> 4, col = lane & 15;
        float4* yo = (float4*)g_yo + (size_t)tb * Nn * 16;
        #pragma unroll
        for (int it = 0; it < 6; it++) {
            int r = it*2 + rhalf;
            float4 v = *(const float4*)((const float*)(R0 + r*ATT_HSTR) + col*4);
            atomicAdd(&yo[(size_t)sIdx[warp][r] * 16 + col], v);
        }
    }
}

// ---------------------------------------------------------------------------
// Logit head + fused value-head segment sums (unchanged, passing).
// ---------------------------------------------------------------------------
__global__ __launch_bounds__(256, 2)
void k_post(const float* __restrict__ nnz,
            const float* __restrict__ W2, const float* __restrict__ b2,
            float* __restrict__ logit_out)
{
    extern __shared__ float ps[];
    float4* sT4 = (float4*)ps;
    float*  sM  = ps + 256*17*4;
    float*  sc1 = sM + 4096;
    float*  sE  = sc1 + 64;
    float*  sW2 = sE + 64;
    float*  sRed = sW2 + 64;
    float*  sR0  = sRed + 256;

    int tid = threadIdx.x;
    int rowbase = blockIdx.x * 256;
    int g = rowbase >> 12;

    const float4* yo4 = (const float4*)g_yo + (size_t)rowbase * 16;
    for (int i = tid; i < 4096; i += 256)
        sT4[(i >> 4) * 17 + (i & 15)] = yo4[i];
    for (int i = tid; i < 4096; i += 256) sM[i] = g_M[i];
    if (tid < 64) { sc1[tid] = g_c1[tid]; sE[tid] = g_E[g*64 + tid]; sW2[tid] = W2[tid]; }
    __syncthreads();

    int row = rowbase + tid;
    int n = row & 16383;
    float inv = 1.f / nnz[n];
    float cninv = (float)g_cnt[n] * inv;

    float yo[64];
    #pragma unroll
    for (int jj = 0; jj < 16; jj++) {
        float4 v = sT4[tid * 17 + jj];
        yo[4*jj] = v.x; yo[4*jj+1] = v.y; yo[4*jj+2] = v.z; yo[4*jj+3] = v.w;
    }

    const ulonglong2* sM2 = (const ulonglong2*)sM;
    float logit = 0.f;
    #pragma unroll 1
    for (int p = 0; p < 8; p++) {
        unsigned long long acc[4] = {0ULL, 0ULL, 0ULL, 0ULL};
        #pragma unroll
        for (int j = 0; j < 64; j++) {
            unsigned long long y2 = packdup(yo[j]);
            ulonglong2 w0 = sM2[j*16 + p*2];
            ulonglong2 w1 = sM2[j*16 + p*2 + 1];
            ffma2(acc[0], y2, w0.x);
            ffma2(acc[1], y2, w0.y);
            ffma2(acc[2], y2, w1.x);
            ffma2(acc[3], y2, w1.y);
        }
        #pragma unroll
        for (int q = 0; q < 4; q++) {
            float2 v = unpack2(acc[q]);
            int c = p*8 + q*2;
            float pre, rr;
            pre = inv*v.x + cninv*sc1[c]   + sE[c];   rr = fmaxf(pre, 0.f); logit += rr*sW2[c];
            pre = inv*v.y + cninv*sc1[c+1] + sE[c+1]; rr = fmaxf(pre, 0.f); logit += rr*sW2[c+1];
        }
    }
    logit_out[row] = logit + b2[0];

    __syncthreads();
    #pragma unroll
    for (int jj = 0; jj < 16; jj++) {
        sT4[tid * 17 + jj] = make_float4(yo[4*jj]*inv, yo[4*jj+1]*inv,
                                         yo[4*jj+2]*inv, yo[4*jj+3]*inv);
    }
    __syncthreads();
    {
        int col = tid & 63, part = tid >> 6;
        const float* sS = ps;
        float s = 0.f;
        #pragma unroll 4
        for (int r = part*64; r < part*64 + 64; r++)
            s += sS[r*68 + col];
        sRed[part*64 + col] = s;
    }
    {
        float v = cninv;
        #pragma unroll
        for (int off = 16; off; off >>= 1) v += __shfl_xor_sync(0xffffffffu, v, off);
        if ((tid & 31) == 0) sR0[tid >> 5] = v;
    }
    __syncthreads();
    if (tid < 64)
        atomicAdd(&g_s1[g*64 + tid], sRed[tid] + sRed[64 + tid] + sRed[128 + tid] + sRed[192 + tid]);
    if (tid == 0) {
        float s0 = 0.f;
        #pragma unroll
        for (int w = 0; w < 8; w++) s0 += sR0[w];
        atomicAdd(&g_s0[g], s0);
    }
}

// ---------------------------------------------------------------------------
__global__ void k_value(const float* __restrict__ extra,
                        const float* __restrict__ Wv1, const float* __restrict__ bv1,
                        float* __restrict__ val_out)
{
    __shared__ float sv[64];
    int tid = threadIdx.x;
    float acc = 0.f;
    #pragma unroll
    for (int j = 0; j < 64; j++) acc += g_s1[tid*64 + j] * g_wv[j];
    acc += g_s0[tid] * g_bv[0];
    acc *= (1.f / (float)N0c);
    #pragma unroll
    for (int d = 0; d < 4; d++) acc += extra[tid*4 + d] * Wv1[64 + d];
    acc += bv1[0];
    sv[tid] = acc;
    __syncthreads();
    if (tid < 16)
        val_out[tid] = sv[tid*4] + sv[tid*4+1] + sv[tid*4+2] + sv[tid*4+3];
}

// ---------------------------------------------------------------------------
extern "C" void kernel_launch(void* const* d_in, const int* in_sizes, int n_in,
                              void* d_out, int out_size)
{
    const float* h0       = (const float*)d_in[0];
    const float* h_global = (const float*)d_in[1];
    const float* x        = (const float*)d_in[2];
    const float* extra    = (const float*)d_in[3];
    const uint32_t* dones = (const uint32_t*)d_in[4];
    const int*   indices  = (const int*)d_in[5];
    const float* nnz      = (const float*)d_in[6];
    const float* Wi  = (const float*)d_in[7];
    const float* bi  = (const float*)d_in[8];
    const float* Wh  = (const float*)d_in[9];
    const float* bhn = (const float*)d_in[10];
    const float* Wq  = (const float*)d_in[11];
    const float* bq  = (const float*)d_in[12];
    const float* Wk  = (const float*)d_in[13];
    const float* bk  = (const float*)d_in[14];
    const float* Wv  = (const float*)d_in[15];
    const float* bv  = (const float*)d_in[16];
    const float* Wo  = (const float*)d_in[17];
    const float* bo  = (const float*)d_in[18];
    const float* W1  = (const float*)d_in[19];
    const float* b1  = (const float*)d_in[20];
    const float* W2  = (const float*)d_in[21];
    const float* b2  = (const float*)d_in[22];
    const float* Wv1 = (const float*)d_in[23];
    const float* bv1 = (const float*)d_in[24];

    float* out       = (float*)d_out;
    float* out_hfin  = out;
    float* out_hg    = out + OFF_HG;
    float* out_logit = out + OFF_LOGIT;
    float* out_val   = out + OFF_VAL;

    void *yo_ptr, *cnt_ptr, *s1_ptr, *s0_ptr;
    cudaGetSymbolAddress(&yo_ptr,  g_yo);
    cudaGetSymbolAddress(&cnt_ptr, g_cnt);
    cudaGetSymbolAddress(&s1_ptr,  g_s1);
    cudaGetSymbolAddress(&s0_ptr,  g_s0);
    cudaMemsetAsync(yo_ptr,  0, sizeof(float) * (size_t)TBNc * Hh, 0);
    cudaMemsetAsync(cnt_ptr, 0, sizeof(int) * Nn, 0);
    cudaMemsetAsync(s1_ptr,  0, sizeof(float) * 64 * 64, 0);
    cudaMemsetAsync(s0_ptr,  0, sizeof(float) * 64, 0);

    cudaMemcpyAsync(out_hg, h_global, 1024 * sizeof(float), cudaMemcpyDeviceToDevice, 0);

    int smem_gru  = GRU_SM_TOT * 4;                                // 140032 B
    cudaFuncSetAttribute(k_gru_qkv, cudaFuncAttributeMaxDynamicSharedMemorySize, smem_gru);
    cudaFuncSetAttribute(k_attn, cudaFuncAttributeMaxDynamicSharedMemorySize, ATT_SM);
    int smem_post = (256*17*4 + 4096 + 64 + 64 + 64 + 256 + 8) * 4; // 88112 B
    cudaFuncSetAttribute(k_post, cudaFuncAttributeMaxDynamicSharedMemorySize, smem_post);

    k_count<<<(Ff * ORD + 255) / 256, 256>>>(indices);
    k_prep<<<32, 256>>>(Wo, bo, W1, b1, Wv1, extra);
    k_gru_qkv<<<148, 512, smem_gru>>>(h0, x, dones, Wi, bi, Wh, bhn,
                                      Wq, bq, Wk, bk, Wv, bv, out_hfin);
    k_attn<<<TBc * Ff / 32, 256, ATT_SM>>>(indices);
    k_post<<<TBNc / 256, 256, smem_post>>>(nnz, W2, b2, out_logit);
    k_value<<<1, 64>>>(extra, Wv1, bv1, out_val);
}

// round 17
// speedup vs baseline: 2.1711x; 1.0099x over previous
#include <cuda_runtime.h>
#include <cuda_fp16.h>
#include <math.h>
#include <stdint.h>

// Problem constants
#define Tt   4
#define Bb   4
#define Nn   16384
#define KALLc 4
#define Ff   16384
#define ORD  3
#define Hh   64
#define N0c  4096

#define TBc  (Tt*Bb)        // 16
#define BNc  (Bb*Nn)        // 65536
#define TBNc (TBc*Nn)       // 262144
#define H3c  (3*Hh)         // 192

// Output layout: h_fin [B,N,H] | h_global [B,K,64] | logit [T,B,N] | value [T,B]
#define OFF_HG    4194304
#define OFF_LOGIT (OFF_HG + 1024)
#define OFF_VAL   (OFF_LOGIT + 262144)

// Scratch
__device__ __half g_qkvh[TBNc * H3c]; // [T,B,N,192] fp16 (intermediate only)
__device__ float g_yo [TBNc * Hh];    // [T,B,N,64]
__device__ int   g_cnt[Nn];
__device__ float g_M  [64*64];        // Wo @ W1[:64]
__device__ float g_c1 [64];           // bo @ W1[:64]
__device__ float g_E  [64*64];        // per (tb,kall): b1 + extra@W1[64:]
__device__ float g_wv [64];           // Wo @ Wv1[:64]
__device__ float g_bv [1];            // bo @ Wv1[:64]
__device__ float g_s1 [64*64];        // per (tb,kall): sum_n yo*invnnz
__device__ float g_s0 [64];           // per (tb,kall): sum_n cnt*invnnz

__device__ __forceinline__ float sigmoidf_(float v) { return 1.f / (1.f + expf(-v)); }

// ---- packed fp32 helpers (fma.rn.f32x2) ----
__device__ __forceinline__ unsigned long long packdup(float v) {
    unsigned long long r;
    asm("mov.b64 %0, {%1, %1};" : "=l"(r) : "f"(v));
    return r;
}
__device__ __forceinline__ unsigned long long pack2(float a, float b) {
    unsigned long long r;
    asm("mov.b64 %0, {%1, %2};" : "=l"(r) : "f"(a), "f"(b));
    return r;
}
__device__ __forceinline__ void ffma2(unsigned long long& acc,
                                      unsigned long long a, unsigned long long b) {
    asm("fma.rn.f32x2 %0, %1, %2, %0;" : "+l"(acc) : "l"(a), "l"(b));
}
__device__ __forceinline__ float2 unpack2(unsigned long long v) {
    float lo, hi;
    asm("mov.b64 {%0, %1}, %2;" : "=f"(lo), "=f"(hi) : "l"(v));
    return make_float2(lo, hi);
}

// load 4 halfs -> float4
__device__ __forceinline__ float4 ld4h(const __half* p) {
    uint2 a = *(const uint2*)p;
    float2 lo = __half22float2(*(__half2*)&a.x);
    float2 hi = __half22float2(*(__half2*)&a.y);
    return make_float4(lo.x, lo.y, hi.x, hi.y);
}

// ---------------------------------------------------------------------------
__global__ void k_count(const int* __restrict__ indices) {
    int i = blockIdx.x * 256 + threadIdx.x;
    if (i < Ff * ORD) atomicAdd(&g_cnt[indices[i]], 1);
}

// ---------------------------------------------------------------------------
// Prep: fold Wo into W1/Wv1, bake extra/bias constants; also zero s1/s0.
// ---------------------------------------------------------------------------
__global__ void k_prep(const float* __restrict__ Wo, const float* __restrict__ bo,
                       const float* __restrict__ W1, const float* __restrict__ b1,
                       const float* __restrict__ Wv1,
                       const float* __restrict__ extra)
{
    int o = blockIdx.x * 256 + threadIdx.x;
    if (o < 4096) {
        int j = o >> 6, c = o & 63;
        float s = 0.f;
        #pragma unroll
        for (int h = 0; h < 64; h++) s += Wo[j*64 + h] * W1[h*64 + c];
        g_M[o] = s;
        g_s1[o] = 0.f;
        if (o < 64) g_s0[o] = 0.f;
    } else {
        int e = o - 4096;
        int g = e >> 6, c = e & 63;
        float s = b1[c];
        #pragma unroll
        for (int d = 0; d < 4; d++) s += extra[g*4 + d] * W1[(64 + d)*64 + c];
        g_E[e] = s;
    }
    if (blockIdx.x == 0 && threadIdx.x < 64) {
        int tid = threadIdx.x;
        float s = 0.f, w = 0.f;
        #pragma unroll
        for (int h = 0; h < 64; h++) {
            s += bo[h] * W1[h*64 + tid];
            w += Wo[tid*64 + h] * Wv1[h];
        }
        g_c1[tid] = s;
        g_wv[tid] = w;
        if (tid == 0) {
            float bvv = 0.f;
            #pragma unroll
            for (int h = 0; h < 64; h++) bvv += bo[h] * Wv1[h];
            g_bv[0] = bvv;
        }
    }
}

// ---------------------------------------------------------------------------
// Fused GRU scan + QKV projection, persistent, 64-row tiles (1024 tiles /
// 148 blocks = 6.92 waves, ~1% quantization). Also zeroes g_yo at start
// (g_yo is first consumed by k_attn, after this kernel).
// ---------------------------------------------------------------------------
#define GRU_HSTR     68
#define GRU_OFF_WI   12288
#define GRU_OFF_BI   (GRU_OFF_WI + 768)
#define GRU_OFF_BHN  (GRU_OFF_BI + 192)
#define GRU_OFF_WQ   (GRU_OFF_BHN + 64)
#define GRU_OFF_BQ   (GRU_OFF_WQ + 12288)
#define GRU_OFF_X    (GRU_OFF_BQ + 192)
#define GRU_OFF_H    (GRU_OFF_X + 256)
#define GRU_SM_TOT   (GRU_OFF_H + 64*GRU_HSTR)   // 30912 floats = 123648 B
#define GRU_NT       1024                        // 65536/64 tiles

__global__ __launch_bounds__(512)
void k_gru_qkv(const float* __restrict__ h0, const float* __restrict__ x,
               const uint32_t* __restrict__ dones,
               const float* __restrict__ Wi, const float* __restrict__ bi,
               const float* __restrict__ Wh, const float* __restrict__ bhn,
               const float* __restrict__ Wq, const float* __restrict__ bq,
               const float* __restrict__ Wk, const float* __restrict__ bk,
               const float* __restrict__ Wv, const float* __restrict__ bv,
               float* __restrict__ hfin_out)
{
    extern __shared__ float gs[];
    float* sWh   = gs;
    float* sWi   = gs + GRU_OFF_WI;
    float* sbi   = gs + GRU_OFF_BI;
    float* sbhn  = gs + GRU_OFF_BHN;
    float* sWq   = gs + GRU_OFF_WQ;
    float* sbq   = gs + GRU_OFF_BQ;
    float* sX    = gs + GRU_OFF_X;
    float* sH    = gs + GRU_OFF_H;

    int tid = threadIdx.x;

    // Zero g_yo slice (parallel replacement for the serial memset)
    {
        size_t total4 = (size_t)TBNc * 16;               // float4 count
        size_t per = (total4 + gridDim.x - 1) / gridDim.x;
        size_t beg = (size_t)blockIdx.x * per;
        size_t end = beg + per; if (end > total4) end = total4;
        float4* yo4 = (float4*)g_yo;
        for (size_t i = beg + tid; i < end; i += 512)
            yo4[i] = make_float4(0.f, 0.f, 0.f, 0.f);
    }

    // Stage weights ONCE per block
    for (int i = tid; i < 12288; i += 512) {
        int k = i / 192, e = i % 192;
        int c = e / 3, g = e % 3;
        sWh[i] = Wh[k*192 + g*64 + c];
    }
    for (int i = tid; i < 768; i += 512) {
        int k = i / 192, e = i % 192;
        int c = e / 3, g = e % 3;
        sWi[i] = Wi[k*192 + g*64 + c];
    }
    if (tid < 192) {
        int c = tid / 3, g = tid % 3;
        sbi[tid] = bi[g*64 + c];
    }
    if (tid < 64) sbhn[tid] = bhn[tid];
    for (int i = tid; i < 12288; i += 512) {
        int k = i / 192, e = i % 192;
        sWq[i] = (e < 64) ? Wq[k*64 + e] : (e < 128) ? Wk[k*64 + e - 64] : Wv[k*64 + e - 128];
    }
    if (tid < 192)
        sbq[tid] = (tid < 64) ? bq[tid] : (tid < 128) ? bk[tid - 64] : bv[tid - 128];

    int rg = tid >> 5;          // 0..15: rows rg + 16*i (i<4)
    int cg = tid & 31;
    int c0 = cg * 6;
    int u0 = cg * 2;

    #pragma unroll 1
    for (int tile = blockIdx.x; tile < GRU_NT; tile += gridDim.x) {
        size_t rowbase = (size_t)tile * 64;
        int b = (int)(rowbase >> 14);

        __syncthreads();
        for (int i = tid; i < 4096; i += 512) {
            int r = i >> 6, c = i & 63;
            sH[r*GRU_HSTR + c] = h0[rowbase*64 + i];
        }

        #pragma unroll 1
        for (int t = 0; t < Tt; t++) {
            __syncthreads();

            if (tid < 256) sX[tid] = x[((size_t)t * BNc + rowbase) * 4 + tid];
            if (dones[t * Bb + b] != 0u) {
                for (int i = tid; i < 4096; i += 512) {
                    int r = i >> 6, c = i & 63;
                    sH[r*GRU_HSTR + c] = 0.f;
                }
            }
            __syncthreads();

            unsigned long long acc[4][3];
            #pragma unroll
            for (int i = 0; i < 4; i++) { acc[i][0] = 0ULL; acc[i][1] = 0ULL; acc[i][2] = 0ULL; }

            const float* sWrow = sWh + c0;
            #pragma unroll 1
            for (int k4 = 0; k4 < 16; k4++) {
                unsigned long long w[4][3];
                #pragma unroll
                for (int kk = 0; kk < 4; kk++) {
                    const float* wr = sWrow + (k4*4 + kk) * 192;
                    w[kk][0] = *(const unsigned long long*)(wr);
                    w[kk][1] = *(const unsigned long long*)(wr + 2);
                    w[kk][2] = *(const unsigned long long*)(wr + 4);
                }
                #pragma unroll
                for (int i = 0; i < 4; i++) {
                    float4 hv = *(const float4*)&sH[(rg + 16*i) * GRU_HSTR + k4*4];
                    unsigned long long hh0 = packdup(hv.x);
                    ffma2(acc[i][0], hh0, w[0][0]); ffma2(acc[i][1], hh0, w[0][1]); ffma2(acc[i][2], hh0, w[0][2]);
                    unsigned long long hh1 = packdup(hv.y);
                    ffma2(acc[i][0], hh1, w[1][0]); ffma2(acc[i][1], hh1, w[1][1]); ffma2(acc[i][2], hh1, w[1][2]);
                    unsigned long long hh2 = packdup(hv.z);
                    ffma2(acc[i][0], hh2, w[2][0]); ffma2(acc[i][1], hh2, w[2][1]); ffma2(acc[i][2], hh2, w[2][2]);
                    unsigned long long hh3 = packdup(hv.w);
                    ffma2(acc[i][0], hh3, w[3][0]); ffma2(acc[i][1], hh3, w[3][1]); ffma2(acc[i][2], hh3, w[3][2]);
                }
            }
            __syncthreads();

            float2 bh2 = *(const float2*)&sbhn[u0];
            #pragma unroll
            for (int i = 0; i < 4; i++) {
                int row = rg + 16*i;
                unsigned long long g0 = *(const unsigned long long*)(sbi + c0);
                unsigned long long g1 = *(const unsigned long long*)(sbi + c0 + 2);
                unsigned long long g2 = *(const unsigned long long*)(sbi + c0 + 4);
                #pragma unroll
                for (int d = 0; d < 4; d++) {
                    unsigned long long xv = packdup(sX[row*4 + d]);
                    const float* wr = sWi + d*192 + c0;
                    ffma2(g0, xv, *(const unsigned long long*)(wr));
                    ffma2(g1, xv, *(const unsigned long long*)(wr + 2));
                    ffma2(g2, xv, *(const unsigned long long*)(wr + 4));
                }
                float2 a0 = unpack2(acc[i][0]);
                float2 a1 = unpack2(acc[i][1]);
                float2 a2 = unpack2(acc[i][2]);
                float2 i0 = unpack2(g0);
                float2 i1 = unpack2(g1);
                float2 i2 = unpack2(g2);

                float2 hold = *(const float2*)&sH[row*GRU_HSTR + u0];
                float r0 = sigmoidf_(i0.x + a0.x);
                float z0 = sigmoidf_(i0.y + a0.y);
                float n0 = tanhf(i1.x + r0 * (a1.x + bh2.x));
                float h0n = (1.f - z0) * n0 + z0 * hold.x;
                float r1 = sigmoidf_(i1.y + a1.y);
                float z1 = sigmoidf_(i2.x + a2.x);
                float n1 = tanhf(i2.y + r1 * (a2.y + bh2.y));
                float h1n = (1.f - z1) * n1 + z1 * hold.y;
                *(float2*)&sH[row*GRU_HSTR + u0] = make_float2(h0n, h1n);
            }
            __syncthreads();

            {
                unsigned long long qa[4][3];
                float2 b01 = *(const float2*)&sbq[c0];
                float2 b23 = *(const float2*)&sbq[c0 + 2];
                float2 b45 = *(const float2*)&sbq[c0 + 4];
                #pragma unroll
                for (int i = 0; i < 4; i++) {
                    qa[i][0] = pack2(b01.x, b01.y);
                    qa[i][1] = pack2(b23.x, b23.y);
                    qa[i][2] = pack2(b45.x, b45.y);
                }
                const float* sQrow = sWq + c0;
                #pragma unroll 1
                for (int k4 = 0; k4 < 16; k4++) {
                    unsigned long long w[4][3];
                    #pragma unroll
                    for (int kk = 0; kk < 4; kk++) {
                        const float* wr = sQrow + (k4*4 + kk) * 192;
                        w[kk][0] = *(const unsigned long long*)(wr);
                        w[kk][1] = *(const unsigned long long*)(wr + 2);
                        w[kk][2] = *(const unsigned long long*)(wr + 4);
                    }
                    #pragma unroll
                    for (int i = 0; i < 4; i++) {
                        float4 hv = *(const float4*)&sH[(rg + 16*i) * GRU_HSTR + k4*4];
                        unsigned long long hh0 = packdup(hv.x);
                        ffma2(qa[i][0], hh0, w[0][0]); ffma2(qa[i][1], hh0, w[0][1]); ffma2(qa[i][2], hh0, w[0][2]);
                        unsigned long long hh1 = packdup(hv.y);
                        ffma2(qa[i][0], hh1, w[1][0]); ffma2(qa[i][1], hh1, w[1][1]); ffma2(qa[i][2], hh1, w[1][2]);
                        unsigned long long hh2 = packdup(hv.z);
                        ffma2(qa[i][0], hh2, w[2][0]); ffma2(qa[i][1], hh2, w[2][1]); ffma2(qa[i][2], hh2, w[2][2]);
                        unsigned long long hh3 = packdup(hv.w);
                        ffma2(qa[i][0], hh3, w[3][0]); ffma2(qa[i][1], hh3, w[3][1]); ffma2(qa[i][2], hh3, w[3][2]);
                    }
                }
                size_t orow0 = (size_t)t * BNc + rowbase;
                #pragma unroll
                for (int i = 0; i < 4; i++) {
                    float2 p0 = unpack2(qa[i][0]);
                    float2 p1 = unpack2(qa[i][1]);
                    float2 p2 = unpack2(qa[i][2]);
                    __half2* dst = (__half2*)(g_qkvh + (orow0 + rg + 16*i) * H3c + c0);
                    dst[0] = __floats2half2_rn(p0.x, p0.y);
                    dst[1] = __floats2half2_rn(p1.x, p1.y);
                    dst[2] = __floats2half2_rn(p2.x, p2.y);
                }
            }
        }

        __syncthreads();
        for (int i = tid; i < 4096; i += 512) {
            int r = i >> 6, c = i & 63;
            hfin_out[rowbase*64 + i] = sH[r*GRU_HSTR + c];
        }
    }
}

// ---------------------------------------------------------------------------
// Attention v5 (unchanged from R16, passing, 93.8us).
// ---------------------------------------------------------------------------
#define ATT_HSTR 200
#define ATT_SM   (8 * 12 * ATT_HSTR * 2)   // 38400 B

__global__ __launch_bounds__(256, 4)
void k_attn(const int* __restrict__ indices)
{
    extern __shared__ __align__(16) __half ah_[];
    __shared__ int sIdx[8][12];

    int warp = threadIdx.x >> 5, lane = threadIdx.x & 31;
    __half* R0 = ah_ + warp * 12 * ATT_HSTR;

    int ip = blockIdx.x * 32 + warp * 4;
    int tb = ip >> 14;
    int f0 = ip & 16383;

    if (lane < 12) sIdx[warp][lane] = __ldg(&indices[f0*3 + lane]);
    __syncwarp();

    const __half* base = g_qkvh + (size_t)tb * Nn * H3c;
    #pragma unroll
    for (int it = 0; it < 9; it++) {
        int idx = it * 32 + lane;
        int r = idx / 24, e = idx - r * 24;
        const uint4* src = (const uint4*)(base + (size_t)sIdx[warp][r] * H3c);
        ((uint4*)(R0 + r * ATT_HSTR))[e] = src[e];
    }
    __syncwarp();

    if (lane < 16) {
        int i = lane & 3, hh = lane >> 2;
        __half* R = R0 + i * 3 * ATT_HSTR;
        int ho = hh * 16;

        float l[3][3];
        #pragma unroll
        for (int qr = 0; qr < 3; qr++) {
            float q[16];
            #pragma unroll
            for (int d4 = 0; d4 < 4; d4++) {
                float4 v = ld4h(R + qr*ATT_HSTR + ho + d4*4);
                q[d4*4+0] = v.x; q[d4*4+1] = v.y; q[d4*4+2] = v.z; q[d4*4+3] = v.w;
            }
            #pragma unroll
            for (int kr = 0; kr < 3; kr++) {
                float s = 0.f;
                #pragma unroll
                for (int d4 = 0; d4 < 4; d4++) {
                    float4 kv = ld4h(R + kr*ATT_HSTR + 64 + ho + d4*4);
                    s += q[d4*4+0]*kv.x + q[d4*4+1]*kv.y + q[d4*4+2]*kv.z + q[d4*4+3]*kv.w;
                }
                l[qr][kr] = s * 0.25f;
            }
        }
        #pragma unroll
        for (int qr = 0; qr < 3; qr++) {
            float m = fmaxf(l[qr][0], fmaxf(l[qr][1], l[qr][2]));
            float e0 = __expf(l[qr][0] - m), e1 = __expf(l[qr][1] - m), e2 = __expf(l[qr][2] - m);
            float inv = 1.f / (e0 + e1 + e2);
            e0 *= inv; e1 *= inv; e2 *= inv;
            float* of = (float*)(R + qr*ATT_HSTR) + ho;
            #pragma unroll
            for (int d4 = 0; d4 < 4; d4++) {
                float4 v0 = ld4h(R + 0*ATT_HSTR + 128 + ho + d4*4);
                float4 v1 = ld4h(R + 1*ATT_HSTR + 128 + ho + d4*4);
                float4 v2 = ld4h(R + 2*ATT_HSTR + 128 + ho + d4*4);
                float4 v;
                v.x = e0*v0.x + e1*v1.x + e2*v2.x;
                v.y = e0*v0.y + e1*v1.y + e2*v2.y;
                v.z = e0*v0.z + e1*v1.z + e2*v2.z;
                v.w = e0*v0.w + e1*v1.w + e2*v2.w;
                *(float4*)(of + d4*4) = v;
            }
        }
    }
    __syncwarp();

    {
        int rhalf = lane >> 4, col = lane & 15;
        float4* yo = (float4*)g_yo + (size_t)tb * Nn * 16;
        #pragma unroll
        for (int it = 0; it < 6; it++) {
            int r = it*2 + rhalf;
            float4 v = *(const float4*)((const float*)(R0 + r*ATT_HSTR) + col*4);
            atomicAdd(&yo[(size_t)sIdx[warp][r] * 16 + col], v);
        }
    }
}

// ---------------------------------------------------------------------------
// Logit head + fused value-head segment sums (unchanged, passing).
// ---------------------------------------------------------------------------
__global__ __launch_bounds__(256, 2)
void k_post(const float* __restrict__ nnz,
            const float* __restrict__ W2, const float* __restrict__ b2,
            float* __restrict__ logit_out)
{
    extern __shared__ float ps[];
    float4* sT4 = (float4*)ps;
    float*  sM  = ps + 256*17*4;
    float*  sc1 = sM + 4096;
    float*  sE  = sc1 + 64;
    float*  sW2 = sE + 64;
    float*  sRed = sW2 + 64;
    float*  sR0  = sRed + 256;

    int tid = threadIdx.x;
    int rowbase = blockIdx.x * 256;
    int g = rowbase >> 12;

    const float4* yo4 = (const float4*)g_yo + (size_t)rowbase * 16;
    for (int i = tid; i < 4096; i += 256)
        sT4[(i >> 4) * 17 + (i & 15)] = yo4[i];
    for (int i = tid; i < 4096; i += 256) sM[i] = g_M[i];
    if (tid < 64) { sc1[tid] = g_c1[tid]; sE[tid] = g_E[g*64 + tid]; sW2[tid] = W2[tid]; }
    __syncthreads();

    int row = rowbase + tid;
    int n = row & 16383;
    float inv = 1.f / nnz[n];
    float cninv = (float)g_cnt[n] * inv;

    float yo[64];
    #pragma unroll
    for (int jj = 0; jj < 16; jj++) {
        float4 v = sT4[tid * 17 + jj];
        yo[4*jj] = v.x; yo[4*jj+1] = v.y; yo[4*jj+2] = v.z; yo[4*jj+3] = v.w;
    }

    const ulonglong2* sM2 = (const ulonglong2*)sM;
    float logit = 0.f;
    #pragma unroll 1
    for (int p = 0; p < 8; p++) {
        unsigned long long acc[4] = {0ULL, 0ULL, 0ULL, 0ULL};
        #pragma unroll
        for (int j = 0; j < 64; j++) {
            unsigned long long y2 = packdup(yo[j]);
            ulonglong2 w0 = sM2[j*16 + p*2];
            ulonglong2 w1 = sM2[j*16 + p*2 + 1];
            ffma2(acc[0], y2, w0.x);
            ffma2(acc[1], y2, w0.y);
            ffma2(acc[2], y2, w1.x);
            ffma2(acc[3], y2, w1.y);
        }
        #pragma unroll
        for (int q = 0; q < 4; q++) {
            float2 v = unpack2(acc[q]);
            int c = p*8 + q*2;
            float pre, rr;
            pre = inv*v.x + cninv*sc1[c]   + sE[c];   rr = fmaxf(pre, 0.f); logit += rr*sW2[c];
            pre = inv*v.y + cninv*sc1[c+1] + sE[c+1]; rr = fmaxf(pre, 0.f); logit += rr*sW2[c+1];
        }
    }
    logit_out[row] = logit + b2[0];

    __syncthreads();
    #pragma unroll
    for (int jj = 0; jj < 16; jj++) {
        sT4[tid * 17 + jj] = make_float4(yo[4*jj]*inv, yo[4*jj+1]*inv,
                                         yo[4*jj+2]*inv, yo[4*jj+3]*inv);
    }
    __syncthreads();
    {
        int col = tid & 63, part = tid >> 6;
        const float* sS = ps;
        float s = 0.f;
        #pragma unroll 4
        for (int r = part*64; r < part*64 + 64; r++)
            s += sS[r*68 + col];
        sRed[part*64 + col] = s;
    }
    {
        float v = cninv;
        #pragma unroll
        for (int off = 16; off; off >>= 1) v += __shfl_xor_sync(0xffffffffu, v, off);
        if ((tid & 31) == 0) sR0[tid >> 5] = v;
    }
    __syncthreads();
    if (tid < 64)
        atomicAdd(&g_s1[g*64 + tid], sRed[tid] + sRed[64 + tid] + sRed[128 + tid] + sRed[192 + tid]);
    if (tid == 0) {
        float s0 = 0.f;
        #pragma unroll
        for (int w = 0; w < 8; w++) s0 += sR0[w];
        atomicAdd(&g_s0[g], s0);
    }
}

// ---------------------------------------------------------------------------
__global__ void k_value(const float* __restrict__ extra,
                        const float* __restrict__ Wv1, const float* __restrict__ bv1,
                        float* __restrict__ val_out)
{
    __shared__ float sv[64];
    int tid = threadIdx.x;
    float acc = 0.f;
    #pragma unroll
    for (int j = 0; j < 64; j++) acc += g_s1[tid*64 + j] * g_wv[j];
    acc += g_s0[tid] * g_bv[0];
    acc *= (1.f / (float)N0c);
    #pragma unroll
    for (int d = 0; d < 4; d++) acc += extra[tid*4 + d] * Wv1[64 + d];
    acc += bv1[0];
    sv[tid] = acc;
    __syncthreads();
    if (tid < 16)
        val_out[tid] = sv[tid*4] + sv[tid*4+1] + sv[tid*4+2] + sv[tid*4+3];
}

// ---------------------------------------------------------------------------
extern "C" void kernel_launch(void* const* d_in, const int* in_sizes, int n_in,
                              void* d_out, int out_size)
{
    const float* h0       = (const float*)d_in[0];
    const float* h_global = (const float*)d_in[1];
    const float* x        = (const float*)d_in[2];
    const float* extra    = (const float*)d_in[3];
    const uint32_t* dones = (const uint32_t*)d_in[4];
    const int*   indices  = (const int*)d_in[5];
    const float* nnz      = (const float*)d_in[6];
    const float* Wi  = (const float*)d_in[7];
    const float* bi  = (const float*)d_in[8];
    const float* Wh  = (const float*)d_in[9];
    const float* bhn = (const float*)d_in[10];
    const float* Wq  = (const float*)d_in[11];
    const float* bq  = (const float*)d_in[12];
    const float* Wk  = (const float*)d_in[13];
    const float* bk  = (const float*)d_in[14];
    const float* Wv  = (const float*)d_in[15];
    const float* bv  = (const float*)d_in[16];
    const float* Wo  = (const float*)d_in[17];
    const float* bo  = (const float*)d_in[18];
    const float* W1  = (const float*)d_in[19];
    const float* b1  = (const float*)d_in[20];
    const float* W2  = (const float*)d_in[21];
    const float* b2  = (const float*)d_in[22];
    const float* Wv1 = (const float*)d_in[23];
    const float* bv1 = (const float*)d_in[24];

    float* out       = (float*)d_out;
    float* out_hfin  = out;
    float* out_hg    = out + OFF_HG;
    float* out_logit = out + OFF_LOGIT;
    float* out_val   = out + OFF_VAL;

    void *cnt_ptr;
    cudaGetSymbolAddress(&cnt_ptr, g_cnt);
    cudaMemsetAsync(cnt_ptr, 0, sizeof(int) * Nn, 0);

    cudaMemcpyAsync(out_hg, h_global, 1024 * sizeof(float), cudaMemcpyDeviceToDevice, 0);

    int smem_gru  = GRU_SM_TOT * 4;                                // 123648 B
    cudaFuncSetAttribute(k_gru_qkv, cudaFuncAttributeMaxDynamicSharedMemorySize, smem_gru);
    cudaFuncSetAttribute(k_attn, cudaFuncAttributeMaxDynamicSharedMemorySize, ATT_SM);
    int smem_post = (256*17*4 + 4096 + 64 + 64 + 64 + 256 + 8) * 4; // 88112 B
    cudaFuncSetAttribute(k_post, cudaFuncAttributeMaxDynamicSharedMemorySize, smem_post);

    k_count<<<(Ff * ORD + 255) / 256, 256>>>(indices);
    k_prep<<<32, 256>>>(Wo, bo, W1, b1, Wv1, extra);
    k_gru_qkv<<<148, 512, smem_gru>>>(h0, x, dones, Wi, bi, Wh, bhn,
                                      Wq, bq, Wk, bk, Wv, bv, out_hfin);
    k_attn<<<TBc * Ff / 32, 256, ATT_SM>>>(indices);
    k_post<<<TBNc / 256, 256, smem_post>>>(nnz, W2, b2, out_logit);
    k_value<<<1, 64>>>(extra, Wv1, bv1, out_val);
}